// round 8
// baseline (speedup 1.0000x reference)
#include <cuda_runtime.h>
#include <cuda_bf16.h>
#include <math.h>
#include <stdint.h>

#define BB 2
#define TT 2048
#define DIM 1024
#define NTOK 4096
#define NEXP 8
#define HID 4096
#define MAXTOK 4096
typedef __nv_bfloat16 bf16;

// ---------- scratch ----------
__device__ bf16 g_h_hi[NTOK*DIM], g_h_lo[NTOK*DIM];
__device__ bf16 g_q_hi[32*2048*64], g_q_lo[32*2048*64];
__device__ bf16 g_k_hi[32*2048*64], g_k_lo[32*2048*64];
__device__ bf16 g_v_hi[32*2048*64], g_v_lo[32*2048*64];
__device__ bf16 g_y_hi[NTOK*DIM], g_y_lo[NTOK*DIM];
__device__ float g_x1[NTOK*DIM], g_h2f[NTOK*DIM];
__device__ bf16 g_h2_hi[NTOK*DIM], g_h2_lo[NTOK*DIM];
__device__ bf16 g_pool_hi[(size_t)2*NTOK*HID], g_pool_lo[(size_t)2*NTOK*HID];
__device__ float g_c0[NTOK*DIM], g_c1[NTOK*DIM];
__device__ int g_cnt[NEXP], g_basei[NEXP], g_tok[NEXP*MAXTOK], g_slot[NEXP*MAXTOK];
__device__ float g_wt[NEXP*MAXTOK];
__device__ bf16 g_waT_hi[(size_t)3*DIM*DIM], g_waT_lo[(size_t)3*DIM*DIM];
__device__ bf16 g_wpT_hi[(size_t)DIM*DIM],   g_wpT_lo[(size_t)DIM*DIM];
__device__ bf16 g_w1T_hi[(size_t)NEXP*HID*DIM], g_w1T_lo[(size_t)NEXP*HID*DIM];
__device__ bf16 g_w2T_hi[(size_t)NEXP*DIM*HID], g_w2T_lo[(size_t)NEXP*DIM*HID];

// ---------- ptx helpers ----------
__device__ __forceinline__ uint32_t s2u(const void* p){
    uint32_t a; asm("{ .reg .u64 t; cvta.to.shared.u64 t, %1; cvt.u32.u64 %0, t; }":"=r"(a):"l"(p)); return a;
}
__device__ __forceinline__ uint32_t swz(uint32_t o){ return o ^ ((o>>3)&0x70); }
__device__ __forceinline__ void cp16(uint32_t d, const bf16* s, bool v){
    asm volatile("cp.async.cg.shared.global [%0], [%1], 16, %2;"
        ::"r"(d),"l"(__cvta_generic_to_global(s)),"r"(v?16:0));
}
__device__ __forceinline__ void ldx4(uint32_t* r, uint32_t a){
    asm volatile("ldmatrix.sync.aligned.m8n8.x4.shared.b16 {%0,%1,%2,%3},[%4];"
        :"=r"(r[0]),"=r"(r[1]),"=r"(r[2]),"=r"(r[3]):"r"(a));
}
__device__ __forceinline__ void ldx4t(uint32_t* r, uint32_t a){
    asm volatile("ldmatrix.sync.aligned.m8n8.x4.trans.shared.b16 {%0,%1,%2,%3},[%4];"
        :"=r"(r[0]),"=r"(r[1]),"=r"(r[2]),"=r"(r[3]):"r"(a));
}
__device__ __forceinline__ void mma16816(float* d, const uint32_t* a, const uint32_t* b){
    asm volatile("mma.sync.aligned.m16n8k16.row.col.f32.bf16.bf16.f32 "
        "{%0,%1,%2,%3},{%4,%5,%6,%7},{%8,%9},{%0,%1,%2,%3};"
        : "+f"(d[0]),"+f"(d[1]),"+f"(d[2]),"+f"(d[3])
        : "r"(a[0]),"r"(a[1]),"r"(a[2]),"r"(a[3]),"r"(b[0]),"r"(b[1]));
}
__device__ __forceinline__ uint32_t packb(float f0, float f1){
    bf16 b0=__float2bfloat16(f0), b1=__float2bfloat16(f1);
    return (uint32_t)__bfloat16_as_ushort(b0) | ((uint32_t)__bfloat16_as_ushort(b1)<<16);
}

// ---------- small kernels ----------
__global__ void zero_cnt_kernel(){ if(threadIdx.x<NEXP) g_cnt[threadIdx.x]=0; }
__global__ void base_kernel(){
    if(threadIdx.x==0){ int s=0; for(int e=0;e<NEXP;++e){ g_basei[e]=s; s+=g_cnt[e]; } }
}
__global__ void final_kernel(float* __restrict__ out){
    int i = blockIdx.x*256 + threadIdx.x;
    out[i] = g_x1[i] + g_c0[i] + g_c1[i];
}

// ---------- layernorm ----------
template<int WHICH>
__global__ void ln_kernel(const float* __restrict__ in, const float* __restrict__ gam,
                          const float* __restrict__ bet){
    __shared__ float sx[DIM]; __shared__ float red[8];
    const int n=blockIdx.x, tid=threadIdx.x;
    const float* row = (WHICH==0 ? in : g_x1) + (size_t)n*DIM;
    float4 x4 = ((const float4*)row)[tid];
    ((float4*)sx)[tid] = x4;
    float s = x4.x+x4.y+x4.z+x4.w;
    #pragma unroll
    for(int o=16;o;o>>=1) s += __shfl_xor_sync(~0u,s,o);
    if((tid&31)==0) red[tid>>5]=s;
    __syncthreads();
    float mu = (red[0]+red[1]+red[2]+red[3]+red[4]+red[5]+red[6]+red[7])*(1.f/DIM);
    float sq=0.f;
    #pragma unroll
    for(int p=0;p<4;++p){ float d=sx[tid+p*256]-mu; sq+=d*d; }
    #pragma unroll
    for(int o=16;o;o>>=1) sq += __shfl_xor_sync(~0u,sq,o);
    __syncthreads();
    if((tid&31)==0) red[tid>>5]=sq;
    __syncthreads();
    float var=(red[0]+red[1]+red[2]+red[3]+red[4]+red[5]+red[6]+red[7])*(1.f/DIM);
    float rs = rsqrtf(var+1e-5f);
    #pragma unroll
    for(int p=0;p<4;++p){
        int d=tid+p*256;
        float v = (sx[d]-mu)*rs*gam[d]+bet[d];
        size_t o=(size_t)n*DIM+d;
        bf16 h = __float2bfloat16(v);
        bf16 l = __float2bfloat16(v - __bfloat162float(h));
        if(WHICH==0){ g_h_hi[o]=h; g_h_lo[o]=l; }
        else { g_h2f[o]=v; g_h2_hi[o]=h; g_h2_lo[o]=l; }
    }
}

// ---------- weight transpose + split: 64x64 tiles, vectorized both directions ----------
template<int WHICH>
__global__ void __launch_bounds__(256) transpose_split(const float* __restrict__ src){
    constexpr int Kd = (WHICH==3)?HID:DIM;
    constexpr int Nd = (WHICH==0)?3*DIM:((WHICH==2)?HID:DIM);
    bf16 *dhi, *dlo;
    if(WHICH==0){dhi=g_waT_hi;dlo=g_waT_lo;}
    else if(WHICH==1){dhi=g_wpT_hi;dlo=g_wpT_lo;}
    else if(WHICH==2){dhi=g_w1T_hi;dlo=g_w1T_lo;}
    else {dhi=g_w2T_hi;dlo=g_w2T_lo;}
    const int e=blockIdx.z;
    src += (size_t)e*Kd*Nd; dhi += (size_t)e*(size_t)Nd*Kd; dlo += (size_t)e*(size_t)Nd*Kd;
    __shared__ float t[64][65];
    const int n0=blockIdx.x*64, k0=blockIdx.y*64;
    const int tid=threadIdx.x;
    const int lr = tid>>4, lc = (tid&15)*4;
    #pragma unroll
    for(int i=0;i<4;++i){
        int k = i*16 + lr;
        float4 v = *(const float4*)(src + (size_t)(k0+k)*Nd + n0 + lc);
        t[k][lc]=v.x; t[k][lc+1]=v.y; t[k][lc+2]=v.z; t[k][lc+3]=v.w;
    }
    __syncthreads();
    const int nr = tid>>2, ks = (tid&3)*16;
    float v[16];
    #pragma unroll
    for(int j=0;j<16;++j) v[j] = t[ks+j][nr];
    uint32_t hw[8], lw[8];
    #pragma unroll
    for(int j=0;j<8;++j){
        float a=v[2*j], b=v[2*j+1];
        bf16 ha=__float2bfloat16(a), hb=__float2bfloat16(b);
        hw[j] = (uint32_t)__bfloat16_as_ushort(ha) | ((uint32_t)__bfloat16_as_ushort(hb)<<16);
        lw[j] = packb(a-__bfloat162float(ha), b-__bfloat162float(hb));
    }
    size_t o = (size_t)(n0+nr)*Kd + k0 + ks;
    *(uint4*)&dhi[o]   = make_uint4(hw[0],hw[1],hw[2],hw[3]);
    *(uint4*)&dhi[o+8] = make_uint4(hw[4],hw[5],hw[6],hw[7]);
    *(uint4*)&dlo[o]   = make_uint4(lw[0],lw[1],lw[2],lw[3]);
    *(uint4*)&dlo[o+8] = make_uint4(lw[4],lw[5],lw[6],lw[7]);
}

// ---------- mma.sync split-bf16 GEMM: block 128x256, warp 64x64, K-step 64, 2-stage ----------
template<int MODE, int N, int K>
__global__ void __launch_bounds__(256,1) tgemm(const float* __restrict__ aux){
    constexpr int NKT = K/64;
    constexpr int STG = 98304;
    const int e = (MODE>=2)? blockIdx.z : 0;
    int Mrows = NTOK, pbase = 0;
    if(MODE>=2){
        Mrows = g_cnt[e]; pbase = g_basei[e];
        if((int)blockIdx.y*128 >= Mrows) return;
    }
    extern __shared__ char smem[];
    const uint32_t sb = s2u(smem);
    const int tid = threadIdx.x, lane = tid&31, wid = tid>>5;
    const int wm = wid>>2, wn = wid&3;
    const int m0 = blockIdx.y*128, n0 = blockIdx.x*256;

    const bf16 *Ahi,*Alo,*Bhi,*Blo;
    if(MODE==0){ Ahi=g_h_hi; Alo=g_h_lo; Bhi=g_waT_hi; Blo=g_waT_lo; }
    else if(MODE==1){ Ahi=g_y_hi; Alo=g_y_lo; Bhi=g_wpT_hi; Blo=g_wpT_lo; }
    else if(MODE==2){ Ahi=g_h2_hi; Alo=g_h2_lo;
        Bhi=g_w1T_hi+(size_t)e*HID*DIM; Blo=g_w1T_lo+(size_t)e*HID*DIM; }
    else { Ahi=g_pool_hi; Alo=g_pool_lo;
        Bhi=g_w2T_hi+(size_t)e*DIM*HID; Blo=g_w2T_lo+(size_t)e*DIM*HID; }

    const uint32_t d0 = swz((uint32_t)((tid>>3)*128 + (tid&7)*16));
    const bf16 *pah[4], *pal[4]; bool av[4];
    #pragma unroll
    for(int i=0;i<4;++i){
        int r = (tid>>3) + i*32, gm = m0 + r;
        bool v = true; long rg = gm;
        if(MODE==2){ v = gm<Mrows; rg = v ? g_tok[e*MAXTOK+gm] : 0; }
        if(MODE==3){ v = gm<Mrows; rg = (long)pbase + (v?gm:0); }
        pah[i]=Ahi+(size_t)rg*K+(tid&7)*8; pal[i]=Alo+(size_t)rg*K+(tid&7)*8; av[i]=v;
    }
    const bf16 *pb_h = Bhi + (size_t)(n0 + (tid>>3))*K + (tid&7)*8;
    const bf16 *pb_l = Blo + (size_t)(n0 + (tid>>3))*K + (tid&7)*8;

    float acc[4][8][4];
    #pragma unroll
    for(int a=0;a<4;++a)
        #pragma unroll
        for(int b=0;b<8;++b)
            #pragma unroll
            for(int c=0;c<4;++c) acc[a][b][c]=0.f;

    const int arow = wm*64 + (lane&15), achk = lane>>4;
    const int brow_b = wn*64 + ((lane>>4)&1)*8 + (lane&7), bchk = (lane>>3)&1;

    auto issue = [&](int kt){
        const uint32_t st = sb + (kt&1)*STG;
        const int ko = kt*64;
        #pragma unroll
        for(int i=0;i<4;++i){
            cp16(st+d0+i*4096,        pah[i]+ko, av[i]);
            cp16(st+16384+d0+i*4096,  pal[i]+ko, av[i]);
        }
        #pragma unroll
        for(int i=0;i<8;++i){
            cp16(st+32768+d0+i*4096,  pb_h + (size_t)i*32*K + ko, true);
            cp16(st+65536+d0+i*4096,  pb_l + (size_t)i*32*K + ko, true);
        }
        asm volatile("cp.async.commit_group;":::"memory");
    };

    issue(0);
    for(int kt=0; kt<NKT; ++kt){
        if(kt+1<NKT){ issue(kt+1); asm volatile("cp.async.wait_group 1;":::"memory"); }
        else        { asm volatile("cp.async.wait_group 0;":::"memory"); }
        __syncthreads();
        const uint32_t st = sb + (kt&1)*STG;
        #pragma unroll
        for(int k16=0;k16<4;++k16){
            uint32_t ah[4][4], al[4][4];
            #pragma unroll
            for(int mi=0;mi<4;++mi){
                uint32_t off = swz((uint32_t)((arow+mi*16)*128 + k16*32 + achk*16));
                ldx4(ah[mi], st + off);
                ldx4(al[mi], st + 16384 + off);
            }
            #pragma unroll
            for(int n16=0;n16<4;++n16){
                uint32_t off = swz((uint32_t)((brow_b+n16*16)*128 + k16*32 + bchk*16));
                uint32_t rh[4], rl[4];
                ldx4(rh, st + 32768 + off);
                ldx4(rl, st + 65536 + off);
                #pragma unroll
                for(int mi=0;mi<4;++mi){
                    mma16816(acc[mi][n16*2],   ah[mi], rh);
                    mma16816(acc[mi][n16*2],   ah[mi], rl);
                    mma16816(acc[mi][n16*2],   al[mi], rh);
                    mma16816(acc[mi][n16*2+1], ah[mi], rh+2);
                    mma16816(acc[mi][n16*2+1], ah[mi], rl+2);
                    mma16816(acc[mi][n16*2+1], al[mi], rh+2);
                }
            }
        }
        __syncthreads();
    }

    const int r0 = lane>>2, c2 = (lane&3)*2;
    const float* bias = (MODE>=2)? (aux+(size_t)e*N) : aux;
    #pragma unroll
    for(int mi=0;mi<4;++mi){
        #pragma unroll
        for(int half=0; half<2; ++half){
            const int m = m0 + wm*64 + mi*16 + r0 + half*8;
            if(MODE>=2 && m>=Mrows) continue;
            int tok=0, slot=0; float wgt=0.f;
            if(MODE==3){ int ix=e*MAXTOK+m; tok=g_tok[ix]; wgt=g_wt[ix]; slot=g_slot[ix]; }
            #pragma unroll
            for(int ni=0;ni<8;++ni){
                const int col = n0 + wn*64 + ni*8 + c2;
                float dd0 = acc[mi][ni][half*2], dd1 = acc[mi][ni][half*2+1];
                if(MODE==0){
                    const int which = col>>10, r = col&1023, h = r>>6, d = r&63;
                    const int b = m>>11, t = m&2047;
                    size_t o = ((size_t)(b*16+h)*2048 + t)*64 + d;
                    bf16 *ph, *pl;
                    if(which==0){ dd0*=0.125f; dd1*=0.125f; ph=g_q_hi; pl=g_q_lo; }
                    else if(which==1){ ph=g_k_hi; pl=g_k_lo; }
                    else { ph=g_v_hi; pl=g_v_lo; }
                    bf16 h0=__float2bfloat16(dd0), h1=__float2bfloat16(dd1);
                    *(uint32_t*)&ph[o] = (uint32_t)__bfloat16_as_ushort(h0)
                                       | ((uint32_t)__bfloat16_as_ushort(h1)<<16);
                    *(uint32_t*)&pl[o] = packb(dd0-__bfloat162float(h0), dd1-__bfloat162float(h1));
                } else if(MODE==1){
                    const float* rx=aux+(size_t)m*N+col;
                    float2 w; w.x = rx[0]+dd0; w.y = rx[1]+dd1;
                    *(float2*)&g_x1[(size_t)m*N+col] = w;
                } else if(MODE==2){
                    size_t prow=(size_t)(pbase+m);
                    float v0=dd0+bias[col], v1=dd1+bias[col+1];
                    float gg0=0.5f*v0*(1.f+erff(v0*0.70710678f));
                    float gg1=0.5f*v1*(1.f+erff(v1*0.70710678f));
                    bf16 h0=__float2bfloat16(gg0), h1=__float2bfloat16(gg1);
                    *(uint32_t*)&g_pool_hi[prow*HID+col] =
                        (uint32_t)__bfloat16_as_ushort(h0) | ((uint32_t)__bfloat16_as_ushort(h1)<<16);
                    *(uint32_t*)&g_pool_lo[prow*HID+col] =
                        packb(gg0-__bfloat162float(h0), gg1-__bfloat162float(h1));
                } else {
                    float2 w; w.x = wgt*(dd0+bias[col]); w.y = wgt*(dd1+bias[col+1]);
                    *(float2*)&((slot?g_c1:g_c0)[(size_t)tok*DIM+col]) = w;
                }
            }
        }
    }
}

// ---------- tensor-core flash attention (unchanged) ----------
__global__ void __launch_bounds__(256,1) attn_mma(){
    extern __shared__ char smem[];
    const uint32_t sb = s2u(smem);
    const int tid=threadIdx.x, lane=tid&31, wid=tid>>5;
    const int bh = blockIdx.y;
    const int qt = (gridDim.x-1) - blockIdx.x;
    const int q0 = qt*128;
    const size_t pbase = (size_t)bh*2048*64;

    #pragma unroll
    for(int i=0;i<4;++i){
        int idx=tid+i*256, r=idx>>3, c=idx&7;
        uint32_t off = swz((uint32_t)(r*128+c*16));
        cp16(sb+off,        g_q_hi + pbase + (size_t)(q0+r)*64 + c*8, true);
        cp16(sb+16384+off,  g_q_lo + pbase + (size_t)(q0+r)*64 + c*8, true);
    }
    auto issueKV = [&](int kb){
        const uint32_t st = sb + 32768 + (kb%3)*32768;
        #pragma unroll
        for(int i=0;i<2;++i){
            int idx=tid+i*256, r=idx>>3, c=idx&7;
            uint32_t off = swz((uint32_t)(r*128+c*16));
            size_t src = pbase + (size_t)(kb*64+r)*64 + c*8;
            cp16(st+off,        g_k_hi+src, true);
            cp16(st+8192+off,   g_k_lo+src, true);
            cp16(st+16384+off,  g_v_hi+src, true);
            cp16(st+24576+off,  g_v_lo+src, true);
        }
        asm volatile("cp.async.commit_group;":::"memory");
    };
    const int kbmax = 2*qt+1;
    issueKV(0);
    issueKV(1);

    asm volatile("cp.async.wait_group 1;":::"memory");
    __syncthreads();
    uint32_t qh[4][4], ql[4][4];
    {
        const int qrow = wid*16 + (lane&15), qchk = lane>>4;
        #pragma unroll
        for(int k16=0;k16<4;++k16){
            uint32_t off = swz((uint32_t)(qrow*128 + k16*32 + qchk*16));
            ldx4(qh[k16], sb+off);
            ldx4(ql[k16], sb+16384+off);
        }
    }

    float O[8][4], mstat[2], lstat[2];
    #pragma unroll
    for(int t=0;t<8;++t){ O[t][0]=0;O[t][1]=0;O[t][2]=0;O[t][3]=0; }
    mstat[0]=mstat[1]=-1e30f; lstat[0]=lstat[1]=0.f;

    const int rloc = lane>>2, cloc = (lane&3)*2;
    const int brow_b = ((lane>>4)&1)*8 + (lane&7), bchk = (lane>>3)&1;
    const int vrow_b = ((lane>>3)&1)*8 + (lane&7), vcol_b = ((lane>>4)&1)*8;

    for(int kb=0; kb<=kbmax; ++kb){
        if(kb<kbmax){ asm volatile("cp.async.wait_group 1;":::"memory"); }
        else        { asm volatile("cp.async.wait_group 0;":::"memory"); }
        __syncthreads();
        if(kb+2<=kbmax) issueKV(kb+2);
        const uint32_t st = sb + 32768 + (kb%3)*32768;

        float s[8][4];
        #pragma unroll
        for(int t=0;t<8;++t){ s[t][0]=0;s[t][1]=0;s[t][2]=0;s[t][3]=0; }
        #pragma unroll
        for(int k16=0;k16<4;++k16){
            uint32_t bkh[8][2], bkl[8][2];
            #pragma unroll
            for(int n16=0;n16<4;++n16){
                uint32_t off = swz((uint32_t)((n16*16+brow_b)*128 + k16*32 + bchk*16));
                uint32_t r[4];
                ldx4(r, st+off);
                bkh[n16*2][0]=r[0]; bkh[n16*2][1]=r[1]; bkh[n16*2+1][0]=r[2]; bkh[n16*2+1][1]=r[3];
                ldx4(r, st+8192+off);
                bkl[n16*2][0]=r[0]; bkl[n16*2][1]=r[1]; bkl[n16*2+1][0]=r[2]; bkl[n16*2+1][1]=r[3];
            }
            #pragma unroll
            for(int t=0;t<8;++t){
                mma16816(s[t], qh[k16], bkh[t]);
                mma16816(s[t], qh[k16], bkl[t]);
                mma16816(s[t], ql[k16], bkh[t]);
            }
        }
        if(kb >= 2*qt){
            const int row0 = q0 + wid*16 + rloc;
            #pragma unroll
            for(int t=0;t<8;++t){
                int c0 = kb*64 + t*8 + cloc;
                if(c0   > row0  ) s[t][0]=-1e30f;
                if(c0+1 > row0  ) s[t][1]=-1e30f;
                if(c0   > row0+8) s[t][2]=-1e30f;
                if(c0+1 > row0+8) s[t][3]=-1e30f;
            }
        }
        float corr[2];
        #pragma unroll
        for(int rh=0; rh<2; ++rh){
            float mt=-1e30f;
            #pragma unroll
            for(int t=0;t<8;++t) mt = fmaxf(mt, fmaxf(s[t][rh*2], s[t][rh*2+1]));
            mt = fmaxf(mt, __shfl_xor_sync(~0u, mt, 1, 4));
            mt = fmaxf(mt, __shfl_xor_sync(~0u, mt, 2, 4));
            float mn = fmaxf(mstat[rh], mt);
            corr[rh] = __expf(mstat[rh]-mn); mstat[rh]=mn;
            float rs=0.f;
            #pragma unroll
            for(int t=0;t<8;++t){
                float p0=__expf(s[t][rh*2]-mn), p1=__expf(s[t][rh*2+1]-mn);
                s[t][rh*2]=p0; s[t][rh*2+1]=p1; rs += p0+p1;
            }
            rs += __shfl_xor_sync(~0u, rs, 1, 4);
            rs += __shfl_xor_sync(~0u, rs, 2, 4);
            lstat[rh] = lstat[rh]*corr[rh] + rs;
        }
        #pragma unroll
        for(int t=0;t<8;++t){
            O[t][0]*=corr[0]; O[t][1]*=corr[0]; O[t][2]*=corr[1]; O[t][3]*=corr[1];
        }
        uint32_t ph[4][4], pl[4][4];
        #pragma unroll
        for(int k16=0;k16<4;++k16){
            #pragma unroll
            for(int half=0; half<2; ++half){
                const int t = 2*k16+half;
                float f0=s[t][0], f1=s[t][1], f2=s[t][2], f3=s[t][3];
                ph[k16][half*2]   = packb(f0,f1);
                ph[k16][half*2+1] = packb(f2,f3);
                bf16 h0=__float2bfloat16(f0), h1=__float2bfloat16(f1);
                bf16 h2=__float2bfloat16(f2), h3=__float2bfloat16(f3);
                pl[k16][half*2]   = packb(f0-__bfloat162float(h0), f1-__bfloat162float(h1));
                pl[k16][half*2+1] = packb(f2-__bfloat162float(h2), f3-__bfloat162float(h3));
            }
        }
        #pragma unroll
        for(int k16=0;k16<4;++k16){
            uint32_t bvh[8][2], bvl[8][2];
            #pragma unroll
            for(int d16=0;d16<4;++d16){
                uint32_t off = swz((uint32_t)((k16*16+vrow_b)*128 + (d16*16+vcol_b)*2));
                uint32_t r[4];
                ldx4t(r, st+16384+off);
                bvh[d16*2][0]=r[0]; bvh[d16*2][1]=r[1]; bvh[d16*2+1][0]=r[2]; bvh[d16*2+1][1]=r[3];
                ldx4t(r, st+24576+off);
                bvl[d16*2][0]=r[0]; bvl[d16*2][1]=r[1]; bvl[d16*2+1][0]=r[2]; bvl[d16*2+1][1]=r[3];
            }
            #pragma unroll
            for(int t=0;t<8;++t){
                mma16816(O[t], ph[k16], bvh[t]);
                mma16816(O[t], ph[k16], bvl[t]);
                mma16816(O[t], pl[k16], bvh[t]);
            }
        }
        __syncthreads();
    }

    const int b = bh>>4, h = bh&15;
    #pragma unroll
    for(int rh=0; rh<2; ++rh){
        const float inv = 1.f/lstat[rh];
        const int row = q0 + wid*16 + rloc + rh*8;
        size_t base = (size_t)(b*TT+row)*DIM + h*64;
        #pragma unroll
        for(int t=0;t<8;++t){
            float v0 = O[t][rh*2]*inv, v1 = O[t][rh*2+1]*inv;
            size_t o = base + t*8 + cloc;
            bf16 h0=__float2bfloat16(v0), h1=__float2bfloat16(v1);
            g_y_hi[o]=h0; g_y_hi[o+1]=h1;
            g_y_lo[o]=__float2bfloat16(v0-__bfloat162float(h0));
            g_y_lo[o+1]=__float2bfloat16(v1-__bfloat162float(h1));
        }
    }
}

// ---------- router ----------
__global__ void router_kernel(const float* __restrict__ wr){
    const int n=blockIdx.x, tid=threadIdx.x;
    float acc[NEXP];
    #pragma unroll
    for(int e=0;e<NEXP;++e) acc[e]=0.f;
    const float* row=g_h2f+(size_t)n*DIM;
    for(int d=tid;d<DIM;d+=128){
        float hv=row[d];
        #pragma unroll
        for(int e=0;e<NEXP;++e) acc[e]+=hv*wr[d*NEXP+e];
    }
    __shared__ float sm[4][NEXP];
    #pragma unroll
    for(int e=0;e<NEXP;++e){
        float v=acc[e];
        #pragma unroll
        for(int o=16;o;o>>=1) v+=__shfl_xor_sync(~0u,v,o);
        if((tid&31)==0) sm[tid>>5][e]=v;
    }
    __syncthreads();
    if(tid==0){
        float lg[NEXP];
        #pragma unroll
        for(int e=0;e<NEXP;++e) lg[e]=sm[0][e]+sm[1][e]+sm[2][e]+sm[3][e];
        int e0=0;
        #pragma unroll
        for(int e=1;e<NEXP;++e) if(lg[e]>lg[e0]) e0=e;
        int e1=-1;
        #pragma unroll
        for(int e=0;e<NEXP;++e) if(e!=e0 && (e1<0||lg[e]>lg[e1])) e1=e;
        float w0=1.f/(1.f+__expf(lg[e1]-lg[e0])), w1=1.f-w0;
        int p0=atomicAdd(&g_cnt[e0],1);
        g_tok[e0*MAXTOK+p0]=n; g_wt[e0*MAXTOK+p0]=w0; g_slot[e0*MAXTOK+p0]=0;
        int p1=atomicAdd(&g_cnt[e1],1);
        g_tok[e1*MAXTOK+p1]=n; g_wt[e1*MAXTOK+p1]=w1; g_slot[e1*MAXTOK+p1]=1;
    }
}

// ---------- launch (reordered so the ncu -s 5 window lands on a GEMM) ----------
extern "C" void kernel_launch(void* const* d_in, const int* in_sizes, int n_in,
                              void* d_out, int out_size){
    const float* x      =(const float*)d_in[0];
    const float* ln1_g  =(const float*)d_in[1];
    const float* ln1_b  =(const float*)d_in[2];
    const float* w_attn =(const float*)d_in[3];
    const float* w_proj =(const float*)d_in[4];
    const float* ln2_g  =(const float*)d_in[5];
    const float* ln2_b  =(const float*)d_in[6];
    const float* w_rtr  =(const float*)d_in[7];
    const float* w1     =(const float*)d_in[8];
    const float* b1     =(const float*)d_in[9];
    const float* w2     =(const float*)d_in[10];
    const float* b2     =(const float*)d_in[11];
    float* out=(float*)d_out;

    const int SMG = 196608;
    cudaFuncSetAttribute(tgemm<0,3*DIM,DIM>, cudaFuncAttributeMaxDynamicSharedMemorySize, SMG);
    cudaFuncSetAttribute(tgemm<1,DIM,DIM>,   cudaFuncAttributeMaxDynamicSharedMemorySize, SMG);
    cudaFuncSetAttribute(tgemm<2,HID,DIM>,   cudaFuncAttributeMaxDynamicSharedMemorySize, SMG);
    cudaFuncSetAttribute(tgemm<3,DIM,HID>,   cudaFuncAttributeMaxDynamicSharedMemorySize, SMG);
    const int SMA = 131072;
    cudaFuncSetAttribute(attn_mma, cudaFuncAttributeMaxDynamicSharedMemorySize, SMA);

    // deps: ln<0> needs x; tgemm<0> needs ln + t<0>; attn needs tgemm<0>;
    // tgemm<1> needs attn + t<1>; moe needs router + t<2>/t<3>.
    ln_kernel<0><<<NTOK,256>>>(x, ln1_g, ln1_b);                     // 0
    transpose_split<0><<<dim3(48,16,1), 256>>>(w_attn);              // 1
    zero_cnt_kernel<<<1,32>>>();                                     // 2
    tgemm<0,3*DIM,DIM><<<dim3(12,32,1),256,SMG>>>(nullptr);          // 3  <- profile target
    attn_mma<<<dim3(TT/128, BB*16),256,SMA>>>();                     // 4
    transpose_split<1><<<dim3(16,16,1), 256>>>(w_proj);              // 5
    tgemm<1,DIM,DIM><<<dim3(4,32,1),256,SMG>>>(x);                   // 6
    ln_kernel<1><<<NTOK,256>>>(nullptr, ln2_g, ln2_b);               // 7
    router_kernel<<<NTOK,128>>>(w_rtr);                              // 8
    base_kernel<<<1,32>>>();                                         // 9
    transpose_split<2><<<dim3(64,16,NEXP), 256>>>(w1);               // 10
    tgemm<2,HID,DIM><<<dim3(16,32,NEXP),256,SMG>>>(b1);              // 11
    transpose_split<3><<<dim3(16,64,NEXP), 256>>>(w2);               // 12
    tgemm<3,DIM,HID><<<dim3(4,32,NEXP),256,SMG>>>(b2);               // 13
    final_kernel<<<NTOK*DIM/256,256>>>(out);                         // 14
}

// round 9
// speedup vs baseline: 1.3626x; 1.3626x over previous
#include <cuda_runtime.h>
#include <cuda_bf16.h>
#include <math.h>
#include <stdint.h>

#define BB 2
#define TT 2048
#define DIM 1024
#define NTOK 4096
#define NEXP 8
#define HID 4096
#define MAXTOK 4096
typedef __nv_bfloat16 bf16;

// ---------- scratch ----------
__device__ bf16 g_h_hi[NTOK*DIM], g_h_lo[NTOK*DIM];
__device__ bf16 g_q_hi[32*2048*64], g_q_lo[32*2048*64];
__device__ bf16 g_k_hi[32*2048*64], g_k_lo[32*2048*64];
__device__ bf16 g_v_hi[32*2048*64], g_v_lo[32*2048*64];
__device__ bf16 g_y_hi[NTOK*DIM], g_y_lo[NTOK*DIM];
__device__ float g_x1[NTOK*DIM], g_h2f[NTOK*DIM];
__device__ bf16 g_h2_hi[NTOK*DIM], g_h2_lo[NTOK*DIM];
__device__ bf16 g_pool_hi[(size_t)2*NTOK*HID], g_pool_lo[(size_t)2*NTOK*HID];
__device__ float g_c0[NTOK*DIM], g_c1[NTOK*DIM];
__device__ int g_cnt[NEXP], g_basei[NEXP], g_tok[NEXP*MAXTOK], g_slot[NEXP*MAXTOK];
__device__ float g_wt[NEXP*MAXTOK];
__device__ bf16 g_waT_hi[(size_t)3*DIM*DIM], g_waT_lo[(size_t)3*DIM*DIM];
__device__ bf16 g_wpT_hi[(size_t)DIM*DIM],   g_wpT_lo[(size_t)DIM*DIM];
__device__ bf16 g_w1T_hi[(size_t)NEXP*HID*DIM], g_w1T_lo[(size_t)NEXP*HID*DIM];
__device__ bf16 g_w2T_hi[(size_t)NEXP*DIM*HID], g_w2T_lo[(size_t)NEXP*DIM*HID];

// ---------- ptx helpers ----------
__device__ __forceinline__ uint32_t s2u(const void* p){
    uint32_t a; asm("{ .reg .u64 t; cvta.to.shared.u64 t, %1; cvt.u32.u64 %0, t; }":"=r"(a):"l"(p)); return a;
}
__device__ __forceinline__ uint32_t swz(uint32_t o){ return o ^ ((o>>3)&0x70); }
__device__ __forceinline__ void cp16(uint32_t d, const bf16* s, bool v){
    asm volatile("cp.async.cg.shared.global [%0], [%1], 16, %2;"
        ::"r"(d),"l"(__cvta_generic_to_global(s)),"r"(v?16:0));
}
__device__ __forceinline__ void ldx4(uint32_t* r, uint32_t a){
    asm volatile("ldmatrix.sync.aligned.m8n8.x4.shared.b16 {%0,%1,%2,%3},[%4];"
        :"=r"(r[0]),"=r"(r[1]),"=r"(r[2]),"=r"(r[3]):"r"(a));
}
__device__ __forceinline__ void ldx4t(uint32_t* r, uint32_t a){
    asm volatile("ldmatrix.sync.aligned.m8n8.x4.trans.shared.b16 {%0,%1,%2,%3},[%4];"
        :"=r"(r[0]),"=r"(r[1]),"=r"(r[2]),"=r"(r[3]):"r"(a));
}
__device__ __forceinline__ void mma16816(float* d, const uint32_t* a, const uint32_t* b){
    asm volatile("mma.sync.aligned.m16n8k16.row.col.f32.bf16.bf16.f32 "
        "{%0,%1,%2,%3},{%4,%5,%6,%7},{%8,%9},{%0,%1,%2,%3};"
        : "+f"(d[0]),"+f"(d[1]),"+f"(d[2]),"+f"(d[3])
        : "r"(a[0]),"r"(a[1]),"r"(a[2]),"r"(a[3]),"r"(b[0]),"r"(b[1]));
}
__device__ __forceinline__ uint32_t packb(float f0, float f1){
    bf16 b0=__float2bfloat16(f0), b1=__float2bfloat16(f1);
    return (uint32_t)__bfloat16_as_ushort(b0) | ((uint32_t)__bfloat16_as_ushort(b1)<<16);
}

// ---------- small kernels ----------
__global__ void zero_cnt_kernel(){ if(threadIdx.x<NEXP) g_cnt[threadIdx.x]=0; }
__global__ void base_kernel(){
    if(threadIdx.x==0){ int s=0; for(int e=0;e<NEXP;++e){ g_basei[e]=s; s+=g_cnt[e]; } }
}
__global__ void final_kernel(float* __restrict__ out){
    int i = blockIdx.x*256 + threadIdx.x;
    out[i] = g_x1[i] + g_c0[i] + g_c1[i];
}

// ---------- layernorm ----------
template<int WHICH>
__global__ void ln_kernel(const float* __restrict__ in, const float* __restrict__ gam,
                          const float* __restrict__ bet){
    __shared__ float sx[DIM]; __shared__ float red[8];
    const int n=blockIdx.x, tid=threadIdx.x;
    const float* row = (WHICH==0 ? in : g_x1) + (size_t)n*DIM;
    float4 x4 = ((const float4*)row)[tid];
    ((float4*)sx)[tid] = x4;
    float s = x4.x+x4.y+x4.z+x4.w;
    #pragma unroll
    for(int o=16;o;o>>=1) s += __shfl_xor_sync(~0u,s,o);
    if((tid&31)==0) red[tid>>5]=s;
    __syncthreads();
    float mu = (red[0]+red[1]+red[2]+red[3]+red[4]+red[5]+red[6]+red[7])*(1.f/DIM);
    float sq=0.f;
    #pragma unroll
    for(int p=0;p<4;++p){ float d=sx[tid+p*256]-mu; sq+=d*d; }
    #pragma unroll
    for(int o=16;o;o>>=1) sq += __shfl_xor_sync(~0u,sq,o);
    __syncthreads();
    if((tid&31)==0) red[tid>>5]=sq;
    __syncthreads();
    float var=(red[0]+red[1]+red[2]+red[3]+red[4]+red[5]+red[6]+red[7])*(1.f/DIM);
    float rs = rsqrtf(var+1e-5f);
    #pragma unroll
    for(int p=0;p<4;++p){
        int d=tid+p*256;
        float v = (sx[d]-mu)*rs*gam[d]+bet[d];
        size_t o=(size_t)n*DIM+d;
        bf16 h = __float2bfloat16(v);
        bf16 l = __float2bfloat16(v - __bfloat162float(h));
        if(WHICH==0){ g_h_hi[o]=h; g_h_lo[o]=l; }
        else { g_h2f[o]=v; g_h2_hi[o]=h; g_h2_lo[o]=l; }
    }
}

// ---------- weight transpose + split (R7-proven 32x32 version) ----------
template<int WHICH>
__global__ void transpose_split(const float* __restrict__ src){
    constexpr int Kd = (WHICH==3)?HID:DIM;
    constexpr int Nd = (WHICH==0)?3*DIM:((WHICH==2)?HID:DIM);
    bf16 *dhi, *dlo;
    if(WHICH==0){dhi=g_waT_hi;dlo=g_waT_lo;}
    else if(WHICH==1){dhi=g_wpT_hi;dlo=g_wpT_lo;}
    else if(WHICH==2){dhi=g_w1T_hi;dlo=g_w1T_lo;}
    else {dhi=g_w2T_hi;dlo=g_w2T_lo;}
    const int e=blockIdx.z;
    src += (size_t)e*Kd*Nd; dhi += (size_t)e*(size_t)Nd*Kd; dlo += (size_t)e*(size_t)Nd*Kd;
    __shared__ float t[32][33];
    const int n0=blockIdx.x*32, k0=blockIdx.y*32;
    const int tx=threadIdx.x, ty=threadIdx.y;
    for(int i=ty;i<32;i+=8)
        t[i][tx] = src[(size_t)(k0+i)*Nd + n0 + tx];
    __syncthreads();
    const int tid = ty*32+tx;
    const int wq = tid&7, nn = tid>>3;
    float v0=t[wq*4+0][nn], v1=t[wq*4+1][nn], v2=t[wq*4+2][nn], v3=t[wq*4+3][nn];
    bf16 h0=__float2bfloat16(v0), h1=__float2bfloat16(v1);
    bf16 h2=__float2bfloat16(v2), h3=__float2bfloat16(v3);
    size_t o = (size_t)(n0+nn)*Kd + k0 + wq*4;
    uint2 hv, lv;
    hv.x = (uint32_t)__bfloat16_as_ushort(h0) | ((uint32_t)__bfloat16_as_ushort(h1)<<16);
    hv.y = (uint32_t)__bfloat16_as_ushort(h2) | ((uint32_t)__bfloat16_as_ushort(h3)<<16);
    lv.x = packb(v0-__bfloat162float(h0), v1-__bfloat162float(h1));
    lv.y = packb(v2-__bfloat162float(h2), v3-__bfloat162float(h3));
    *(uint2*)&dhi[o] = hv;
    *(uint2*)&dlo[o] = lv;
}

// ---------- mma.sync split-bf16 GEMM: block 128x256, warp 64x64, K-step 32, 4-stage ----------
// stage (48KB): A rows 0..127 at +0 (row=128B: hi[0,64) lo[64,128)), B rows 0..255 at +16K
template<int MODE, int N, int K>
__global__ void __launch_bounds__(256,1) tgemm(const float* __restrict__ aux){
    constexpr int NKT = K/32;
    constexpr int STG = 49152;
    const int e = (MODE>=2)? blockIdx.z : 0;
    int Mrows = NTOK, pbase = 0;
    if(MODE>=2){
        Mrows = g_cnt[e]; pbase = g_basei[e];
        if((int)blockIdx.y*128 >= Mrows) return;
    }
    extern __shared__ char smem[];
    const uint32_t sb = s2u(smem);
    const int tid = threadIdx.x, lane = tid&31, wid = tid>>5;
    const int wm = wid>>2, wn = wid&3;
    const int m0 = blockIdx.y*128, n0 = blockIdx.x*256;

    const bf16 *Ahi,*Alo,*Bhi,*Blo;
    if(MODE==0){ Ahi=g_h_hi; Alo=g_h_lo; Bhi=g_waT_hi; Blo=g_waT_lo; }
    else if(MODE==1){ Ahi=g_y_hi; Alo=g_y_lo; Bhi=g_wpT_hi; Blo=g_wpT_lo; }
    else if(MODE==2){ Ahi=g_h2_hi; Alo=g_h2_lo;
        Bhi=g_w1T_hi+(size_t)e*HID*DIM; Blo=g_w1T_lo+(size_t)e*HID*DIM; }
    else { Ahi=g_pool_hi; Alo=g_pool_lo;
        Bhi=g_w2T_hi+(size_t)e*DIM*HID; Blo=g_w2T_lo+(size_t)e*DIM*HID; }

    // chunk mapping: row r = (tid>>3)+i*32, col chunk c = tid&7 (c<4: hi cols, c>=4: lo cols)
    const int cc = tid&7;
    const bool isHi = cc < 4;
    const int colel = (cc&3)*8;                      // element col within 32-wide K-step
    const uint32_t d0 = swz((uint32_t)((tid>>3)*128 + cc*16));
    const bf16 *pa[4]; bool av[4];
    #pragma unroll
    for(int i=0;i<4;++i){
        int r = (tid>>3) + i*32, gm = m0 + r;
        bool v = true; long rg = gm;
        if(MODE==2){ v = gm<Mrows; rg = v ? g_tok[e*MAXTOK+gm] : 0; }
        if(MODE==3){ v = gm<Mrows; rg = (long)pbase + (v?gm:0); }
        pa[i] = (isHi?Ahi:Alo) + (size_t)rg*K + colel; av[i]=v;
    }
    const bf16 *pb = (isHi?Bhi:Blo) + (size_t)(n0 + (tid>>3))*K + colel;

    float acc[4][8][4];
    #pragma unroll
    for(int a=0;a<4;++a)
        #pragma unroll
        for(int b=0;b<8;++b)
            #pragma unroll
            for(int c=0;c<4;++c) acc[a][b][c]=0.f;

    const int arow = wm*64 + (lane&15), achk = lane>>4;
    const int brow_b = wn*64 + ((lane>>4)&1)*8 + (lane&7), bchk = (lane>>3)&1;

    auto issue = [&](int kt){
        const uint32_t st = sb + (kt&3)*STG;
        const int ko = kt*32;
        #pragma unroll
        for(int i=0;i<4;++i) cp16(st+d0+i*4096, pa[i]+ko, av[i]);
        #pragma unroll
        for(int i=0;i<8;++i) cp16(st+16384+d0+i*4096, pb + (size_t)i*32*K + ko, true);
        asm volatile("cp.async.commit_group;":::"memory");
    };

    issue(0); issue(1); issue(2);
    for(int kt=0; kt<NKT; ++kt){
        if(kt<NKT-2)      { asm volatile("cp.async.wait_group 2;":::"memory"); }
        else if(kt<NKT-1) { asm volatile("cp.async.wait_group 1;":::"memory"); }
        else              { asm volatile("cp.async.wait_group 0;":::"memory"); }
        __syncthreads();
        if(kt+3<NKT) issue(kt+3);
        const uint32_t st = sb + (kt&3)*STG;
        #pragma unroll
        for(int k16=0;k16<2;++k16){
            uint32_t ah[4][4], al[4][4];
            #pragma unroll
            for(int mi=0;mi<4;++mi){
                uint32_t roff = (uint32_t)((arow+mi*16)*128 + k16*32 + achk*16);
                ldx4(ah[mi], st + swz(roff));
                ldx4(al[mi], st + swz(roff+64));
            }
            #pragma unroll
            for(int n16=0;n16<4;++n16){
                uint32_t roff = (uint32_t)((brow_b+n16*16)*128 + k16*32 + bchk*16);
                uint32_t rh[4], rl[4];
                ldx4(rh, st + 16384 + swz(roff));
                ldx4(rl, st + 16384 + swz(roff+64));
                #pragma unroll
                for(int mi=0;mi<4;++mi){
                    mma16816(acc[mi][n16*2],   ah[mi], rh);
                    mma16816(acc[mi][n16*2],   ah[mi], rl);
                    mma16816(acc[mi][n16*2],   al[mi], rh);
                    mma16816(acc[mi][n16*2+1], ah[mi], rh+2);
                    mma16816(acc[mi][n16*2+1], ah[mi], rl+2);
                    mma16816(acc[mi][n16*2+1], al[mi], rh+2);
                }
            }
        }
        __syncthreads();
    }

    const int r0 = lane>>2, c2 = (lane&3)*2;
    const float* bias = (MODE>=2)? (aux+(size_t)e*N) : aux;
    #pragma unroll
    for(int mi=0;mi<4;++mi){
        #pragma unroll
        for(int half=0; half<2; ++half){
            const int m = m0 + wm*64 + mi*16 + r0 + half*8;
            if(MODE>=2 && m>=Mrows) continue;
            int tok=0, slot=0; float wgt=0.f;
            if(MODE==3){ int ix=e*MAXTOK+m; tok=g_tok[ix]; wgt=g_wt[ix]; slot=g_slot[ix]; }
            #pragma unroll
            for(int ni=0;ni<8;++ni){
                const int col = n0 + wn*64 + ni*8 + c2;
                float dd0 = acc[mi][ni][half*2], dd1 = acc[mi][ni][half*2+1];
                if(MODE==0){
                    const int which = col>>10, r = col&1023, h = r>>6, d = r&63;
                    const int b = m>>11, t = m&2047;
                    size_t o = ((size_t)(b*16+h)*2048 + t)*64 + d;
                    bf16 *ph, *pl;
                    if(which==0){ dd0*=0.125f; dd1*=0.125f; ph=g_q_hi; pl=g_q_lo; }
                    else if(which==1){ ph=g_k_hi; pl=g_k_lo; }
                    else { ph=g_v_hi; pl=g_v_lo; }
                    bf16 h0=__float2bfloat16(dd0), h1=__float2bfloat16(dd1);
                    *(uint32_t*)&ph[o] = (uint32_t)__bfloat16_as_ushort(h0)
                                       | ((uint32_t)__bfloat16_as_ushort(h1)<<16);
                    *(uint32_t*)&pl[o] = packb(dd0-__bfloat162float(h0), dd1-__bfloat162float(h1));
                } else if(MODE==1){
                    const float* rx=aux+(size_t)m*N+col;
                    float2 w; w.x = rx[0]+dd0; w.y = rx[1]+dd1;
                    *(float2*)&g_x1[(size_t)m*N+col] = w;
                } else if(MODE==2){
                    size_t prow=(size_t)(pbase+m);
                    float v0=dd0+bias[col], v1=dd1+bias[col+1];
                    float gg0=0.5f*v0*(1.f+erff(v0*0.70710678f));
                    float gg1=0.5f*v1*(1.f+erff(v1*0.70710678f));
                    bf16 h0=__float2bfloat16(gg0), h1=__float2bfloat16(gg1);
                    *(uint32_t*)&g_pool_hi[prow*HID+col] =
                        (uint32_t)__bfloat16_as_ushort(h0) | ((uint32_t)__bfloat16_as_ushort(h1)<<16);
                    *(uint32_t*)&g_pool_lo[prow*HID+col] =
                        packb(gg0-__bfloat162float(h0), gg1-__bfloat162float(h1));
                } else {
                    float2 w; w.x = wgt*(dd0+bias[col]); w.y = wgt*(dd1+bias[col+1]);
                    *(float2*)&((slot?g_c1:g_c0)[(size_t)tok*DIM+col]) = w;
                }
            }
        }
    }
}

// ---------- tensor-core flash attention (R7-proven, unchanged) ----------
__global__ void __launch_bounds__(256,1) attn_mma(){
    extern __shared__ char smem[];
    const uint32_t sb = s2u(smem);
    const int tid=threadIdx.x, lane=tid&31, wid=tid>>5;
    const int bh = blockIdx.y;
    const int qt = (gridDim.x-1) - blockIdx.x;
    const int q0 = qt*128;
    const size_t pbase = (size_t)bh*2048*64;

    #pragma unroll
    for(int i=0;i<4;++i){
        int idx=tid+i*256, r=idx>>3, c=idx&7;
        uint32_t off = swz((uint32_t)(r*128+c*16));
        cp16(sb+off,        g_q_hi + pbase + (size_t)(q0+r)*64 + c*8, true);
        cp16(sb+16384+off,  g_q_lo + pbase + (size_t)(q0+r)*64 + c*8, true);
    }
    auto issueKV = [&](int kb){
        const uint32_t st = sb + 32768 + (kb%3)*32768;
        #pragma unroll
        for(int i=0;i<2;++i){
            int idx=tid+i*256, r=idx>>3, c=idx&7;
            uint32_t off = swz((uint32_t)(r*128+c*16));
            size_t src = pbase + (size_t)(kb*64+r)*64 + c*8;
            cp16(st+off,        g_k_hi+src, true);
            cp16(st+8192+off,   g_k_lo+src, true);
            cp16(st+16384+off,  g_v_hi+src, true);
            cp16(st+24576+off,  g_v_lo+src, true);
        }
        asm volatile("cp.async.commit_group;":::"memory");
    };
    const int kbmax = 2*qt+1;
    issueKV(0);
    issueKV(1);

    asm volatile("cp.async.wait_group 1;":::"memory");
    __syncthreads();
    uint32_t qh[4][4], ql[4][4];
    {
        const int qrow = wid*16 + (lane&15), qchk = lane>>4;
        #pragma unroll
        for(int k16=0;k16<4;++k16){
            uint32_t off = swz((uint32_t)(qrow*128 + k16*32 + qchk*16));
            ldx4(qh[k16], sb+off);
            ldx4(ql[k16], sb+16384+off);
        }
    }

    float O[8][4], mstat[2], lstat[2];
    #pragma unroll
    for(int t=0;t<8;++t){ O[t][0]=0;O[t][1]=0;O[t][2]=0;O[t][3]=0; }
    mstat[0]=mstat[1]=-1e30f; lstat[0]=lstat[1]=0.f;

    const int rloc = lane>>2, cloc = (lane&3)*2;
    const int brow_b = ((lane>>4)&1)*8 + (lane&7), bchk = (lane>>3)&1;
    const int vrow_b = ((lane>>3)&1)*8 + (lane&7), vcol_b = ((lane>>4)&1)*8;

    for(int kb=0; kb<=kbmax; ++kb){
        if(kb<kbmax){ asm volatile("cp.async.wait_group 1;":::"memory"); }
        else        { asm volatile("cp.async.wait_group 0;":::"memory"); }
        __syncthreads();
        if(kb+2<=kbmax) issueKV(kb+2);
        const uint32_t st = sb + 32768 + (kb%3)*32768;

        float s[8][4];
        #pragma unroll
        for(int t=0;t<8;++t){ s[t][0]=0;s[t][1]=0;s[t][2]=0;s[t][3]=0; }
        #pragma unroll
        for(int k16=0;k16<4;++k16){
            uint32_t bkh[8][2], bkl[8][2];
            #pragma unroll
            for(int n16=0;n16<4;++n16){
                uint32_t off = swz((uint32_t)((n16*16+brow_b)*128 + k16*32 + bchk*16));
                uint32_t r[4];
                ldx4(r, st+off);
                bkh[n16*2][0]=r[0]; bkh[n16*2][1]=r[1]; bkh[n16*2+1][0]=r[2]; bkh[n16*2+1][1]=r[3];
                ldx4(r, st+8192+off);
                bkl[n16*2][0]=r[0]; bkl[n16*2][1]=r[1]; bkl[n16*2+1][0]=r[2]; bkl[n16*2+1][1]=r[3];
            }
            #pragma unroll
            for(int t=0;t<8;++t){
                mma16816(s[t], qh[k16], bkh[t]);
                mma16816(s[t], qh[k16], bkl[t]);
                mma16816(s[t], ql[k16], bkh[t]);
            }
        }
        if(kb >= 2*qt){
            const int row0 = q0 + wid*16 + rloc;
            #pragma unroll
            for(int t=0;t<8;++t){
                int c0 = kb*64 + t*8 + cloc;
                if(c0   > row0  ) s[t][0]=-1e30f;
                if(c0+1 > row0  ) s[t][1]=-1e30f;
                if(c0   > row0+8) s[t][2]=-1e30f;
                if(c0+1 > row0+8) s[t][3]=-1e30f;
            }
        }
        float corr[2];
        #pragma unroll
        for(int rh=0; rh<2; ++rh){
            float mt=-1e30f;
            #pragma unroll
            for(int t=0;t<8;++t) mt = fmaxf(mt, fmaxf(s[t][rh*2], s[t][rh*2+1]));
            mt = fmaxf(mt, __shfl_xor_sync(~0u, mt, 1, 4));
            mt = fmaxf(mt, __shfl_xor_sync(~0u, mt, 2, 4));
            float mn = fmaxf(mstat[rh], mt);
            corr[rh] = __expf(mstat[rh]-mn); mstat[rh]=mn;
            float rs=0.f;
            #pragma unroll
            for(int t=0;t<8;++t){
                float p0=__expf(s[t][rh*2]-mn), p1=__expf(s[t][rh*2+1]-mn);
                s[t][rh*2]=p0; s[t][rh*2+1]=p1; rs += p0+p1;
            }
            rs += __shfl_xor_sync(~0u, rs, 1, 4);
            rs += __shfl_xor_sync(~0u, rs, 2, 4);
            lstat[rh] = lstat[rh]*corr[rh] + rs;
        }
        #pragma unroll
        for(int t=0;t<8;++t){
            O[t][0]*=corr[0]; O[t][1]*=corr[0]; O[t][2]*=corr[1]; O[t][3]*=corr[1];
        }
        uint32_t ph[4][4], pl[4][4];
        #pragma unroll
        for(int k16=0;k16<4;++k16){
            #pragma unroll
            for(int half=0; half<2; ++half){
                const int t = 2*k16+half;
                float f0=s[t][0], f1=s[t][1], f2=s[t][2], f3=s[t][3];
                ph[k16][half*2]   = packb(f0,f1);
                ph[k16][half*2+1] = packb(f2,f3);
                bf16 h0=__float2bfloat16(f0), h1=__float2bfloat16(f1);
                bf16 h2=__float2bfloat16(f2), h3=__float2bfloat16(f3);
                pl[k16][half*2]   = packb(f0-__bfloat162float(h0), f1-__bfloat162float(h1));
                pl[k16][half*2+1] = packb(f2-__bfloat162float(h2), f3-__bfloat162float(h3));
            }
        }
        #pragma unroll
        for(int k16=0;k16<4;++k16){
            uint32_t bvh[8][2], bvl[8][2];
            #pragma unroll
            for(int d16=0;d16<4;++d16){
                uint32_t off = swz((uint32_t)((k16*16+vrow_b)*128 + (d16*16+vcol_b)*2));
                uint32_t r[4];
                ldx4t(r, st+16384+off);
                bvh[d16*2][0]=r[0]; bvh[d16*2][1]=r[1]; bvh[d16*2+1][0]=r[2]; bvh[d16*2+1][1]=r[3];
                ldx4t(r, st+24576+off);
                bvl[d16*2][0]=r[0]; bvl[d16*2][1]=r[1]; bvl[d16*2+1][0]=r[2]; bvl[d16*2+1][1]=r[3];
            }
            #pragma unroll
            for(int t=0;t<8;++t){
                mma16816(O[t], ph[k16], bvh[t]);
                mma16816(O[t], ph[k16], bvl[t]);
                mma16816(O[t], pl[k16], bvh[t]);
            }
        }
        __syncthreads();
    }

    const int b = bh>>4, h = bh&15;
    #pragma unroll
    for(int rh=0; rh<2; ++rh){
        const float inv = 1.f/lstat[rh];
        const int row = q0 + wid*16 + rloc + rh*8;
        size_t base = (size_t)(b*TT+row)*DIM + h*64;
        #pragma unroll
        for(int t=0;t<8;++t){
            float v0 = O[t][rh*2]*inv, v1 = O[t][rh*2+1]*inv;
            size_t o = base + t*8 + cloc;
            bf16 h0=__float2bfloat16(v0), h1=__float2bfloat16(v1);
            g_y_hi[o]=h0; g_y_hi[o+1]=h1;
            g_y_lo[o]=__float2bfloat16(v0-__bfloat162float(h0));
            g_y_lo[o+1]=__float2bfloat16(v1-__bfloat162float(h1));
        }
    }
}

// ---------- router ----------
__global__ void router_kernel(const float* __restrict__ wr){
    const int n=blockIdx.x, tid=threadIdx.x;
    float acc[NEXP];
    #pragma unroll
    for(int e=0;e<NEXP;++e) acc[e]=0.f;
    const float* row=g_h2f+(size_t)n*DIM;
    for(int d=tid;d<DIM;d+=128){
        float hv=row[d];
        #pragma unroll
        for(int e=0;e<NEXP;++e) acc[e]+=hv*wr[d*NEXP+e];
    }
    __shared__ float sm[4][NEXP];
    #pragma unroll
    for(int e=0;e<NEXP;++e){
        float v=acc[e];
        #pragma unroll
        for(int o=16;o;o>>=1) v+=__shfl_xor_sync(~0u,v,o);
        if((tid&31)==0) sm[tid>>5][e]=v;
    }
    __syncthreads();
    if(tid==0){
        float lg[NEXP];
        #pragma unroll
        for(int e=0;e<NEXP;++e) lg[e]=sm[0][e]+sm[1][e]+sm[2][e]+sm[3][e];
        int e0=0;
        #pragma unroll
        for(int e=1;e<NEXP;++e) if(lg[e]>lg[e0]) e0=e;
        int e1=-1;
        #pragma unroll
        for(int e=0;e<NEXP;++e) if(e!=e0 && (e1<0||lg[e]>lg[e1])) e1=e;
        float w0=1.f/(1.f+__expf(lg[e1]-lg[e0])), w1=1.f-w0;
        int p0=atomicAdd(&g_cnt[e0],1);
        g_tok[e0*MAXTOK+p0]=n; g_wt[e0*MAXTOK+p0]=w0; g_slot[e0*MAXTOK+p0]=0;
        int p1=atomicAdd(&g_cnt[e1],1);
        g_tok[e1*MAXTOK+p1]=n; g_wt[e1*MAXTOK+p1]=w1; g_slot[e1*MAXTOK+p1]=1;
    }
}

// ---------- launch (R7-proven order) ----------
extern "C" void kernel_launch(void* const* d_in, const int* in_sizes, int n_in,
                              void* d_out, int out_size){
    const float* x      =(const float*)d_in[0];
    const float* ln1_g  =(const float*)d_in[1];
    const float* ln1_b  =(const float*)d_in[2];
    const float* w_attn =(const float*)d_in[3];
    const float* w_proj =(const float*)d_in[4];
    const float* ln2_g  =(const float*)d_in[5];
    const float* ln2_b  =(const float*)d_in[6];
    const float* w_rtr  =(const float*)d_in[7];
    const float* w1     =(const float*)d_in[8];
    const float* b1     =(const float*)d_in[9];
    const float* w2     =(const float*)d_in[10];
    const float* b2     =(const float*)d_in[11];
    float* out=(float*)d_out;

    const int SMG = 196608;
    cudaFuncSetAttribute(tgemm<0,3*DIM,DIM>, cudaFuncAttributeMaxDynamicSharedMemorySize, SMG);
    cudaFuncSetAttribute(tgemm<1,DIM,DIM>,   cudaFuncAttributeMaxDynamicSharedMemorySize, SMG);
    cudaFuncSetAttribute(tgemm<2,HID,DIM>,   cudaFuncAttributeMaxDynamicSharedMemorySize, SMG);
    cudaFuncSetAttribute(tgemm<3,DIM,HID>,   cudaFuncAttributeMaxDynamicSharedMemorySize, SMG);
    const int SMA = 131072;
    cudaFuncSetAttribute(attn_mma, cudaFuncAttributeMaxDynamicSharedMemorySize, SMA);

    zero_cnt_kernel<<<1,32>>>();
    transpose_split<0><<<dim3(96,32,1), dim3(32,8)>>>(w_attn);
    transpose_split<1><<<dim3(32,32,1), dim3(32,8)>>>(w_proj);
    transpose_split<2><<<dim3(128,32,NEXP), dim3(32,8)>>>(w1);
    transpose_split<3><<<dim3(32,128,NEXP), dim3(32,8)>>>(w2);

    ln_kernel<0><<<NTOK,256>>>(x, ln1_g, ln1_b);
    tgemm<0,3*DIM,DIM><<<dim3(12,32,1),256,SMG>>>(nullptr);
    attn_mma<<<dim3(TT/128, BB*16),256,SMA>>>();
    tgemm<1,DIM,DIM><<<dim3(4,32,1),256,SMG>>>(x);
    ln_kernel<1><<<NTOK,256>>>(nullptr, ln2_g, ln2_b);
    router_kernel<<<NTOK,128>>>(w_rtr);
    base_kernel<<<1,32>>>();
    tgemm<2,HID,DIM><<<dim3(16,32,NEXP),256,SMG>>>(b1);
    tgemm<3,DIM,HID><<<dim3(4,32,NEXP),256,SMG>>>(b2);
    final_kernel<<<NTOK*DIM/256,256>>>(out);
}

// round 10
// speedup vs baseline: 1.4273x; 1.0475x over previous
#include <cuda_runtime.h>
#include <cuda_bf16.h>
#include <math.h>
#include <stdint.h>

#define BB 2
#define TT 2048
#define DIM 1024
#define NTOK 4096
#define NEXP 8
#define HID 4096
#define MAXTOK 4096
typedef __nv_bfloat16 bf16;

// ---------- scratch ----------
__device__ bf16 g_h_hi[NTOK*DIM], g_h_lo[NTOK*DIM];
__device__ bf16 g_q_hi[32*2048*64], g_q_lo[32*2048*64];
__device__ bf16 g_k_hi[32*2048*64], g_k_lo[32*2048*64];
__device__ bf16 g_v_hi[32*2048*64], g_v_lo[32*2048*64];
__device__ bf16 g_y_hi[NTOK*DIM], g_y_lo[NTOK*DIM];
__device__ float g_x1[NTOK*DIM], g_h2f[NTOK*DIM];
__device__ bf16 g_h2_hi[NTOK*DIM], g_h2_lo[NTOK*DIM];
__device__ bf16 g_pool_hi[(size_t)2*NTOK*HID], g_pool_lo[(size_t)2*NTOK*HID];
__device__ float g_c0[NTOK*DIM], g_c1[NTOK*DIM];
__device__ int g_cnt[NEXP], g_basei[NEXP], g_tok[NEXP*MAXTOK], g_slot[NEXP*MAXTOK];
__device__ float g_wt[NEXP*MAXTOK];
__device__ bf16 g_waT_hi[(size_t)3*DIM*DIM], g_waT_lo[(size_t)3*DIM*DIM];
__device__ bf16 g_wpT_hi[(size_t)DIM*DIM],   g_wpT_lo[(size_t)DIM*DIM];
__device__ bf16 g_w1T_hi[(size_t)NEXP*HID*DIM], g_w1T_lo[(size_t)NEXP*HID*DIM];
__device__ bf16 g_w2T_hi[(size_t)NEXP*DIM*HID], g_w2T_lo[(size_t)NEXP*DIM*HID];

// ---------- ptx helpers ----------
__device__ __forceinline__ uint32_t s2u(const void* p){
    uint32_t a; asm("{ .reg .u64 t; cvta.to.shared.u64 t, %1; cvt.u32.u64 %0, t; }":"=r"(a):"l"(p)); return a;
}
__device__ __forceinline__ uint32_t swz(uint32_t o){ return o ^ ((o>>3)&0x70); }
__device__ __forceinline__ void cp16(uint32_t d, const bf16* s, bool v){
    asm volatile("cp.async.cg.shared.global [%0], [%1], 16, %2;"
        ::"r"(d),"l"(__cvta_generic_to_global(s)),"r"(v?16:0));
}
__device__ __forceinline__ void ldx4(uint32_t* r, uint32_t a){
    asm volatile("ldmatrix.sync.aligned.m8n8.x4.shared.b16 {%0,%1,%2,%3},[%4];"
        :"=r"(r[0]),"=r"(r[1]),"=r"(r[2]),"=r"(r[3]):"r"(a));
}
__device__ __forceinline__ void ldx4t(uint32_t* r, uint32_t a){
    asm volatile("ldmatrix.sync.aligned.m8n8.x4.trans.shared.b16 {%0,%1,%2,%3},[%4];"
        :"=r"(r[0]),"=r"(r[1]),"=r"(r[2]),"=r"(r[3]):"r"(a));
}
__device__ __forceinline__ void mma16816(float* d, const uint32_t* a, const uint32_t* b){
    asm volatile("mma.sync.aligned.m16n8k16.row.col.f32.bf16.bf16.f32 "
        "{%0,%1,%2,%3},{%4,%5,%6,%7},{%8,%9},{%0,%1,%2,%3};"
        : "+f"(d[0]),"+f"(d[1]),"+f"(d[2]),"+f"(d[3])
        : "r"(a[0]),"r"(a[1]),"r"(a[2]),"r"(a[3]),"r"(b[0]),"r"(b[1]));
}
__device__ __forceinline__ uint32_t packb(float f0, float f1){
    bf16 b0=__float2bfloat16(f0), b1=__float2bfloat16(f1);
    return (uint32_t)__bfloat16_as_ushort(b0) | ((uint32_t)__bfloat16_as_ushort(b1)<<16);
}

// ---------- small kernels ----------
__global__ void zero_cnt_kernel(){ if(threadIdx.x<NEXP) g_cnt[threadIdx.x]=0; }
__global__ void base_kernel(){
    if(threadIdx.x==0){ int s=0; for(int e=0;e<NEXP;++e){ g_basei[e]=s; s+=g_cnt[e]; } }
}
__global__ void final_kernel(float* __restrict__ out){
    int i = blockIdx.x*256 + threadIdx.x;
    out[i] = g_x1[i] + g_c0[i] + g_c1[i];
}

// ---------- layernorm ----------
template<int WHICH>
__global__ void ln_kernel(const float* __restrict__ in, const float* __restrict__ gam,
                          const float* __restrict__ bet){
    __shared__ float sx[DIM]; __shared__ float red[8];
    const int n=blockIdx.x, tid=threadIdx.x;
    const float* row = (WHICH==0 ? in : g_x1) + (size_t)n*DIM;
    float4 x4 = ((const float4*)row)[tid];
    ((float4*)sx)[tid] = x4;
    float s = x4.x+x4.y+x4.z+x4.w;
    #pragma unroll
    for(int o=16;o;o>>=1) s += __shfl_xor_sync(~0u,s,o);
    if((tid&31)==0) red[tid>>5]=s;
    __syncthreads();
    float mu = (red[0]+red[1]+red[2]+red[3]+red[4]+red[5]+red[6]+red[7])*(1.f/DIM);
    float sq=0.f;
    #pragma unroll
    for(int p=0;p<4;++p){ float d=sx[tid+p*256]-mu; sq+=d*d; }
    #pragma unroll
    for(int o=16;o;o>>=1) sq += __shfl_xor_sync(~0u,sq,o);
    __syncthreads();
    if((tid&31)==0) red[tid>>5]=sq;
    __syncthreads();
    float var=(red[0]+red[1]+red[2]+red[3]+red[4]+red[5]+red[6]+red[7])*(1.f/DIM);
    float rs = rsqrtf(var+1e-5f);
    #pragma unroll
    for(int p=0;p<4;++p){
        int d=tid+p*256;
        float v = (sx[d]-mu)*rs*gam[d]+bet[d];
        size_t o=(size_t)n*DIM+d;
        bf16 h = __float2bfloat16(v);
        bf16 l = __float2bfloat16(v - __bfloat162float(h));
        if(WHICH==0){ g_h_hi[o]=h; g_h_lo[o]=l; }
        else { g_h2f[o]=v; g_h2_hi[o]=h; g_h2_lo[o]=l; }
    }
}

// ---------- weight transpose + split (R7-proven 32x32 version) ----------
template<int WHICH>
__global__ void transpose_split(const float* __restrict__ src){
    constexpr int Kd = (WHICH==3)?HID:DIM;
    constexpr int Nd = (WHICH==0)?3*DIM:((WHICH==2)?HID:DIM);
    bf16 *dhi, *dlo;
    if(WHICH==0){dhi=g_waT_hi;dlo=g_waT_lo;}
    else if(WHICH==1){dhi=g_wpT_hi;dlo=g_wpT_lo;}
    else if(WHICH==2){dhi=g_w1T_hi;dlo=g_w1T_lo;}
    else {dhi=g_w2T_hi;dlo=g_w2T_lo;}
    const int e=blockIdx.z;
    src += (size_t)e*Kd*Nd; dhi += (size_t)e*(size_t)Nd*Kd; dlo += (size_t)e*(size_t)Nd*Kd;
    __shared__ float t[32][33];
    const int n0=blockIdx.x*32, k0=blockIdx.y*32;
    const int tx=threadIdx.x, ty=threadIdx.y;
    for(int i=ty;i<32;i+=8)
        t[i][tx] = src[(size_t)(k0+i)*Nd + n0 + tx];
    __syncthreads();
    const int tid = ty*32+tx;
    const int wq = tid&7, nn = tid>>3;
    float v0=t[wq*4+0][nn], v1=t[wq*4+1][nn], v2=t[wq*4+2][nn], v3=t[wq*4+3][nn];
    bf16 h0=__float2bfloat16(v0), h1=__float2bfloat16(v1);
    bf16 h2=__float2bfloat16(v2), h3=__float2bfloat16(v3);
    size_t o = (size_t)(n0+nn)*Kd + k0 + wq*4;
    uint2 hv, lv;
    hv.x = (uint32_t)__bfloat16_as_ushort(h0) | ((uint32_t)__bfloat16_as_ushort(h1)<<16);
    hv.y = (uint32_t)__bfloat16_as_ushort(h2) | ((uint32_t)__bfloat16_as_ushort(h3)<<16);
    lv.x = packb(v0-__bfloat162float(h0), v1-__bfloat162float(h1));
    lv.y = packb(v2-__bfloat162float(h2), v3-__bfloat162float(h3));
    *(uint2*)&dhi[o] = hv;
    *(uint2*)&dlo[o] = lv;
}

// ---------- mma.sync split-bf16 GEMM ----------
// block 128x128, 128 threads (4 warps, warp tile 64x64), K-step 32,
// 3 stages x 32KB (A 16K + B 16K, row = hi 64B | lo 64B), 2 CTAs/SM.
// schedule: pre-issue 0,1; per iter: wait(1|0); sync; issue(kt+2); compute. single sync.
template<int MODE, int N, int K>
__global__ void __launch_bounds__(128,2) tgemm(const float* __restrict__ aux){
    constexpr int NKT = K/32;
    constexpr int STG = 32768;
    const int e = (MODE>=2)? blockIdx.z : 0;
    int Mrows = NTOK, pbase = 0;
    if(MODE>=2){
        Mrows = g_cnt[e]; pbase = g_basei[e];
        if((int)blockIdx.y*128 >= Mrows) return;
    }
    extern __shared__ char smem[];
    const uint32_t sb = s2u(smem);
    const int tid = threadIdx.x, lane = tid&31, wid = tid>>5;
    const int wm = wid>>1, wn = wid&1;       // warps 2x2, warp tile 64x64
    const int m0 = blockIdx.y*128, n0 = blockIdx.x*128;

    const bf16 *Ahi,*Alo,*Bhi,*Blo;
    if(MODE==0){ Ahi=g_h_hi; Alo=g_h_lo; Bhi=g_waT_hi; Blo=g_waT_lo; }
    else if(MODE==1){ Ahi=g_y_hi; Alo=g_y_lo; Bhi=g_wpT_hi; Blo=g_wpT_lo; }
    else if(MODE==2){ Ahi=g_h2_hi; Alo=g_h2_lo;
        Bhi=g_w1T_hi+(size_t)e*HID*DIM; Blo=g_w1T_lo+(size_t)e*HID*DIM; }
    else { Ahi=g_pool_hi; Alo=g_pool_lo;
        Bhi=g_w2T_hi+(size_t)e*DIM*HID; Blo=g_w2T_lo+(size_t)e*DIM*HID; }

    // chunk plan: row r = (tid>>3)+i*16 (i<8), col chunk cc=tid&7 (cc<4: hi, else lo)
    const int cc = tid&7;
    const bool isHi = cc < 4;
    const int colel = (cc&3)*8;
    const uint32_t d0 = swz((uint32_t)((tid>>3)*128 + cc*16));   // +i*2048 swizzle-invariant
    const bf16 *pa[8]; bool av[8];
    #pragma unroll
    for(int i=0;i<8;++i){
        int r = (tid>>3) + i*16, gm = m0 + r;
        bool v = true; long rg = gm;
        if(MODE==2){ v = gm<Mrows; rg = v ? g_tok[e*MAXTOK+gm] : 0; }
        if(MODE==3){ v = gm<Mrows; rg = (long)pbase + (v?gm:0); }
        pa[i] = (isHi?Ahi:Alo) + (size_t)rg*K + colel; av[i]=v;
    }
    const bf16 *pb = (isHi?Bhi:Blo) + (size_t)(n0 + (tid>>3))*K + colel;

    float acc[4][8][4];
    #pragma unroll
    for(int a=0;a<4;++a)
        #pragma unroll
        for(int b=0;b<8;++b)
            #pragma unroll
            for(int c=0;c<4;++c) acc[a][b][c]=0.f;

    const int arow = wm*64 + (lane&15), achk = lane>>4;
    const int brow_b = wn*64 + ((lane>>4)&1)*8 + (lane&7), bchk = (lane>>3)&1;

    auto issue = [&](int kt){
        const uint32_t st = sb + (kt%3)*STG;
        const int ko = kt*32;
        #pragma unroll
        for(int i=0;i<8;++i) cp16(st+d0+i*2048, pa[i]+ko, av[i]);
        #pragma unroll
        for(int i=0;i<8;++i) cp16(st+16384+d0+i*2048, pb + (size_t)i*16*K + ko, true);
        asm volatile("cp.async.commit_group;":::"memory");
    };

    issue(0); issue(1);
    for(int kt=0; kt<NKT; ++kt){
        if(kt<NKT-1){ asm volatile("cp.async.wait_group 1;":::"memory"); }
        else        { asm volatile("cp.async.wait_group 0;":::"memory"); }
        __syncthreads();
        if(kt+2<NKT) issue(kt+2);       // writes stage (kt-1)%3: all reads done per sync above
        const uint32_t st = sb + (kt%3)*STG;
        #pragma unroll
        for(int k16=0;k16<2;++k16){
            uint32_t ah[4][4], al[4][4];
            #pragma unroll
            for(int mi=0;mi<4;++mi){
                uint32_t roff = (uint32_t)((arow+mi*16)*128 + k16*32 + achk*16);
                ldx4(ah[mi], st + swz(roff));
                ldx4(al[mi], st + swz(roff+64));
            }
            #pragma unroll
            for(int n16=0;n16<4;++n16){
                uint32_t roff = (uint32_t)((brow_b+n16*16)*128 + k16*32 + bchk*16);
                uint32_t rh[4], rl[4];
                ldx4(rh, st + 16384 + swz(roff));
                ldx4(rl, st + 16384 + swz(roff+64));
                #pragma unroll
                for(int mi=0;mi<4;++mi){
                    mma16816(acc[mi][n16*2],   ah[mi], rh);
                    mma16816(acc[mi][n16*2],   ah[mi], rl);
                    mma16816(acc[mi][n16*2],   al[mi], rh);
                    mma16816(acc[mi][n16*2+1], ah[mi], rh+2);
                    mma16816(acc[mi][n16*2+1], ah[mi], rl+2);
                    mma16816(acc[mi][n16*2+1], al[mi], rh+2);
                }
            }
        }
    }

    const int r0 = lane>>2, c2 = (lane&3)*2;
    const float* bias = (MODE>=2)? (aux+(size_t)e*N) : aux;
    #pragma unroll
    for(int mi=0;mi<4;++mi){
        #pragma unroll
        for(int half=0; half<2; ++half){
            const int m = m0 + wm*64 + mi*16 + r0 + half*8;
            if(MODE>=2 && m>=Mrows) continue;
            int tok=0, slot=0; float wgt=0.f;
            if(MODE==3){ int ix=e*MAXTOK+m; tok=g_tok[ix]; wgt=g_wt[ix]; slot=g_slot[ix]; }
            #pragma unroll
            for(int ni=0;ni<8;++ni){
                const int col = n0 + wn*64 + ni*8 + c2;
                float dd0 = acc[mi][ni][half*2], dd1 = acc[mi][ni][half*2+1];
                if(MODE==0){
                    const int which = col>>10, r = col&1023, h = r>>6, d = r&63;
                    const int b = m>>11, t = m&2047;
                    size_t o = ((size_t)(b*16+h)*2048 + t)*64 + d;
                    bf16 *ph, *pl;
                    if(which==0){ dd0*=0.125f; dd1*=0.125f; ph=g_q_hi; pl=g_q_lo; }
                    else if(which==1){ ph=g_k_hi; pl=g_k_lo; }
                    else { ph=g_v_hi; pl=g_v_lo; }
                    bf16 h0=__float2bfloat16(dd0), h1=__float2bfloat16(dd1);
                    *(uint32_t*)&ph[o] = (uint32_t)__bfloat16_as_ushort(h0)
                                       | ((uint32_t)__bfloat16_as_ushort(h1)<<16);
                    *(uint32_t*)&pl[o] = packb(dd0-__bfloat162float(h0), dd1-__bfloat162float(h1));
                } else if(MODE==1){
                    const float* rx=aux+(size_t)m*N+col;
                    float2 w; w.x = rx[0]+dd0; w.y = rx[1]+dd1;
                    *(float2*)&g_x1[(size_t)m*N+col] = w;
                } else if(MODE==2){
                    size_t prow=(size_t)(pbase+m);
                    float v0=dd0+bias[col], v1=dd1+bias[col+1];
                    float gg0=0.5f*v0*(1.f+erff(v0*0.70710678f));
                    float gg1=0.5f*v1*(1.f+erff(v1*0.70710678f));
                    bf16 h0=__float2bfloat16(gg0), h1=__float2bfloat16(gg1);
                    *(uint32_t*)&g_pool_hi[prow*HID+col] =
                        (uint32_t)__bfloat16_as_ushort(h0) | ((uint32_t)__bfloat16_as_ushort(h1)<<16);
                    *(uint32_t*)&g_pool_lo[prow*HID+col] =
                        packb(gg0-__bfloat162float(h0), gg1-__bfloat162float(h1));
                } else {
                    float2 w; w.x = wgt*(dd0+bias[col]); w.y = wgt*(dd1+bias[col+1]);
                    *(float2*)&((slot?g_c1:g_c0)[(size_t)tok*DIM+col]) = w;
                }
            }
        }
    }
}

// ---------- tensor-core flash attention (R7-proven, unchanged) ----------
__global__ void __launch_bounds__(256,1) attn_mma(){
    extern __shared__ char smem[];
    const uint32_t sb = s2u(smem);
    const int tid=threadIdx.x, lane=tid&31, wid=tid>>5;
    const int bh = blockIdx.y;
    const int qt = (gridDim.x-1) - blockIdx.x;
    const int q0 = qt*128;
    const size_t pbase = (size_t)bh*2048*64;

    #pragma unroll
    for(int i=0;i<4;++i){
        int idx=tid+i*256, r=idx>>3, c=idx&7;
        uint32_t off = swz((uint32_t)(r*128+c*16));
        cp16(sb+off,        g_q_hi + pbase + (size_t)(q0+r)*64 + c*8, true);
        cp16(sb+16384+off,  g_q_lo + pbase + (size_t)(q0+r)*64 + c*8, true);
    }
    auto issueKV = [&](int kb){
        const uint32_t st = sb + 32768 + (kb%3)*32768;
        #pragma unroll
        for(int i=0;i<2;++i){
            int idx=tid+i*256, r=idx>>3, c=idx&7;
            uint32_t off = swz((uint32_t)(r*128+c*16));
            size_t src = pbase + (size_t)(kb*64+r)*64 + c*8;
            cp16(st+off,        g_k_hi+src, true);
            cp16(st+8192+off,   g_k_lo+src, true);
            cp16(st+16384+off,  g_v_hi+src, true);
            cp16(st+24576+off,  g_v_lo+src, true);
        }
        asm volatile("cp.async.commit_group;":::"memory");
    };
    const int kbmax = 2*qt+1;
    issueKV(0);
    issueKV(1);

    asm volatile("cp.async.wait_group 1;":::"memory");
    __syncthreads();
    uint32_t qh[4][4], ql[4][4];
    {
        const int qrow = wid*16 + (lane&15), qchk = lane>>4;
        #pragma unroll
        for(int k16=0;k16<4;++k16){
            uint32_t off = swz((uint32_t)(qrow*128 + k16*32 + qchk*16));
            ldx4(qh[k16], sb+off);
            ldx4(ql[k16], sb+16384+off);
        }
    }

    float O[8][4], mstat[2], lstat[2];
    #pragma unroll
    for(int t=0;t<8;++t){ O[t][0]=0;O[t][1]=0;O[t][2]=0;O[t][3]=0; }
    mstat[0]=mstat[1]=-1e30f; lstat[0]=lstat[1]=0.f;

    const int rloc = lane>>2, cloc = (lane&3)*2;
    const int brow_b = ((lane>>4)&1)*8 + (lane&7), bchk = (lane>>3)&1;
    const int vrow_b = ((lane>>3)&1)*8 + (lane&7), vcol_b = ((lane>>4)&1)*8;

    for(int kb=0; kb<=kbmax; ++kb){
        if(kb<kbmax){ asm volatile("cp.async.wait_group 1;":::"memory"); }
        else        { asm volatile("cp.async.wait_group 0;":::"memory"); }
        __syncthreads();
        if(kb+2<=kbmax) issueKV(kb+2);
        const uint32_t st = sb + 32768 + (kb%3)*32768;

        float s[8][4];
        #pragma unroll
        for(int t=0;t<8;++t){ s[t][0]=0;s[t][1]=0;s[t][2]=0;s[t][3]=0; }
        #pragma unroll
        for(int k16=0;k16<4;++k16){
            uint32_t bkh[8][2], bkl[8][2];
            #pragma unroll
            for(int n16=0;n16<4;++n16){
                uint32_t off = swz((uint32_t)((n16*16+brow_b)*128 + k16*32 + bchk*16));
                uint32_t r[4];
                ldx4(r, st+off);
                bkh[n16*2][0]=r[0]; bkh[n16*2][1]=r[1]; bkh[n16*2+1][0]=r[2]; bkh[n16*2+1][1]=r[3];
                ldx4(r, st+8192+off);
                bkl[n16*2][0]=r[0]; bkl[n16*2][1]=r[1]; bkl[n16*2+1][0]=r[2]; bkl[n16*2+1][1]=r[3];
            }
            #pragma unroll
            for(int t=0;t<8;++t){
                mma16816(s[t], qh[k16], bkh[t]);
                mma16816(s[t], qh[k16], bkl[t]);
                mma16816(s[t], ql[k16], bkh[t]);
            }
        }
        if(kb >= 2*qt){
            const int row0 = q0 + wid*16 + rloc;
            #pragma unroll
            for(int t=0;t<8;++t){
                int c0 = kb*64 + t*8 + cloc;
                if(c0   > row0  ) s[t][0]=-1e30f;
                if(c0+1 > row0  ) s[t][1]=-1e30f;
                if(c0   > row0+8) s[t][2]=-1e30f;
                if(c0+1 > row0+8) s[t][3]=-1e30f;
            }
        }
        float corr[2];
        #pragma unroll
        for(int rh=0; rh<2; ++rh){
            float mt=-1e30f;
            #pragma unroll
            for(int t=0;t<8;++t) mt = fmaxf(mt, fmaxf(s[t][rh*2], s[t][rh*2+1]));
            mt = fmaxf(mt, __shfl_xor_sync(~0u, mt, 1, 4));
            mt = fmaxf(mt, __shfl_xor_sync(~0u, mt, 2, 4));
            float mn = fmaxf(mstat[rh], mt);
            corr[rh] = __expf(mstat[rh]-mn); mstat[rh]=mn;
            float rs=0.f;
            #pragma unroll
            for(int t=0;t<8;++t){
                float p0=__expf(s[t][rh*2]-mn), p1=__expf(s[t][rh*2+1]-mn);
                s[t][rh*2]=p0; s[t][rh*2+1]=p1; rs += p0+p1;
            }
            rs += __shfl_xor_sync(~0u, rs, 1, 4);
            rs += __shfl_xor_sync(~0u, rs, 2, 4);
            lstat[rh] = lstat[rh]*corr[rh] + rs;
        }
        #pragma unroll
        for(int t=0;t<8;++t){
            O[t][0]*=corr[0]; O[t][1]*=corr[0]; O[t][2]*=corr[1]; O[t][3]*=corr[1];
        }
        uint32_t ph[4][4], pl[4][4];
        #pragma unroll
        for(int k16=0;k16<4;++k16){
            #pragma unroll
            for(int half=0; half<2; ++half){
                const int t = 2*k16+half;
                float f0=s[t][0], f1=s[t][1], f2=s[t][2], f3=s[t][3];
                ph[k16][half*2]   = packb(f0,f1);
                ph[k16][half*2+1] = packb(f2,f3);
                bf16 h0=__float2bfloat16(f0), h1=__float2bfloat16(f1);
                bf16 h2=__float2bfloat16(f2), h3=__float2bfloat16(f3);
                pl[k16][half*2]   = packb(f0-__bfloat162float(h0), f1-__bfloat162float(h1));
                pl[k16][half*2+1] = packb(f2-__bfloat162float(h2), f3-__bfloat162float(h3));
            }
        }
        #pragma unroll
        for(int k16=0;k16<4;++k16){
            uint32_t bvh[8][2], bvl[8][2];
            #pragma unroll
            for(int d16=0;d16<4;++d16){
                uint32_t off = swz((uint32_t)((k16*16+vrow_b)*128 + (d16*16+vcol_b)*2));
                uint32_t r[4];
                ldx4t(r, st+16384+off);
                bvh[d16*2][0]=r[0]; bvh[d16*2][1]=r[1]; bvh[d16*2+1][0]=r[2]; bvh[d16*2+1][1]=r[3];
                ldx4t(r, st+24576+off);
                bvl[d16*2][0]=r[0]; bvl[d16*2][1]=r[1]; bvl[d16*2+1][0]=r[2]; bvl[d16*2+1][1]=r[3];
            }
            #pragma unroll
            for(int t=0;t<8;++t){
                mma16816(O[t], ph[k16], bvh[t]);
                mma16816(O[t], ph[k16], bvl[t]);
                mma16816(O[t], pl[k16], bvh[t]);
            }
        }
        __syncthreads();
    }

    const int b = bh>>4, h = bh&15;
    #pragma unroll
    for(int rh=0; rh<2; ++rh){
        const float inv = 1.f/lstat[rh];
        const int row = q0 + wid*16 + rloc + rh*8;
        size_t base = (size_t)(b*TT+row)*DIM + h*64;
        #pragma unroll
        for(int t=0;t<8;++t){
            float v0 = O[t][rh*2]*inv, v1 = O[t][rh*2+1]*inv;
            size_t o = base + t*8 + cloc;
            bf16 h0=__float2bfloat16(v0), h1=__float2bfloat16(v1);
            g_y_hi[o]=h0; g_y_hi[o+1]=h1;
            g_y_lo[o]=__float2bfloat16(v0-__bfloat162float(h0));
            g_y_lo[o+1]=__float2bfloat16(v1-__bfloat162float(h1));
        }
    }
}

// ---------- router ----------
__global__ void router_kernel(const float* __restrict__ wr){
    const int n=blockIdx.x, tid=threadIdx.x;
    float acc[NEXP];
    #pragma unroll
    for(int e=0;e<NEXP;++e) acc[e]=0.f;
    const float* row=g_h2f+(size_t)n*DIM;
    for(int d=tid;d<DIM;d+=128){
        float hv=row[d];
        #pragma unroll
        for(int e=0;e<NEXP;++e) acc[e]+=hv*wr[d*NEXP+e];
    }
    __shared__ float sm[4][NEXP];
    #pragma unroll
    for(int e=0;e<NEXP;++e){
        float v=acc[e];
        #pragma unroll
        for(int o=16;o;o>>=1) v+=__shfl_xor_sync(~0u,v,o);
        if((tid&31)==0) sm[tid>>5][e]=v;
    }
    __syncthreads();
    if(tid==0){
        float lg[NEXP];
        #pragma unroll
        for(int e=0;e<NEXP;++e) lg[e]=sm[0][e]+sm[1][e]+sm[2][e]+sm[3][e];
        int e0=0;
        #pragma unroll
        for(int e=1;e<NEXP;++e) if(lg[e]>lg[e0]) e0=e;
        int e1=-1;
        #pragma unroll
        for(int e=0;e<NEXP;++e) if(e!=e0 && (e1<0||lg[e]>lg[e1])) e1=e;
        float w0=1.f/(1.f+__expf(lg[e1]-lg[e0])), w1=1.f-w0;
        int p0=atomicAdd(&g_cnt[e0],1);
        g_tok[e0*MAXTOK+p0]=n; g_wt[e0*MAXTOK+p0]=w0; g_slot[e0*MAXTOK+p0]=0;
        int p1=atomicAdd(&g_cnt[e1],1);
        g_tok[e1*MAXTOK+p1]=n; g_wt[e1*MAXTOK+p1]=w1; g_slot[e1*MAXTOK+p1]=1;
    }
}

// ---------- launch (R7-proven order) ----------
extern "C" void kernel_launch(void* const* d_in, const int* in_sizes, int n_in,
                              void* d_out, int out_size){
    const float* x      =(const float*)d_in[0];
    const float* ln1_g  =(const float*)d_in[1];
    const float* ln1_b  =(const float*)d_in[2];
    const float* w_attn =(const float*)d_in[3];
    const float* w_proj =(const float*)d_in[4];
    const float* ln2_g  =(const float*)d_in[5];
    const float* ln2_b  =(const float*)d_in[6];
    const float* w_rtr  =(const float*)d_in[7];
    const float* w1     =(const float*)d_in[8];
    const float* b1     =(const float*)d_in[9];
    const float* w2     =(const float*)d_in[10];
    const float* b2     =(const float*)d_in[11];
    float* out=(float*)d_out;

    const int SMG = 98304;
    cudaFuncSetAttribute(tgemm<0,3*DIM,DIM>, cudaFuncAttributeMaxDynamicSharedMemorySize, SMG);
    cudaFuncSetAttribute(tgemm<1,DIM,DIM>,   cudaFuncAttributeMaxDynamicSharedMemorySize, SMG);
    cudaFuncSetAttribute(tgemm<2,HID,DIM>,   cudaFuncAttributeMaxDynamicSharedMemorySize, SMG);
    cudaFuncSetAttribute(tgemm<3,DIM,HID>,   cudaFuncAttributeMaxDynamicSharedMemorySize, SMG);
    const int SMA = 131072;
    cudaFuncSetAttribute(attn_mma, cudaFuncAttributeMaxDynamicSharedMemorySize, SMA);

    zero_cnt_kernel<<<1,32>>>();
    transpose_split<0><<<dim3(96,32,1), dim3(32,8)>>>(w_attn);
    transpose_split<1><<<dim3(32,32,1), dim3(32,8)>>>(w_proj);
    transpose_split<2><<<dim3(128,32,NEXP), dim3(32,8)>>>(w1);
    transpose_split<3><<<dim3(32,128,NEXP), dim3(32,8)>>>(w2);

    ln_kernel<0><<<NTOK,256>>>(x, ln1_g, ln1_b);
    tgemm<0,3*DIM,DIM><<<dim3(24,32,1),128,SMG>>>(nullptr);
    attn_mma<<<dim3(TT/128, BB*16),256,SMA>>>();
    tgemm<1,DIM,DIM><<<dim3(8,32,1),128,SMG>>>(x);
    ln_kernel<1><<<NTOK,256>>>(nullptr, ln2_g, ln2_b);
    router_kernel<<<NTOK,128>>>(w_rtr);
    base_kernel<<<1,32>>>();
    tgemm<2,HID,DIM><<<dim3(32,32,NEXP),128,SMG>>>(b1);
    tgemm<3,DIM,HID><<<dim3(8,32,NEXP),128,SMG>>>(b2);
    final_kernel<<<NTOK*DIM/256,256>>>(out);
}

// round 11
// speedup vs baseline: 1.8282x; 1.2809x over previous
#include <cuda_runtime.h>
#include <cuda_bf16.h>
#include <cuda_fp16.h>
#include <math.h>
#include <stdint.h>

#define BB 2
#define TT 2048
#define DIM 1024
#define NTOK 4096
#define NEXP 8
#define HID 4096
#define MAXTOK 4096
typedef __nv_bfloat16 bf16;
typedef __half h16;

// ---------- scratch ----------
__device__ bf16 g_h_hi[NTOK*DIM], g_h_lo[NTOK*DIM];
__device__ bf16 g_q_hi[32*2048*64], g_q_lo[32*2048*64];
__device__ bf16 g_k_hi[32*2048*64], g_k_lo[32*2048*64];
__device__ bf16 g_v_hi[32*2048*64], g_v_lo[32*2048*64];
__device__ bf16 g_y_hi[NTOK*DIM], g_y_lo[NTOK*DIM];
__device__ float g_x1[NTOK*DIM], g_h2f[NTOK*DIM];
__device__ h16  g_h2h_hi[NTOK*DIM], g_h2h_lo[NTOK*DIM];
__device__ h16  g_poolh_hi[(size_t)2*NTOK*HID], g_poolh_lo[(size_t)2*NTOK*HID];
__device__ float g_c0[NTOK*DIM], g_c1[NTOK*DIM];
__device__ int g_cnt[NEXP], g_basei[NEXP], g_tok[NEXP*MAXTOK], g_slot[NEXP*MAXTOK];
__device__ float g_wt[NEXP*MAXTOK];
__device__ bf16 g_waT_hi[(size_t)3*DIM*DIM], g_waT_lo[(size_t)3*DIM*DIM];
__device__ bf16 g_wpT_hi[(size_t)DIM*DIM],   g_wpT_lo[(size_t)DIM*DIM];
__device__ h16  g_w1T_h[(size_t)NEXP*HID*DIM];
__device__ h16  g_w2T_h[(size_t)NEXP*DIM*HID];

// ---------- ptx helpers ----------
__device__ __forceinline__ uint32_t s2u(const void* p){
    uint32_t a; asm("{ .reg .u64 t; cvta.to.shared.u64 t, %1; cvt.u32.u64 %0, t; }":"=r"(a):"l"(p)); return a;
}
__device__ __forceinline__ uint32_t swz(uint32_t o){ return o ^ ((o>>3)&0x70); }
__device__ __forceinline__ void cp16(uint32_t d, const void* s, bool v){
    asm volatile("cp.async.cg.shared.global [%0], [%1], 16, %2;"
        ::"r"(d),"l"(__cvta_generic_to_global(s)),"r"(v?16:0));
}
__device__ __forceinline__ void ldx4(uint32_t* r, uint32_t a){
    asm volatile("ldmatrix.sync.aligned.m8n8.x4.shared.b16 {%0,%1,%2,%3},[%4];"
        :"=r"(r[0]),"=r"(r[1]),"=r"(r[2]),"=r"(r[3]):"r"(a));
}
__device__ __forceinline__ void ldx4t(uint32_t* r, uint32_t a){
    asm volatile("ldmatrix.sync.aligned.m8n8.x4.trans.shared.b16 {%0,%1,%2,%3},[%4];"
        :"=r"(r[0]),"=r"(r[1]),"=r"(r[2]),"=r"(r[3]):"r"(a));
}
__device__ __forceinline__ void mma16816(float* d, const uint32_t* a, const uint32_t* b){
    asm volatile("mma.sync.aligned.m16n8k16.row.col.f32.bf16.bf16.f32 "
        "{%0,%1,%2,%3},{%4,%5,%6,%7},{%8,%9},{%0,%1,%2,%3};"
        : "+f"(d[0]),"+f"(d[1]),"+f"(d[2]),"+f"(d[3])
        : "r"(a[0]),"r"(a[1]),"r"(a[2]),"r"(a[3]),"r"(b[0]),"r"(b[1]));
}
__device__ __forceinline__ void mma16816h(float* d, const uint32_t* a, const uint32_t* b){
    asm volatile("mma.sync.aligned.m16n8k16.row.col.f32.f16.f16.f32 "
        "{%0,%1,%2,%3},{%4,%5,%6,%7},{%8,%9},{%0,%1,%2,%3};"
        : "+f"(d[0]),"+f"(d[1]),"+f"(d[2]),"+f"(d[3])
        : "r"(a[0]),"r"(a[1]),"r"(a[2]),"r"(a[3]),"r"(b[0]),"r"(b[1]));
}
__device__ __forceinline__ uint32_t packb(float f0, float f1){
    bf16 b0=__float2bfloat16(f0), b1=__float2bfloat16(f1);
    return (uint32_t)__bfloat16_as_ushort(b0) | ((uint32_t)__bfloat16_as_ushort(b1)<<16);
}
__device__ __forceinline__ uint32_t packh(float f0, float f1){
    __half2 p = __floats2half2_rn(f0, f1);
    return *(uint32_t*)&p;
}

// ---------- small kernels ----------
__global__ void zero_cnt_kernel(){ if(threadIdx.x<NEXP) g_cnt[threadIdx.x]=0; }
__global__ void base_kernel(){
    if(threadIdx.x==0){ int s=0; for(int e=0;e<NEXP;++e){ g_basei[e]=s; s+=g_cnt[e]; } }
}
__global__ void final_kernel(float* __restrict__ out){
    int i = blockIdx.x*256 + threadIdx.x;
    out[i] = g_x1[i] + g_c0[i] + g_c1[i];
}

// ---------- layernorm ----------
template<int WHICH>
__global__ void ln_kernel(const float* __restrict__ in, const float* __restrict__ gam,
                          const float* __restrict__ bet){
    __shared__ float sx[DIM]; __shared__ float red[8];
    const int n=blockIdx.x, tid=threadIdx.x;
    const float* row = (WHICH==0 ? in : g_x1) + (size_t)n*DIM;
    float4 x4 = ((const float4*)row)[tid];
    ((float4*)sx)[tid] = x4;
    float s = x4.x+x4.y+x4.z+x4.w;
    #pragma unroll
    for(int o=16;o;o>>=1) s += __shfl_xor_sync(~0u,s,o);
    if((tid&31)==0) red[tid>>5]=s;
    __syncthreads();
    float mu = (red[0]+red[1]+red[2]+red[3]+red[4]+red[5]+red[6]+red[7])*(1.f/DIM);
    float sq=0.f;
    #pragma unroll
    for(int p=0;p<4;++p){ float d=sx[tid+p*256]-mu; sq+=d*d; }
    #pragma unroll
    for(int o=16;o;o>>=1) sq += __shfl_xor_sync(~0u,sq,o);
    __syncthreads();
    if((tid&31)==0) red[tid>>5]=sq;
    __syncthreads();
    float var=(red[0]+red[1]+red[2]+red[3]+red[4]+red[5]+red[6]+red[7])*(1.f/DIM);
    float rs = rsqrtf(var+1e-5f);
    #pragma unroll
    for(int p=0;p<4;++p){
        int d=tid+p*256;
        float v = (sx[d]-mu)*rs*gam[d]+bet[d];
        size_t o=(size_t)n*DIM+d;
        if(WHICH==0){
            bf16 h = __float2bfloat16(v);
            g_h_hi[o]=h; g_h_lo[o]=__float2bfloat16(v - __bfloat162float(h));
        } else {
            g_h2f[o]=v;
            h16 h = __float2half_rn(v);
            g_h2h_hi[o]=h; g_h2h_lo[o]=__float2half_rn(v - __half2float(h));
        }
    }
}

// ---------- weight transpose + split to bf16 hi/lo (qkv, proj weights) ----------
template<int WHICH>   // 0: w_attn, 1: w_proj
__global__ void transpose_split(const float* __restrict__ src){
    constexpr int Kd = DIM;
    constexpr int Nd = (WHICH==0)?3*DIM:DIM;
    bf16 *dhi = (WHICH==0)? g_waT_hi : g_wpT_hi;
    bf16 *dlo = (WHICH==0)? g_waT_lo : g_wpT_lo;
    __shared__ float t[32][33];
    const int n0=blockIdx.x*32, k0=blockIdx.y*32;
    const int tx=threadIdx.x, ty=threadIdx.y;
    for(int i=ty;i<32;i+=8)
        t[i][tx] = src[(size_t)(k0+i)*Nd + n0 + tx];
    __syncthreads();
    const int tid = ty*32+tx;
    const int wq = tid&7, nn = tid>>3;
    float v0=t[wq*4+0][nn], v1=t[wq*4+1][nn], v2=t[wq*4+2][nn], v3=t[wq*4+3][nn];
    bf16 h0=__float2bfloat16(v0), h1=__float2bfloat16(v1);
    bf16 h2=__float2bfloat16(v2), h3=__float2bfloat16(v3);
    size_t o = (size_t)(n0+nn)*Kd + k0 + wq*4;
    uint2 hv, lv;
    hv.x = (uint32_t)__bfloat16_as_ushort(h0) | ((uint32_t)__bfloat16_as_ushort(h1)<<16);
    hv.y = (uint32_t)__bfloat16_as_ushort(h2) | ((uint32_t)__bfloat16_as_ushort(h3)<<16);
    lv.x = packb(v0-__bfloat162float(h0), v1-__bfloat162float(h1));
    lv.y = packb(v2-__bfloat162float(h2), v3-__bfloat162float(h3));
    *(uint2*)&dhi[o] = hv;
    *(uint2*)&dlo[o] = lv;
}

// ---------- weight transpose to single fp16 (moe weights) ----------
template<int WHICH>   // 2: w1, 3: w2
__global__ void transpose_h(const float* __restrict__ src){
    constexpr int Kd = (WHICH==3)?HID:DIM;
    constexpr int Nd = (WHICH==2)?HID:DIM;
    h16* dst = (WHICH==2)? g_w1T_h : g_w2T_h;
    const int e=blockIdx.z;
    src += (size_t)e*Kd*Nd; dst += (size_t)e*(size_t)Nd*Kd;
    __shared__ float t[32][33];
    const int n0=blockIdx.x*32, k0=blockIdx.y*32;
    const int tx=threadIdx.x, ty=threadIdx.y;
    for(int i=ty;i<32;i+=8)
        t[i][tx] = src[(size_t)(k0+i)*Nd + n0 + tx];
    __syncthreads();
    const int tid = ty*32+tx;
    const int wq = tid&7, nn = tid>>3;
    uint2 w;
    w.x = packh(t[wq*4+0][nn], t[wq*4+1][nn]);
    w.y = packh(t[wq*4+2][nn], t[wq*4+3][nn]);
    *(uint2*)&dst[(size_t)(n0+nn)*Kd + k0 + wq*4] = w;
}

// ---------- bf16 3-pass GEMM (R7-proven): block 128x256, warp 64x64, K64, 2-stage ----------
// MODE 0: qkv (planar out), MODE 1: proj (+x residual)
template<int MODE, int N, int K>
__global__ void __launch_bounds__(256,1) tgemm(const float* __restrict__ aux){
    constexpr int NKT = K/64;
    constexpr int STG = 98304;
    extern __shared__ char smem[];
    const uint32_t sb = s2u(smem);
    const int tid = threadIdx.x, lane = tid&31, wid = tid>>5;
    const int wm = wid>>2, wn = wid&3;
    const int m0 = blockIdx.y*128, n0 = blockIdx.x*256;

    const bf16 *Ahi,*Alo,*Bhi,*Blo;
    if(MODE==0){ Ahi=g_h_hi; Alo=g_h_lo; Bhi=g_waT_hi; Blo=g_waT_lo; }
    else       { Ahi=g_y_hi; Alo=g_y_lo; Bhi=g_wpT_hi; Blo=g_wpT_lo; }

    const uint32_t d0 = swz((uint32_t)((tid>>3)*128 + (tid&7)*16));
    const bf16 *pah[4], *pal[4];
    #pragma unroll
    for(int i=0;i<4;++i){
        int r = (tid>>3) + i*32;
        pah[i]=Ahi+(size_t)(m0+r)*K+(tid&7)*8; pal[i]=Alo+(size_t)(m0+r)*K+(tid&7)*8;
    }
    const bf16 *pb_h = Bhi + (size_t)(n0 + (tid>>3))*K + (tid&7)*8;
    const bf16 *pb_l = Blo + (size_t)(n0 + (tid>>3))*K + (tid&7)*8;

    float acc[4][8][4];
    #pragma unroll
    for(int a=0;a<4;++a)
        #pragma unroll
        for(int b=0;b<8;++b)
            #pragma unroll
            for(int c=0;c<4;++c) acc[a][b][c]=0.f;

    const int arow = wm*64 + (lane&15), achk = lane>>4;
    const int brow_b = wn*64 + ((lane>>4)&1)*8 + (lane&7), bchk = (lane>>3)&1;

    auto issue = [&](int kt){
        const uint32_t st = sb + (kt&1)*STG;
        const int ko = kt*64;
        #pragma unroll
        for(int i=0;i<4;++i){
            cp16(st+d0+i*4096,        pah[i]+ko, true);
            cp16(st+16384+d0+i*4096,  pal[i]+ko, true);
        }
        #pragma unroll
        for(int i=0;i<8;++i){
            cp16(st+32768+d0+i*4096,  pb_h + (size_t)i*32*K + ko, true);
            cp16(st+65536+d0+i*4096,  pb_l + (size_t)i*32*K + ko, true);
        }
        asm volatile("cp.async.commit_group;":::"memory");
    };

    issue(0);
    for(int kt=0; kt<NKT; ++kt){
        if(kt+1<NKT){ issue(kt+1); asm volatile("cp.async.wait_group 1;":::"memory"); }
        else        { asm volatile("cp.async.wait_group 0;":::"memory"); }
        __syncthreads();
        const uint32_t st = sb + (kt&1)*STG;
        #pragma unroll
        for(int k16=0;k16<4;++k16){
            uint32_t ah[4][4], al[4][4];
            #pragma unroll
            for(int mi=0;mi<4;++mi){
                uint32_t off = swz((uint32_t)((arow+mi*16)*128 + k16*32 + achk*16));
                ldx4(ah[mi], st + off);
                ldx4(al[mi], st + 16384 + off);
            }
            #pragma unroll
            for(int n16=0;n16<4;++n16){
                uint32_t off = swz((uint32_t)((brow_b+n16*16)*128 + k16*32 + bchk*16));
                uint32_t rh[4], rl[4];
                ldx4(rh, st + 32768 + off);
                ldx4(rl, st + 65536 + off);
                #pragma unroll
                for(int mi=0;mi<4;++mi){
                    mma16816(acc[mi][n16*2],   ah[mi], rh);
                    mma16816(acc[mi][n16*2],   ah[mi], rl);
                    mma16816(acc[mi][n16*2],   al[mi], rh);
                    mma16816(acc[mi][n16*2+1], ah[mi], rh+2);
                    mma16816(acc[mi][n16*2+1], ah[mi], rl+2);
                    mma16816(acc[mi][n16*2+1], al[mi], rh+2);
                }
            }
        }
        __syncthreads();
    }

    const int r0 = lane>>2, c2 = (lane&3)*2;
    #pragma unroll
    for(int mi=0;mi<4;++mi){
        #pragma unroll
        for(int half=0; half<2; ++half){
            const int m = m0 + wm*64 + mi*16 + r0 + half*8;
            #pragma unroll
            for(int ni=0;ni<8;++ni){
                const int col = n0 + wn*64 + ni*8 + c2;
                float dd0 = acc[mi][ni][half*2], dd1 = acc[mi][ni][half*2+1];
                if(MODE==0){
                    const int which = col>>10, r = col&1023, h = r>>6, d = r&63;
                    const int b = m>>11, t = m&2047;
                    size_t o = ((size_t)(b*16+h)*2048 + t)*64 + d;
                    bf16 *ph, *pl;
                    if(which==0){ dd0*=0.125f; dd1*=0.125f; ph=g_q_hi; pl=g_q_lo; }
                    else if(which==1){ ph=g_k_hi; pl=g_k_lo; }
                    else { ph=g_v_hi; pl=g_v_lo; }
                    bf16 h0=__float2bfloat16(dd0), h1=__float2bfloat16(dd1);
                    *(uint32_t*)&ph[o] = (uint32_t)__bfloat16_as_ushort(h0)
                                       | ((uint32_t)__bfloat16_as_ushort(h1)<<16);
                    *(uint32_t*)&pl[o] = packb(dd0-__bfloat162float(h0), dd1-__bfloat162float(h1));
                } else {
                    const float* rx=aux+(size_t)m*N+col;
                    float2 w; w.x = rx[0]+dd0; w.y = rx[1]+dd1;
                    *(float2*)&g_x1[(size_t)m*N+col] = w;
                }
            }
        }
    }
}

// ---------- fp16 2-term MoE GEMM: block 128x256, warp 64x64, K64, 3 stages x 64KB ----------
// D = Ahi*B + Alo*B  (A = activations split fp16 hi/lo, B = weights single fp16)
// stage layout: A-hi [0,16K), A-lo [16K,32K), B [32K,64K). single sync per iter.
// MODE 2: moe-up (gather h2, gelu -> pool hi/lo). MODE 3: moe-dn (pool, scatter).
template<int MODE, int N, int K>
__global__ void __launch_bounds__(256,1) hgemm(const float* __restrict__ aux){
    constexpr int NKT = K/64;
    constexpr int STG = 65536;
    const int e = blockIdx.z;
    const int Mrows = g_cnt[e], pbase = g_basei[e];
    if((int)blockIdx.y*128 >= Mrows) return;
    extern __shared__ char smem[];
    const uint32_t sb = s2u(smem);
    const int tid = threadIdx.x, lane = tid&31, wid = tid>>5;
    const int wm = wid>>2, wn = wid&3;
    const int m0 = blockIdx.y*128, n0 = blockIdx.x*256;

    const h16 *Ahi, *Alo, *B;
    if(MODE==2){ Ahi=g_h2h_hi; Alo=g_h2h_lo; B=g_w1T_h+(size_t)e*HID*DIM; }
    else       { Ahi=g_poolh_hi; Alo=g_poolh_lo; B=g_w2T_h+(size_t)e*DIM*HID; }

    const uint32_t d0 = swz((uint32_t)((tid>>3)*128 + (tid&7)*16));
    const h16 *pah[4], *pal[4]; bool av[4];
    #pragma unroll
    for(int i=0;i<4;++i){
        int r = (tid>>3) + i*32, gm = m0 + r;
        bool v = gm < Mrows;
        long rg;
        if(MODE==2) rg = v ? g_tok[e*MAXTOK+gm] : 0;
        else        rg = (long)pbase + (v?gm:0);
        pah[i]=Ahi+(size_t)rg*K+(tid&7)*8; pal[i]=Alo+(size_t)rg*K+(tid&7)*8; av[i]=v;
    }
    const h16 *pb = B + (size_t)(n0 + (tid>>3))*K + (tid&7)*8;

    float acc[4][8][4];
    #pragma unroll
    for(int a=0;a<4;++a)
        #pragma unroll
        for(int b=0;b<8;++b)
            #pragma unroll
            for(int c=0;c<4;++c) acc[a][b][c]=0.f;

    const int arow = wm*64 + (lane&15), achk = lane>>4;
    const int brow_b = wn*64 + ((lane>>4)&1)*8 + (lane&7), bchk = (lane>>3)&1;

    auto issue = [&](int kt){
        const uint32_t st = sb + (kt%3)*STG;
        const int ko = kt*64;
        #pragma unroll
        for(int i=0;i<4;++i){
            cp16(st+d0+i*4096,        pah[i]+ko, av[i]);
            cp16(st+16384+d0+i*4096,  pal[i]+ko, av[i]);
        }
        #pragma unroll
        for(int i=0;i<8;++i)
            cp16(st+32768+d0+i*4096,  pb + (size_t)i*32*K + ko, true);
        asm volatile("cp.async.commit_group;":::"memory");
    };

    issue(0); issue(1);
    for(int kt=0; kt<NKT; ++kt){
        if(kt+1<NKT){ asm volatile("cp.async.wait_group 1;":::"memory"); }
        else        { asm volatile("cp.async.wait_group 0;":::"memory"); }
        __syncthreads();
        if(kt+2<NKT) issue(kt+2);   // writes stage (kt-1)%3: reads finished before this sync
        const uint32_t st = sb + (kt%3)*STG;
        #pragma unroll
        for(int k16=0;k16<4;++k16){
            uint32_t ah[4][4], al[4][4];
            #pragma unroll
            for(int mi=0;mi<4;++mi){
                uint32_t off = swz((uint32_t)((arow+mi*16)*128 + k16*32 + achk*16));
                ldx4(ah[mi], st + off);
                ldx4(al[mi], st + 16384 + off);
            }
            #pragma unroll
            for(int n16=0;n16<4;++n16){
                uint32_t off = swz((uint32_t)((brow_b+n16*16)*128 + k16*32 + bchk*16));
                uint32_t rb[4];
                ldx4(rb, st + 32768 + off);
                #pragma unroll
                for(int mi=0;mi<4;++mi){
                    mma16816h(acc[mi][n16*2],   ah[mi], rb);
                    mma16816h(acc[mi][n16*2],   al[mi], rb);
                    mma16816h(acc[mi][n16*2+1], ah[mi], rb+2);
                    mma16816h(acc[mi][n16*2+1], al[mi], rb+2);
                }
            }
        }
    }

    const int r0 = lane>>2, c2 = (lane&3)*2;
    const float* bias = aux + (size_t)e*N;
    #pragma unroll
    for(int mi=0;mi<4;++mi){
        #pragma unroll
        for(int half=0; half<2; ++half){
            const int m = m0 + wm*64 + mi*16 + r0 + half*8;
            if(m>=Mrows) continue;
            int tok=0, slot=0; float wgt=0.f;
            if(MODE==3){ int ix=e*MAXTOK+m; tok=g_tok[ix]; wgt=g_wt[ix]; slot=g_slot[ix]; }
            #pragma unroll
            for(int ni=0;ni<8;++ni){
                const int col = n0 + wn*64 + ni*8 + c2;
                float dd0 = acc[mi][ni][half*2], dd1 = acc[mi][ni][half*2+1];
                if(MODE==2){
                    size_t prow=(size_t)(pbase+m);
                    float v0=dd0+bias[col], v1=dd1+bias[col+1];
                    float gg0=0.5f*v0*(1.f+erff(v0*0.70710678f));
                    float gg1=0.5f*v1*(1.f+erff(v1*0.70710678f));
                    h16 h0=__float2half_rn(gg0), h1=__float2half_rn(gg1);
                    *(uint32_t*)&g_poolh_hi[prow*HID+col] = packh(gg0, gg1);
                    *(uint32_t*)&g_poolh_lo[prow*HID+col] =
                        packh(gg0-__half2float(h0), gg1-__half2float(h1));
                } else {
                    float2 w; w.x = wgt*(dd0+bias[col]); w.y = wgt*(dd1+bias[col+1]);
                    *(float2*)&((slot?g_c1:g_c0)[(size_t)tok*DIM+col]) = w;
                }
            }
        }
    }
}

// ---------- tensor-core flash attention (R7-proven, unchanged) ----------
__global__ void __launch_bounds__(256,1) attn_mma(){
    extern __shared__ char smem[];
    const uint32_t sb = s2u(smem);
    const int tid=threadIdx.x, lane=tid&31, wid=tid>>5;
    const int bh = blockIdx.y;
    const int qt = (gridDim.x-1) - blockIdx.x;
    const int q0 = qt*128;
    const size_t pbase = (size_t)bh*2048*64;

    #pragma unroll
    for(int i=0;i<4;++i){
        int idx=tid+i*256, r=idx>>3, c=idx&7;
        uint32_t off = swz((uint32_t)(r*128+c*16));
        cp16(sb+off,        g_q_hi + pbase + (size_t)(q0+r)*64 + c*8, true);
        cp16(sb+16384+off,  g_q_lo + pbase + (size_t)(q0+r)*64 + c*8, true);
    }
    auto issueKV = [&](int kb){
        const uint32_t st = sb + 32768 + (kb%3)*32768;
        #pragma unroll
        for(int i=0;i<2;++i){
            int idx=tid+i*256, r=idx>>3, c=idx&7;
            uint32_t off = swz((uint32_t)(r*128+c*16));
            size_t src = pbase + (size_t)(kb*64+r)*64 + c*8;
            cp16(st+off,        g_k_hi+src, true);
            cp16(st+8192+off,   g_k_lo+src, true);
            cp16(st+16384+off,  g_v_hi+src, true);
            cp16(st+24576+off,  g_v_lo+src, true);
        }
        asm volatile("cp.async.commit_group;":::"memory");
    };
    const int kbmax = 2*qt+1;
    issueKV(0);
    issueKV(1);

    asm volatile("cp.async.wait_group 1;":::"memory");
    __syncthreads();
    uint32_t qh[4][4], ql[4][4];
    {
        const int qrow = wid*16 + (lane&15), qchk = lane>>4;
        #pragma unroll
        for(int k16=0;k16<4;++k16){
            uint32_t off = swz((uint32_t)(qrow*128 + k16*32 + qchk*16));
            ldx4(qh[k16], sb+off);
            ldx4(ql[k16], sb+16384+off);
        }
    }

    float O[8][4], mstat[2], lstat[2];
    #pragma unroll
    for(int t=0;t<8;++t){ O[t][0]=0;O[t][1]=0;O[t][2]=0;O[t][3]=0; }
    mstat[0]=mstat[1]=-1e30f; lstat[0]=lstat[1]=0.f;

    const int rloc = lane>>2, cloc = (lane&3)*2;
    const int brow_b = ((lane>>4)&1)*8 + (lane&7), bchk = (lane>>3)&1;
    const int vrow_b = ((lane>>3)&1)*8 + (lane&7), vcol_b = ((lane>>4)&1)*8;

    for(int kb=0; kb<=kbmax; ++kb){
        if(kb<kbmax){ asm volatile("cp.async.wait_group 1;":::"memory"); }
        else        { asm volatile("cp.async.wait_group 0;":::"memory"); }
        __syncthreads();
        if(kb+2<=kbmax) issueKV(kb+2);
        const uint32_t st = sb + 32768 + (kb%3)*32768;

        float s[8][4];
        #pragma unroll
        for(int t=0;t<8;++t){ s[t][0]=0;s[t][1]=0;s[t][2]=0;s[t][3]=0; }
        #pragma unroll
        for(int k16=0;k16<4;++k16){
            uint32_t bkh[8][2], bkl[8][2];
            #pragma unroll
            for(int n16=0;n16<4;++n16){
                uint32_t off = swz((uint32_t)((n16*16+brow_b)*128 + k16*32 + bchk*16));
                uint32_t r[4];
                ldx4(r, st+off);
                bkh[n16*2][0]=r[0]; bkh[n16*2][1]=r[1]; bkh[n16*2+1][0]=r[2]; bkh[n16*2+1][1]=r[3];
                ldx4(r, st+8192+off);
                bkl[n16*2][0]=r[0]; bkl[n16*2][1]=r[1]; bkl[n16*2+1][0]=r[2]; bkl[n16*2+1][1]=r[3];
            }
            #pragma unroll
            for(int t=0;t<8;++t){
                mma16816(s[t], qh[k16], bkh[t]);
                mma16816(s[t], qh[k16], bkl[t]);
                mma16816(s[t], ql[k16], bkh[t]);
            }
        }
        if(kb >= 2*qt){
            const int row0 = q0 + wid*16 + rloc;
            #pragma unroll
            for(int t=0;t<8;++t){
                int c0 = kb*64 + t*8 + cloc;
                if(c0   > row0  ) s[t][0]=-1e30f;
                if(c0+1 > row0  ) s[t][1]=-1e30f;
                if(c0   > row0+8) s[t][2]=-1e30f;
                if(c0+1 > row0+8) s[t][3]=-1e30f;
            }
        }
        float corr[2];
        #pragma unroll
        for(int rh=0; rh<2; ++rh){
            float mt=-1e30f;
            #pragma unroll
            for(int t=0;t<8;++t) mt = fmaxf(mt, fmaxf(s[t][rh*2], s[t][rh*2+1]));
            mt = fmaxf(mt, __shfl_xor_sync(~0u, mt, 1, 4));
            mt = fmaxf(mt, __shfl_xor_sync(~0u, mt, 2, 4));
            float mn = fmaxf(mstat[rh], mt);
            corr[rh] = __expf(mstat[rh]-mn); mstat[rh]=mn;
            float rs=0.f;
            #pragma unroll
            for(int t=0;t<8;++t){
                float p0=__expf(s[t][rh*2]-mn), p1=__expf(s[t][rh*2+1]-mn);
                s[t][rh*2]=p0; s[t][rh*2+1]=p1; rs += p0+p1;
            }
            rs += __shfl_xor_sync(~0u, rs, 1, 4);
            rs += __shfl_xor_sync(~0u, rs, 2, 4);
            lstat[rh] = lstat[rh]*corr[rh] + rs;
        }
        #pragma unroll
        for(int t=0;t<8;++t){
            O[t][0]*=corr[0]; O[t][1]*=corr[0]; O[t][2]*=corr[1]; O[t][3]*=corr[1];
        }
        uint32_t ph[4][4], pl[4][4];
        #pragma unroll
        for(int k16=0;k16<4;++k16){
            #pragma unroll
            for(int half=0; half<2; ++half){
                const int t = 2*k16+half;
                float f0=s[t][0], f1=s[t][1], f2=s[t][2], f3=s[t][3];
                ph[k16][half*2]   = packb(f0,f1);
                ph[k16][half*2+1] = packb(f2,f3);
                bf16 h0=__float2bfloat16(f0), h1=__float2bfloat16(f1);
                bf16 h2=__float2bfloat16(f2), h3=__float2bfloat16(f3);
                pl[k16][half*2]   = packb(f0-__bfloat162float(h0), f1-__bfloat162float(h1));
                pl[k16][half*2+1] = packb(f2-__bfloat162float(h2), f3-__bfloat162float(h3));
            }
        }
        #pragma unroll
        for(int k16=0;k16<4;++k16){
            uint32_t bvh[8][2], bvl[8][2];
            #pragma unroll
            for(int d16=0;d16<4;++d16){
                uint32_t off = swz((uint32_t)((k16*16+vrow_b)*128 + (d16*16+vcol_b)*2));
                uint32_t r[4];
                ldx4t(r, st+16384+off);
                bvh[d16*2][0]=r[0]; bvh[d16*2][1]=r[1]; bvh[d16*2+1][0]=r[2]; bvh[d16*2+1][1]=r[3];
                ldx4t(r, st+24576+off);
                bvl[d16*2][0]=r[0]; bvl[d16*2][1]=r[1]; bvl[d16*2+1][0]=r[2]; bvl[d16*2+1][1]=r[3];
            }
            #pragma unroll
            for(int t=0;t<8;++t){
                mma16816(O[t], ph[k16], bvh[t]);
                mma16816(O[t], ph[k16], bvl[t]);
                mma16816(O[t], pl[k16], bvh[t]);
            }
        }
        __syncthreads();
    }

    const int b = bh>>4, h = bh&15;
    #pragma unroll
    for(int rh=0; rh<2; ++rh){
        const float inv = 1.f/lstat[rh];
        const int row = q0 + wid*16 + rloc + rh*8;
        size_t base = (size_t)(b*TT+row)*DIM + h*64;
        #pragma unroll
        for(int t=0;t<8;++t){
            float v0 = O[t][rh*2]*inv, v1 = O[t][rh*2+1]*inv;
            size_t o = base + t*8 + cloc;
            bf16 h0=__float2bfloat16(v0), h1=__float2bfloat16(v1);
            g_y_hi[o]=h0; g_y_hi[o+1]=h1;
            g_y_lo[o]=__float2bfloat16(v0-__bfloat162float(h0));
            g_y_lo[o+1]=__float2bfloat16(v1-__bfloat162float(h1));
        }
    }
}

// ---------- router ----------
__global__ void router_kernel(const float* __restrict__ wr){
    const int n=blockIdx.x, tid=threadIdx.x;
    float acc[NEXP];
    #pragma unroll
    for(int e=0;e<NEXP;++e) acc[e]=0.f;
    const float* row=g_h2f+(size_t)n*DIM;
    for(int d=tid;d<DIM;d+=128){
        float hv=row[d];
        #pragma unroll
        for(int e=0;e<NEXP;++e) acc[e]+=hv*wr[d*NEXP+e];
    }
    __shared__ float sm[4][NEXP];
    #pragma unroll
    for(int e=0;e<NEXP;++e){
        float v=acc[e];
        #pragma unroll
        for(int o=16;o;o>>=1) v+=__shfl_xor_sync(~0u,v,o);
        if((tid&31)==0) sm[tid>>5][e]=v;
    }
    __syncthreads();
    if(tid==0){
        float lg[NEXP];
        #pragma unroll
        for(int e=0;e<NEXP;++e) lg[e]=sm[0][e]+sm[1][e]+sm[2][e]+sm[3][e];
        int e0=0;
        #pragma unroll
        for(int e=1;e<NEXP;++e) if(lg[e]>lg[e0]) e0=e;
        int e1=-1;
        #pragma unroll
        for(int e=0;e<NEXP;++e) if(e!=e0 && (e1<0||lg[e]>lg[e1])) e1=e;
        float w0=1.f/(1.f+__expf(lg[e1]-lg[e0])), w1=1.f-w0;
        int p0=atomicAdd(&g_cnt[e0],1);
        g_tok[e0*MAXTOK+p0]=n; g_wt[e0*MAXTOK+p0]=w0; g_slot[e0*MAXTOK+p0]=0;
        int p1=atomicAdd(&g_cnt[e1],1);
        g_tok[e1*MAXTOK+p1]=n; g_wt[e1*MAXTOK+p1]=w1; g_slot[e1*MAXTOK+p1]=1;
    }
}

// ---------- launch (R7-proven order) ----------
extern "C" void kernel_launch(void* const* d_in, const int* in_sizes, int n_in,
                              void* d_out, int out_size){
    const float* x      =(const float*)d_in[0];
    const float* ln1_g  =(const float*)d_in[1];
    const float* ln1_b  =(const float*)d_in[2];
    const float* w_attn =(const float*)d_in[3];
    const float* w_proj =(const float*)d_in[4];
    const float* ln2_g  =(const float*)d_in[5];
    const float* ln2_b  =(const float*)d_in[6];
    const float* w_rtr  =(const float*)d_in[7];
    const float* w1     =(const float*)d_in[8];
    const float* b1     =(const float*)d_in[9];
    const float* w2     =(const float*)d_in[10];
    const float* b2     =(const float*)d_in[11];
    float* out=(float*)d_out;

    const int SMG = 196608;
    cudaFuncSetAttribute(tgemm<0,3*DIM,DIM>, cudaFuncAttributeMaxDynamicSharedMemorySize, SMG);
    cudaFuncSetAttribute(tgemm<1,DIM,DIM>,   cudaFuncAttributeMaxDynamicSharedMemorySize, SMG);
    cudaFuncSetAttribute(hgemm<2,HID,DIM>,   cudaFuncAttributeMaxDynamicSharedMemorySize, SMG);
    cudaFuncSetAttribute(hgemm<3,DIM,HID>,   cudaFuncAttributeMaxDynamicSharedMemorySize, SMG);
    const int SMA = 131072;
    cudaFuncSetAttribute(attn_mma, cudaFuncAttributeMaxDynamicSharedMemorySize, SMA);

    zero_cnt_kernel<<<1,32>>>();
    transpose_split<0><<<dim3(96,32,1), dim3(32,8)>>>(w_attn);
    transpose_split<1><<<dim3(32,32,1), dim3(32,8)>>>(w_proj);
    transpose_h<2><<<dim3(128,32,NEXP), dim3(32,8)>>>(w1);
    transpose_h<3><<<dim3(32,128,NEXP), dim3(32,8)>>>(w2);

    ln_kernel<0><<<NTOK,256>>>(x, ln1_g, ln1_b);
    tgemm<0,3*DIM,DIM><<<dim3(12,32,1),256,SMG>>>(nullptr);
    attn_mma<<<dim3(TT/128, BB*16),256,SMA>>>();
    tgemm<1,DIM,DIM><<<dim3(4,32,1),256,SMG>>>(x);
    ln_kernel<1><<<NTOK,256>>>(nullptr, ln2_g, ln2_b);
    router_kernel<<<NTOK,128>>>(w_rtr);
    base_kernel<<<1,32>>>();
    hgemm<2,HID,DIM><<<dim3(16,32,NEXP),256,SMG>>>(b1);
    hgemm<3,DIM,HID><<<dim3(4,32,NEXP),256,SMG>>>(b2);
    final_kernel<<<NTOK*DIM/256,256>>>(out);
}

// round 12
// speedup vs baseline: 2.2824x; 1.2484x over previous
#include <cuda_runtime.h>
#include <cuda_bf16.h>
#include <cuda_fp16.h>
#include <math.h>
#include <stdint.h>

#define BB 2
#define TT 2048
#define DIM 1024
#define NTOK 4096
#define NEXP 8
#define HID 4096
#define MAXTOK 4096
typedef __nv_bfloat16 bf16;
typedef __half h16;

// ---------- scratch ----------
__device__ bf16 g_h_hi[NTOK*DIM], g_h_lo[NTOK*DIM];
__device__ bf16 g_q_hi[32*2048*64], g_q_lo[32*2048*64];
__device__ bf16 g_k_hi[32*2048*64], g_k_lo[32*2048*64];
__device__ bf16 g_v_hi[32*2048*64], g_v_lo[32*2048*64];
__device__ bf16 g_y_hi[NTOK*DIM], g_y_lo[NTOK*DIM];
__device__ float g_x1[NTOK*DIM], g_h2f[NTOK*DIM];
__device__ h16  g_h2h[NTOK*DIM];
__device__ h16  g_poolh[(size_t)2*NTOK*HID];
__device__ float g_c0[NTOK*DIM], g_c1[NTOK*DIM];
__device__ int g_cnt[NEXP], g_basei[NEXP], g_tok[NEXP*MAXTOK], g_slot[NEXP*MAXTOK];
__device__ float g_wt[NEXP*MAXTOK];
__device__ bf16 g_waT_hi[(size_t)3*DIM*DIM], g_waT_lo[(size_t)3*DIM*DIM];
__device__ bf16 g_wpT_hi[(size_t)DIM*DIM],   g_wpT_lo[(size_t)DIM*DIM];
__device__ h16  g_w1T_h[(size_t)NEXP*HID*DIM];
__device__ h16  g_w2T_h[(size_t)NEXP*DIM*HID];

// ---------- ptx helpers ----------
__device__ __forceinline__ uint32_t s2u(const void* p){
    uint32_t a; asm("{ .reg .u64 t; cvta.to.shared.u64 t, %1; cvt.u32.u64 %0, t; }":"=r"(a):"l"(p)); return a;
}
__device__ __forceinline__ uint32_t swz(uint32_t o){ return o ^ ((o>>3)&0x70); }
__device__ __forceinline__ void cp16(uint32_t d, const void* s, bool v){
    asm volatile("cp.async.cg.shared.global [%0], [%1], 16, %2;"
        ::"r"(d),"l"(__cvta_generic_to_global(s)),"r"(v?16:0));
}
__device__ __forceinline__ void ldx4(uint32_t* r, uint32_t a){
    asm volatile("ldmatrix.sync.aligned.m8n8.x4.shared.b16 {%0,%1,%2,%3},[%4];"
        :"=r"(r[0]),"=r"(r[1]),"=r"(r[2]),"=r"(r[3]):"r"(a));
}
__device__ __forceinline__ void ldx4t(uint32_t* r, uint32_t a){
    asm volatile("ldmatrix.sync.aligned.m8n8.x4.trans.shared.b16 {%0,%1,%2,%3},[%4];"
        :"=r"(r[0]),"=r"(r[1]),"=r"(r[2]),"=r"(r[3]):"r"(a));
}
__device__ __forceinline__ void mma16816(float* d, const uint32_t* a, const uint32_t* b){
    asm volatile("mma.sync.aligned.m16n8k16.row.col.f32.bf16.bf16.f32 "
        "{%0,%1,%2,%3},{%4,%5,%6,%7},{%8,%9},{%0,%1,%2,%3};"
        : "+f"(d[0]),"+f"(d[1]),"+f"(d[2]),"+f"(d[3])
        : "r"(a[0]),"r"(a[1]),"r"(a[2]),"r"(a[3]),"r"(b[0]),"r"(b[1]));
}
__device__ __forceinline__ void mma16816h(float* d, const uint32_t* a, const uint32_t* b){
    asm volatile("mma.sync.aligned.m16n8k16.row.col.f32.f16.f16.f32 "
        "{%0,%1,%2,%3},{%4,%5,%6,%7},{%8,%9},{%0,%1,%2,%3};"
        : "+f"(d[0]),"+f"(d[1]),"+f"(d[2]),"+f"(d[3])
        : "r"(a[0]),"r"(a[1]),"r"(a[2]),"r"(a[3]),"r"(b[0]),"r"(b[1]));
}
__device__ __forceinline__ uint32_t packb(float f0, float f1){
    bf16 b0=__float2bfloat16(f0), b1=__float2bfloat16(f1);
    return (uint32_t)__bfloat16_as_ushort(b0) | ((uint32_t)__bfloat16_as_ushort(b1)<<16);
}
__device__ __forceinline__ uint32_t packh(float f0, float f1){
    __half2 p = __floats2half2_rn(f0, f1);
    return *(uint32_t*)&p;
}

// ---------- small kernels ----------
__global__ void zero_cnt_kernel(){ if(threadIdx.x<NEXP) g_cnt[threadIdx.x]=0; }
__global__ void base_kernel(){
    if(threadIdx.x==0){ int s=0; for(int e=0;e<NEXP;++e){ g_basei[e]=s; s+=g_cnt[e]; } }
}
__global__ void final_kernel(float* __restrict__ out){
    int i = blockIdx.x*256 + threadIdx.x;
    out[i] = g_x1[i] + g_c0[i] + g_c1[i];
}

// ---------- layernorm ----------
template<int WHICH>
__global__ void ln_kernel(const float* __restrict__ in, const float* __restrict__ gam,
                          const float* __restrict__ bet){
    __shared__ float sx[DIM]; __shared__ float red[8];
    const int n=blockIdx.x, tid=threadIdx.x;
    const float* row = (WHICH==0 ? in : g_x1) + (size_t)n*DIM;
    float4 x4 = ((const float4*)row)[tid];
    ((float4*)sx)[tid] = x4;
    float s = x4.x+x4.y+x4.z+x4.w;
    #pragma unroll
    for(int o=16;o;o>>=1) s += __shfl_xor_sync(~0u,s,o);
    if((tid&31)==0) red[tid>>5]=s;
    __syncthreads();
    float mu = (red[0]+red[1]+red[2]+red[3]+red[4]+red[5]+red[6]+red[7])*(1.f/DIM);
    float sq=0.f;
    #pragma unroll
    for(int p=0;p<4;++p){ float d=sx[tid+p*256]-mu; sq+=d*d; }
    #pragma unroll
    for(int o=16;o;o>>=1) sq += __shfl_xor_sync(~0u,sq,o);
    __syncthreads();
    if((tid&31)==0) red[tid>>5]=sq;
    __syncthreads();
    float var=(red[0]+red[1]+red[2]+red[3]+red[4]+red[5]+red[6]+red[7])*(1.f/DIM);
    float rs = rsqrtf(var+1e-5f);
    #pragma unroll
    for(int p=0;p<4;++p){
        int d=tid+p*256;
        float v = (sx[d]-mu)*rs*gam[d]+bet[d];
        size_t o=(size_t)n*DIM+d;
        if(WHICH==0){
            bf16 h = __float2bfloat16(v);
            g_h_hi[o]=h; g_h_lo[o]=__float2bfloat16(v - __bfloat162float(h));
        } else {
            g_h2f[o]=v;
            g_h2h[o]=__float2half_rn(v);
        }
    }
}

// ---------- weight transpose + split to bf16 hi/lo (qkv, proj weights) ----------
template<int WHICH>   // 0: w_attn, 1: w_proj
__global__ void transpose_split(const float* __restrict__ src){
    constexpr int Kd = DIM;
    constexpr int Nd = (WHICH==0)?3*DIM:DIM;
    bf16 *dhi = (WHICH==0)? g_waT_hi : g_wpT_hi;
    bf16 *dlo = (WHICH==0)? g_waT_lo : g_wpT_lo;
    __shared__ float t[32][33];
    const int n0=blockIdx.x*32, k0=blockIdx.y*32;
    const int tx=threadIdx.x, ty=threadIdx.y;
    for(int i=ty;i<32;i+=8)
        t[i][tx] = src[(size_t)(k0+i)*Nd + n0 + tx];
    __syncthreads();
    const int tid = ty*32+tx;
    const int wq = tid&7, nn = tid>>3;
    float v0=t[wq*4+0][nn], v1=t[wq*4+1][nn], v2=t[wq*4+2][nn], v3=t[wq*4+3][nn];
    bf16 h0=__float2bfloat16(v0), h1=__float2bfloat16(v1);
    bf16 h2=__float2bfloat16(v2), h3=__float2bfloat16(v3);
    size_t o = (size_t)(n0+nn)*Kd + k0 + wq*4;
    uint2 hv, lv;
    hv.x = (uint32_t)__bfloat16_as_ushort(h0) | ((uint32_t)__bfloat16_as_ushort(h1)<<16);
    hv.y = (uint32_t)__bfloat16_as_ushort(h2) | ((uint32_t)__bfloat16_as_ushort(h3)<<16);
    lv.x = packb(v0-__bfloat162float(h0), v1-__bfloat162float(h1));
    lv.y = packb(v2-__bfloat162float(h2), v3-__bfloat162float(h3));
    *(uint2*)&dhi[o] = hv;
    *(uint2*)&dlo[o] = lv;
}

// ---------- weight transpose to single fp16 (moe weights) ----------
template<int WHICH>   // 2: w1, 3: w2
__global__ void transpose_h(const float* __restrict__ src){
    constexpr int Kd = (WHICH==3)?HID:DIM;
    constexpr int Nd = (WHICH==2)?HID:DIM;
    h16* dst = (WHICH==2)? g_w1T_h : g_w2T_h;
    const int e=blockIdx.z;
    src += (size_t)e*Kd*Nd; dst += (size_t)e*(size_t)Nd*Kd;
    __shared__ float t[32][33];
    const int n0=blockIdx.x*32, k0=blockIdx.y*32;
    const int tx=threadIdx.x, ty=threadIdx.y;
    for(int i=ty;i<32;i+=8)
        t[i][tx] = src[(size_t)(k0+i)*Nd + n0 + tx];
    __syncthreads();
    const int tid = ty*32+tx;
    const int wq = tid&7, nn = tid>>3;
    uint2 w;
    w.x = packh(t[wq*4+0][nn], t[wq*4+1][nn]);
    w.y = packh(t[wq*4+2][nn], t[wq*4+3][nn]);
    *(uint2*)&dst[(size_t)(n0+nn)*Kd + k0 + wq*4] = w;
}

// ---------- bf16 3-pass GEMM (R7-proven): block 128x256, warp 64x64, K64, 2-stage ----------
// MODE 0: qkv (planar out), MODE 1: proj (+x residual)
template<int MODE, int N, int K>
__global__ void __launch_bounds__(256,1) tgemm(const float* __restrict__ aux){
    constexpr int NKT = K/64;
    constexpr int STG = 98304;
    extern __shared__ char smem[];
    const uint32_t sb = s2u(smem);
    const int tid = threadIdx.x, lane = tid&31, wid = tid>>5;
    const int wm = wid>>2, wn = wid&3;
    const int m0 = blockIdx.y*128, n0 = blockIdx.x*256;

    const bf16 *Ahi,*Alo,*Bhi,*Blo;
    if(MODE==0){ Ahi=g_h_hi; Alo=g_h_lo; Bhi=g_waT_hi; Blo=g_waT_lo; }
    else       { Ahi=g_y_hi; Alo=g_y_lo; Bhi=g_wpT_hi; Blo=g_wpT_lo; }

    const uint32_t d0 = swz((uint32_t)((tid>>3)*128 + (tid&7)*16));
    const bf16 *pah[4], *pal[4];
    #pragma unroll
    for(int i=0;i<4;++i){
        int r = (tid>>3) + i*32;
        pah[i]=Ahi+(size_t)(m0+r)*K+(tid&7)*8; pal[i]=Alo+(size_t)(m0+r)*K+(tid&7)*8;
    }
    const bf16 *pb_h = Bhi + (size_t)(n0 + (tid>>3))*K + (tid&7)*8;
    const bf16 *pb_l = Blo + (size_t)(n0 + (tid>>3))*K + (tid&7)*8;

    float acc[4][8][4];
    #pragma unroll
    for(int a=0;a<4;++a)
        #pragma unroll
        for(int b=0;b<8;++b)
            #pragma unroll
            for(int c=0;c<4;++c) acc[a][b][c]=0.f;

    const int arow = wm*64 + (lane&15), achk = lane>>4;
    const int brow_b = wn*64 + ((lane>>4)&1)*8 + (lane&7), bchk = (lane>>3)&1;

    auto issue = [&](int kt){
        const uint32_t st = sb + (kt&1)*STG;
        const int ko = kt*64;
        #pragma unroll
        for(int i=0;i<4;++i){
            cp16(st+d0+i*4096,        pah[i]+ko, true);
            cp16(st+16384+d0+i*4096,  pal[i]+ko, true);
        }
        #pragma unroll
        for(int i=0;i<8;++i){
            cp16(st+32768+d0+i*4096,  pb_h + (size_t)i*32*K + ko, true);
            cp16(st+65536+d0+i*4096,  pb_l + (size_t)i*32*K + ko, true);
        }
        asm volatile("cp.async.commit_group;":::"memory");
    };

    issue(0);
    for(int kt=0; kt<NKT; ++kt){
        if(kt+1<NKT){ issue(kt+1); asm volatile("cp.async.wait_group 1;":::"memory"); }
        else        { asm volatile("cp.async.wait_group 0;":::"memory"); }
        __syncthreads();
        const uint32_t st = sb + (kt&1)*STG;
        #pragma unroll
        for(int k16=0;k16<4;++k16){
            uint32_t ah[4][4], al[4][4];
            #pragma unroll
            for(int mi=0;mi<4;++mi){
                uint32_t off = swz((uint32_t)((arow+mi*16)*128 + k16*32 + achk*16));
                ldx4(ah[mi], st + off);
                ldx4(al[mi], st + 16384 + off);
            }
            #pragma unroll
            for(int n16=0;n16<4;++n16){
                uint32_t off = swz((uint32_t)((brow_b+n16*16)*128 + k16*32 + bchk*16));
                uint32_t rh[4], rl[4];
                ldx4(rh, st + 32768 + off);
                ldx4(rl, st + 65536 + off);
                #pragma unroll
                for(int mi=0;mi<4;++mi){
                    mma16816(acc[mi][n16*2],   ah[mi], rh);
                    mma16816(acc[mi][n16*2],   ah[mi], rl);
                    mma16816(acc[mi][n16*2],   al[mi], rh);
                    mma16816(acc[mi][n16*2+1], ah[mi], rh+2);
                    mma16816(acc[mi][n16*2+1], ah[mi], rl+2);
                    mma16816(acc[mi][n16*2+1], al[mi], rh+2);
                }
            }
        }
        __syncthreads();
    }

    const int r0 = lane>>2, c2 = (lane&3)*2;
    #pragma unroll
    for(int mi=0;mi<4;++mi){
        #pragma unroll
        for(int half=0; half<2; ++half){
            const int m = m0 + wm*64 + mi*16 + r0 + half*8;
            #pragma unroll
            for(int ni=0;ni<8;++ni){
                const int col = n0 + wn*64 + ni*8 + c2;
                float dd0 = acc[mi][ni][half*2], dd1 = acc[mi][ni][half*2+1];
                if(MODE==0){
                    const int which = col>>10, r = col&1023, h = r>>6, d = r&63;
                    const int b = m>>11, t = m&2047;
                    size_t o = ((size_t)(b*16+h)*2048 + t)*64 + d;
                    bf16 *ph, *pl;
                    if(which==0){ dd0*=0.125f; dd1*=0.125f; ph=g_q_hi; pl=g_q_lo; }
                    else if(which==1){ ph=g_k_hi; pl=g_k_lo; }
                    else { ph=g_v_hi; pl=g_v_lo; }
                    bf16 h0=__float2bfloat16(dd0), h1=__float2bfloat16(dd1);
                    *(uint32_t*)&ph[o] = (uint32_t)__bfloat16_as_ushort(h0)
                                       | ((uint32_t)__bfloat16_as_ushort(h1)<<16);
                    *(uint32_t*)&pl[o] = packb(dd0-__bfloat162float(h0), dd1-__bfloat162float(h1));
                } else {
                    const float* rx=aux+(size_t)m*N+col;
                    float2 w; w.x = rx[0]+dd0; w.y = rx[1]+dd1;
                    *(float2*)&g_x1[(size_t)m*N+col] = w;
                }
            }
        }
    }
}

// ---------- single-fp16 MoE GEMM: block 128x256, warp 64x64, K64, 3 stages x 48KB ----------
// D = A*B, A single fp16 activations, B single fp16 weights, fp32 accumulate.
// stage: A [0,16K), B [16K,48K). single sync per iter (R10/R11-proven schedule).
// MODE 2: moe-up (gather h2h, gelu -> poolh). MODE 3: moe-dn (poolh, scatter).
template<int MODE, int N, int K>
__global__ void __launch_bounds__(256,1) hgemm(const float* __restrict__ aux){
    constexpr int NKT = K/64;
    constexpr int STG = 49152;
    const int e = blockIdx.z;
    const int Mrows = g_cnt[e], pbase = g_basei[e];
    if((int)blockIdx.y*128 >= Mrows) return;
    extern __shared__ char smem[];
    const uint32_t sb = s2u(smem);
    const int tid = threadIdx.x, lane = tid&31, wid = tid>>5;
    const int wm = wid>>2, wn = wid&3;
    const int m0 = blockIdx.y*128, n0 = blockIdx.x*256;

    const h16 *A, *B;
    if(MODE==2){ A=g_h2h;  B=g_w1T_h+(size_t)e*HID*DIM; }
    else       { A=g_poolh; B=g_w2T_h+(size_t)e*DIM*HID; }

    const uint32_t d0 = swz((uint32_t)((tid>>3)*128 + (tid&7)*16));
    const h16 *pa[4]; bool av[4];
    #pragma unroll
    for(int i=0;i<4;++i){
        int r = (tid>>3) + i*32, gm = m0 + r;
        bool v = gm < Mrows;
        long rg;
        if(MODE==2) rg = v ? g_tok[e*MAXTOK+gm] : 0;
        else        rg = (long)pbase + (v?gm:0);
        pa[i]=A+(size_t)rg*K+(tid&7)*8; av[i]=v;
    }
    const h16 *pb = B + (size_t)(n0 + (tid>>3))*K + (tid&7)*8;

    float acc[4][8][4];
    #pragma unroll
    for(int a=0;a<4;++a)
        #pragma unroll
        for(int b=0;b<8;++b)
            #pragma unroll
            for(int c=0;c<4;++c) acc[a][b][c]=0.f;

    const int arow = wm*64 + (lane&15), achk = lane>>4;
    const int brow_b = wn*64 + ((lane>>4)&1)*8 + (lane&7), bchk = (lane>>3)&1;

    auto issue = [&](int kt){
        const uint32_t st = sb + (kt%3)*STG;
        const int ko = kt*64;
        #pragma unroll
        for(int i=0;i<4;++i)
            cp16(st+d0+i*4096, pa[i]+ko, av[i]);
        #pragma unroll
        for(int i=0;i<8;++i)
            cp16(st+16384+d0+i*4096, pb + (size_t)i*32*K + ko, true);
        asm volatile("cp.async.commit_group;":::"memory");
    };

    issue(0); issue(1);
    for(int kt=0; kt<NKT; ++kt){
        if(kt+1<NKT){ asm volatile("cp.async.wait_group 1;":::"memory"); }
        else        { asm volatile("cp.async.wait_group 0;":::"memory"); }
        __syncthreads();
        if(kt+2<NKT) issue(kt+2);   // writes stage (kt-1)%3: reads finished before this sync
        const uint32_t st = sb + (kt%3)*STG;
        #pragma unroll
        for(int k16=0;k16<4;++k16){
            uint32_t ah[4][4];
            #pragma unroll
            for(int mi=0;mi<4;++mi){
                uint32_t off = swz((uint32_t)((arow+mi*16)*128 + k16*32 + achk*16));
                ldx4(ah[mi], st + off);
            }
            #pragma unroll
            for(int n16=0;n16<4;++n16){
                uint32_t off = swz((uint32_t)((brow_b+n16*16)*128 + k16*32 + bchk*16));
                uint32_t rb[4];
                ldx4(rb, st + 16384 + off);
                #pragma unroll
                for(int mi=0;mi<4;++mi){
                    mma16816h(acc[mi][n16*2],   ah[mi], rb);
                    mma16816h(acc[mi][n16*2+1], ah[mi], rb+2);
                }
            }
        }
    }

    const int r0 = lane>>2, c2 = (lane&3)*2;
    const float* bias = aux + (size_t)e*N;
    #pragma unroll
    for(int mi=0;mi<4;++mi){
        #pragma unroll
        for(int half=0; half<2; ++half){
            const int m = m0 + wm*64 + mi*16 + r0 + half*8;
            if(m>=Mrows) continue;
            int tok=0, slot=0; float wgt=0.f;
            if(MODE==3){ int ix=e*MAXTOK+m; tok=g_tok[ix]; wgt=g_wt[ix]; slot=g_slot[ix]; }
            #pragma unroll
            for(int ni=0;ni<8;++ni){
                const int col = n0 + wn*64 + ni*8 + c2;
                float dd0 = acc[mi][ni][half*2], dd1 = acc[mi][ni][half*2+1];
                if(MODE==2){
                    size_t prow=(size_t)(pbase+m);
                    float v0=dd0+bias[col], v1=dd1+bias[col+1];
                    float gg0=0.5f*v0*(1.f+erff(v0*0.70710678f));
                    float gg1=0.5f*v1*(1.f+erff(v1*0.70710678f));
                    *(uint32_t*)&g_poolh[prow*HID+col] = packh(gg0, gg1);
                } else {
                    float2 w; w.x = wgt*(dd0+bias[col]); w.y = wgt*(dd1+bias[col+1]);
                    *(float2*)&((slot?g_c1:g_c0)[(size_t)tok*DIM+col]) = w;
                }
            }
        }
    }
}

// ---------- tensor-core flash attention (R7-proven, unchanged) ----------
__global__ void __launch_bounds__(256,1) attn_mma(){
    extern __shared__ char smem[];
    const uint32_t sb = s2u(smem);
    const int tid=threadIdx.x, lane=tid&31, wid=tid>>5;
    const int bh = blockIdx.y;
    const int qt = (gridDim.x-1) - blockIdx.x;
    const int q0 = qt*128;
    const size_t pbase = (size_t)bh*2048*64;

    #pragma unroll
    for(int i=0;i<4;++i){
        int idx=tid+i*256, r=idx>>3, c=idx&7;
        uint32_t off = swz((uint32_t)(r*128+c*16));
        cp16(sb+off,        g_q_hi + pbase + (size_t)(q0+r)*64 + c*8, true);
        cp16(sb+16384+off,  g_q_lo + pbase + (size_t)(q0+r)*64 + c*8, true);
    }
    auto issueKV = [&](int kb){
        const uint32_t st = sb + 32768 + (kb%3)*32768;
        #pragma unroll
        for(int i=0;i<2;++i){
            int idx=tid+i*256, r=idx>>3, c=idx&7;
            uint32_t off = swz((uint32_t)(r*128+c*16));
            size_t src = pbase + (size_t)(kb*64+r)*64 + c*8;
            cp16(st+off,        g_k_hi+src, true);
            cp16(st+8192+off,   g_k_lo+src, true);
            cp16(st+16384+off,  g_v_hi+src, true);
            cp16(st+24576+off,  g_v_lo+src, true);
        }
        asm volatile("cp.async.commit_group;":::"memory");
    };
    const int kbmax = 2*qt+1;
    issueKV(0);
    issueKV(1);

    asm volatile("cp.async.wait_group 1;":::"memory");
    __syncthreads();
    uint32_t qh[4][4], ql[4][4];
    {
        const int qrow = wid*16 + (lane&15), qchk = lane>>4;
        #pragma unroll
        for(int k16=0;k16<4;++k16){
            uint32_t off = swz((uint32_t)(qrow*128 + k16*32 + qchk*16));
            ldx4(qh[k16], sb+off);
            ldx4(ql[k16], sb+16384+off);
        }
    }

    float O[8][4], mstat[2], lstat[2];
    #pragma unroll
    for(int t=0;t<8;++t){ O[t][0]=0;O[t][1]=0;O[t][2]=0;O[t][3]=0; }
    mstat[0]=mstat[1]=-1e30f; lstat[0]=lstat[1]=0.f;

    const int rloc = lane>>2, cloc = (lane&3)*2;
    const int brow_b = ((lane>>4)&1)*8 + (lane&7), bchk = (lane>>3)&1;
    const int vrow_b = ((lane>>3)&1)*8 + (lane&7), vcol_b = ((lane>>4)&1)*8;

    for(int kb=0; kb<=kbmax; ++kb){
        if(kb<kbmax){ asm volatile("cp.async.wait_group 1;":::"memory"); }
        else        { asm volatile("cp.async.wait_group 0;":::"memory"); }
        __syncthreads();
        if(kb+2<=kbmax) issueKV(kb+2);
        const uint32_t st = sb + 32768 + (kb%3)*32768;

        float s[8][4];
        #pragma unroll
        for(int t=0;t<8;++t){ s[t][0]=0;s[t][1]=0;s[t][2]=0;s[t][3]=0; }
        #pragma unroll
        for(int k16=0;k16<4;++k16){
            uint32_t bkh[8][2], bkl[8][2];
            #pragma unroll
            for(int n16=0;n16<4;++n16){
                uint32_t off = swz((uint32_t)((n16*16+brow_b)*128 + k16*32 + bchk*16));
                uint32_t r[4];
                ldx4(r, st+off);
                bkh[n16*2][0]=r[0]; bkh[n16*2][1]=r[1]; bkh[n16*2+1][0]=r[2]; bkh[n16*2+1][1]=r[3];
                ldx4(r, st+8192+off);
                bkl[n16*2][0]=r[0]; bkl[n16*2][1]=r[1]; bkl[n16*2+1][0]=r[2]; bkl[n16*2+1][1]=r[3];
            }
            #pragma unroll
            for(int t=0;t<8;++t){
                mma16816(s[t], qh[k16], bkh[t]);
                mma16816(s[t], qh[k16], bkl[t]);
                mma16816(s[t], ql[k16], bkh[t]);
            }
        }
        if(kb >= 2*qt){
            const int row0 = q0 + wid*16 + rloc;
            #pragma unroll
            for(int t=0;t<8;++t){
                int c0 = kb*64 + t*8 + cloc;
                if(c0   > row0  ) s[t][0]=-1e30f;
                if(c0+1 > row0  ) s[t][1]=-1e30f;
                if(c0   > row0+8) s[t][2]=-1e30f;
                if(c0+1 > row0+8) s[t][3]=-1e30f;
            }
        }
        float corr[2];
        #pragma unroll
        for(int rh=0; rh<2; ++rh){
            float mt=-1e30f;
            #pragma unroll
            for(int t=0;t<8;++t) mt = fmaxf(mt, fmaxf(s[t][rh*2], s[t][rh*2+1]));
            mt = fmaxf(mt, __shfl_xor_sync(~0u, mt, 1, 4));
            mt = fmaxf(mt, __shfl_xor_sync(~0u, mt, 2, 4));
            float mn = fmaxf(mstat[rh], mt);
            corr[rh] = __expf(mstat[rh]-mn); mstat[rh]=mn;
            float rs=0.f;
            #pragma unroll
            for(int t=0;t<8;++t){
                float p0=__expf(s[t][rh*2]-mn), p1=__expf(s[t][rh*2+1]-mn);
                s[t][rh*2]=p0; s[t][rh*2+1]=p1; rs += p0+p1;
            }
            rs += __shfl_xor_sync(~0u, rs, 1, 4);
            rs += __shfl_xor_sync(~0u, rs, 2, 4);
            lstat[rh] = lstat[rh]*corr[rh] + rs;
        }
        #pragma unroll
        for(int t=0;t<8;++t){
            O[t][0]*=corr[0]; O[t][1]*=corr[0]; O[t][2]*=corr[1]; O[t][3]*=corr[1];
        }
        uint32_t ph[4][4], pl[4][4];
        #pragma unroll
        for(int k16=0;k16<4;++k16){
            #pragma unroll
            for(int half=0; half<2; ++half){
                const int t = 2*k16+half;
                float f0=s[t][0], f1=s[t][1], f2=s[t][2], f3=s[t][3];
                ph[k16][half*2]   = packb(f0,f1);
                ph[k16][half*2+1] = packb(f2,f3);
                bf16 h0=__float2bfloat16(f0), h1=__float2bfloat16(f1);
                bf16 h2=__float2bfloat16(f2), h3=__float2bfloat16(f3);
                pl[k16][half*2]   = packb(f0-__bfloat162float(h0), f1-__bfloat162float(h1));
                pl[k16][half*2+1] = packb(f2-__bfloat162float(h2), f3-__bfloat162float(h3));
            }
        }
        #pragma unroll
        for(int k16=0;k16<4;++k16){
            uint32_t bvh[8][2], bvl[8][2];
            #pragma unroll
            for(int d16=0;d16<4;++d16){
                uint32_t off = swz((uint32_t)((k16*16+vrow_b)*128 + (d16*16+vcol_b)*2));
                uint32_t r[4];
                ldx4t(r, st+16384+off);
                bvh[d16*2][0]=r[0]; bvh[d16*2][1]=r[1]; bvh[d16*2+1][0]=r[2]; bvh[d16*2+1][1]=r[3];
                ldx4t(r, st+24576+off);
                bvl[d16*2][0]=r[0]; bvl[d16*2][1]=r[1]; bvl[d16*2+1][0]=r[2]; bvl[d16*2+1][1]=r[3];
            }
            #pragma unroll
            for(int t=0;t<8;++t){
                mma16816(O[t], ph[k16], bvh[t]);
                mma16816(O[t], ph[k16], bvl[t]);
                mma16816(O[t], pl[k16], bvh[t]);
            }
        }
        __syncthreads();
    }

    const int b = bh>>4, h = bh&15;
    #pragma unroll
    for(int rh=0; rh<2; ++rh){
        const float inv = 1.f/lstat[rh];
        const int row = q0 + wid*16 + rloc + rh*8;
        size_t base = (size_t)(b*TT+row)*DIM + h*64;
        #pragma unroll
        for(int t=0;t<8;++t){
            float v0 = O[t][rh*2]*inv, v1 = O[t][rh*2+1]*inv;
            size_t o = base + t*8 + cloc;
            bf16 h0=__float2bfloat16(v0), h1=__float2bfloat16(v1);
            g_y_hi[o]=h0; g_y_hi[o+1]=h1;
            g_y_lo[o]=__float2bfloat16(v0-__bfloat162float(h0));
            g_y_lo[o+1]=__float2bfloat16(v1-__bfloat162float(h1));
        }
    }
}

// ---------- router ----------
__global__ void router_kernel(const float* __restrict__ wr){
    const int n=blockIdx.x, tid=threadIdx.x;
    float acc[NEXP];
    #pragma unroll
    for(int e=0;e<NEXP;++e) acc[e]=0.f;
    const float* row=g_h2f+(size_t)n*DIM;
    for(int d=tid;d<DIM;d+=128){
        float hv=row[d];
        #pragma unroll
        for(int e=0;e<NEXP;++e) acc[e]+=hv*wr[d*NEXP+e];
    }
    __shared__ float sm[4][NEXP];
    #pragma unroll
    for(int e=0;e<NEXP;++e){
        float v=acc[e];
        #pragma unroll
        for(int o=16;o;o>>=1) v+=__shfl_xor_sync(~0u,v,o);
        if((tid&31)==0) sm[tid>>5][e]=v;
    }
    __syncthreads();
    if(tid==0){
        float lg[NEXP];
        #pragma unroll
        for(int e=0;e<NEXP;++e) lg[e]=sm[0][e]+sm[1][e]+sm[2][e]+sm[3][e];
        int e0=0;
        #pragma unroll
        for(int e=1;e<NEXP;++e) if(lg[e]>lg[e0]) e0=e;
        int e1=-1;
        #pragma unroll
        for(int e=0;e<NEXP;++e) if(e!=e0 && (e1<0||lg[e]>lg[e1])) e1=e;
        float w0=1.f/(1.f+__expf(lg[e1]-lg[e0])), w1=1.f-w0;
        int p0=atomicAdd(&g_cnt[e0],1);
        g_tok[e0*MAXTOK+p0]=n; g_wt[e0*MAXTOK+p0]=w0; g_slot[e0*MAXTOK+p0]=0;
        int p1=atomicAdd(&g_cnt[e1],1);
        g_tok[e1*MAXTOK+p1]=n; g_wt[e1*MAXTOK+p1]=w1; g_slot[e1*MAXTOK+p1]=1;
    }
}

// ---------- launch ----------
extern "C" void kernel_launch(void* const* d_in, const int* in_sizes, int n_in,
                              void* d_out, int out_size){
    const float* x      =(const float*)d_in[0];
    const float* ln1_g  =(const float*)d_in[1];
    const float* ln1_b  =(const float*)d_in[2];
    const float* w_attn =(const float*)d_in[3];
    const float* w_proj =(const float*)d_in[4];
    const float* ln2_g  =(const float*)d_in[5];
    const float* ln2_b  =(const float*)d_in[6];
    const float* w_rtr  =(const float*)d_in[7];
    const float* w1     =(const float*)d_in[8];
    const float* b1     =(const float*)d_in[9];
    const float* w2     =(const float*)d_in[10];
    const float* b2     =(const float*)d_in[11];
    float* out=(float*)d_out;

    const int SMG = 196608;
    const int SMH = 147456;
    cudaFuncSetAttribute(tgemm<0,3*DIM,DIM>, cudaFuncAttributeMaxDynamicSharedMemorySize, SMG);
    cudaFuncSetAttribute(tgemm<1,DIM,DIM>,   cudaFuncAttributeMaxDynamicSharedMemorySize, SMG);
    cudaFuncSetAttribute(hgemm<2,HID,DIM>,   cudaFuncAttributeMaxDynamicSharedMemorySize, SMH);
    cudaFuncSetAttribute(hgemm<3,DIM,HID>,   cudaFuncAttributeMaxDynamicSharedMemorySize, SMH);
    const int SMA = 131072;
    cudaFuncSetAttribute(attn_mma, cudaFuncAttributeMaxDynamicSharedMemorySize, SMA);

    zero_cnt_kernel<<<1,32>>>();
    transpose_split<0><<<dim3(96,32,1), dim3(32,8)>>>(w_attn);
    transpose_split<1><<<dim3(32,32,1), dim3(32,8)>>>(w_proj);
    transpose_h<2><<<dim3(128,32,NEXP), dim3(32,8)>>>(w1);
    transpose_h<3><<<dim3(32,128,NEXP), dim3(32,8)>>>(w2);

    ln_kernel<0><<<NTOK,256>>>(x, ln1_g, ln1_b);
    tgemm<0,3*DIM,DIM><<<dim3(12,32,1),256,SMG>>>(nullptr);
    attn_mma<<<dim3(TT/128, BB*16),256,SMA>>>();
    tgemm<1,DIM,DIM><<<dim3(4,32,1),256,SMG>>>(x);
    ln_kernel<1><<<NTOK,256>>>(nullptr, ln2_g, ln2_b);
    router_kernel<<<NTOK,128>>>(w_rtr);
    base_kernel<<<1,32>>>();
    hgemm<2,HID,DIM><<<dim3(16,32,NEXP),256,SMH>>>(b1);
    hgemm<3,DIM,HID><<<dim3(4,32,NEXP),256,SMH>>>(b2);
    final_kernel<<<NTOK*DIM/256,256>>>(out);
}

// round 13
// speedup vs baseline: 2.5168x; 1.1027x over previous
#include <cuda_runtime.h>
#include <cuda_bf16.h>
#include <cuda_fp16.h>
#include <math.h>
#include <stdint.h>

#define BB 2
#define TT 2048
#define DIM 1024
#define NTOK 4096
#define NEXP 8
#define HID 4096
#define MAXTOK 4096
typedef __nv_bfloat16 bf16;
typedef __half h16;

// ---------- scratch ----------
__device__ bf16 g_h_hi[NTOK*DIM], g_h_lo[NTOK*DIM];
__device__ bf16 g_q_hi[32*2048*64], g_q_lo[32*2048*64];
__device__ bf16 g_k_hi[32*2048*64], g_k_lo[32*2048*64];
__device__ h16  g_vh[32*2048*64];
__device__ h16  g_yh[NTOK*DIM];
__device__ float g_x1[NTOK*DIM], g_h2f[NTOK*DIM];
__device__ h16  g_h2h[NTOK*DIM];
__device__ h16  g_poolh[(size_t)2*NTOK*HID];
__device__ float g_c0[NTOK*DIM], g_c1[NTOK*DIM];
__device__ int g_cnt[NEXP], g_basei[NEXP], g_tok[NEXP*MAXTOK], g_slot[NEXP*MAXTOK];
__device__ float g_wt[NEXP*MAXTOK];
__device__ bf16 g_waT_hi[(size_t)3*DIM*DIM], g_waT_lo[(size_t)3*DIM*DIM];
__device__ h16  g_wpT_h[(size_t)DIM*DIM];
__device__ h16  g_w1T_h[(size_t)NEXP*HID*DIM];
__device__ h16  g_w2T_h[(size_t)NEXP*DIM*HID];

// ---------- ptx helpers ----------
__device__ __forceinline__ uint32_t s2u(const void* p){
    uint32_t a; asm("{ .reg .u64 t; cvta.to.shared.u64 t, %1; cvt.u32.u64 %0, t; }":"=r"(a):"l"(p)); return a;
}
__device__ __forceinline__ uint32_t swz(uint32_t o){ return o ^ ((o>>3)&0x70); }
__device__ __forceinline__ void cp16(uint32_t d, const void* s, bool v){
    asm volatile("cp.async.cg.shared.global [%0], [%1], 16, %2;"
        ::"r"(d),"l"(__cvta_generic_to_global(s)),"r"(v?16:0));
}
__device__ __forceinline__ void ldx4(uint32_t* r, uint32_t a){
    asm volatile("ldmatrix.sync.aligned.m8n8.x4.shared.b16 {%0,%1,%2,%3},[%4];"
        :"=r"(r[0]),"=r"(r[1]),"=r"(r[2]),"=r"(r[3]):"r"(a));
}
__device__ __forceinline__ void ldx4t(uint32_t* r, uint32_t a){
    asm volatile("ldmatrix.sync.aligned.m8n8.x4.trans.shared.b16 {%0,%1,%2,%3},[%4];"
        :"=r"(r[0]),"=r"(r[1]),"=r"(r[2]),"=r"(r[3]):"r"(a));
}
__device__ __forceinline__ void mma16816(float* d, const uint32_t* a, const uint32_t* b){
    asm volatile("mma.sync.aligned.m16n8k16.row.col.f32.bf16.bf16.f32 "
        "{%0,%1,%2,%3},{%4,%5,%6,%7},{%8,%9},{%0,%1,%2,%3};"
        : "+f"(d[0]),"+f"(d[1]),"+f"(d[2]),"+f"(d[3])
        : "r"(a[0]),"r"(a[1]),"r"(a[2]),"r"(a[3]),"r"(b[0]),"r"(b[1]));
}
__device__ __forceinline__ void mma16816h(float* d, const uint32_t* a, const uint32_t* b){
    asm volatile("mma.sync.aligned.m16n8k16.row.col.f32.f16.f16.f32 "
        "{%0,%1,%2,%3},{%4,%5,%6,%7},{%8,%9},{%0,%1,%2,%3};"
        : "+f"(d[0]),"+f"(d[1]),"+f"(d[2]),"+f"(d[3])
        : "r"(a[0]),"r"(a[1]),"r"(a[2]),"r"(a[3]),"r"(b[0]),"r"(b[1]));
}
__device__ __forceinline__ uint32_t packb(float f0, float f1){
    bf16 b0=__float2bfloat16(f0), b1=__float2bfloat16(f1);
    return (uint32_t)__bfloat16_as_ushort(b0) | ((uint32_t)__bfloat16_as_ushort(b1)<<16);
}
__device__ __forceinline__ uint32_t packh(float f0, float f1){
    __half2 p = __floats2half2_rn(f0, f1);
    return *(uint32_t*)&p;
}

// ---------- small kernels ----------
__global__ void zero_cnt_kernel(){ if(threadIdx.x<NEXP) g_cnt[threadIdx.x]=0; }
__global__ void base_kernel(){
    if(threadIdx.x==0){ int s=0; for(int e=0;e<NEXP;++e){ g_basei[e]=s; s+=g_cnt[e]; } }
}
__global__ void final_kernel(float* __restrict__ out){
    int i = blockIdx.x*256 + threadIdx.x;
    out[i] = g_x1[i] + g_c0[i] + g_c1[i];
}

// ---------- layernorm ----------
template<int WHICH>
__global__ void ln_kernel(const float* __restrict__ in, const float* __restrict__ gam,
                          const float* __restrict__ bet){
    __shared__ float sx[DIM]; __shared__ float red[8];
    const int n=blockIdx.x, tid=threadIdx.x;
    const float* row = (WHICH==0 ? in : g_x1) + (size_t)n*DIM;
    float4 x4 = ((const float4*)row)[tid];
    ((float4*)sx)[tid] = x4;
    float s = x4.x+x4.y+x4.z+x4.w;
    #pragma unroll
    for(int o=16;o;o>>=1) s += __shfl_xor_sync(~0u,s,o);
    if((tid&31)==0) red[tid>>5]=s;
    __syncthreads();
    float mu = (red[0]+red[1]+red[2]+red[3]+red[4]+red[5]+red[6]+red[7])*(1.f/DIM);
    float sq=0.f;
    #pragma unroll
    for(int p=0;p<4;++p){ float d=sx[tid+p*256]-mu; sq+=d*d; }
    #pragma unroll
    for(int o=16;o;o>>=1) sq += __shfl_xor_sync(~0u,sq,o);
    __syncthreads();
    if((tid&31)==0) red[tid>>5]=sq;
    __syncthreads();
    float var=(red[0]+red[1]+red[2]+red[3]+red[4]+red[5]+red[6]+red[7])*(1.f/DIM);
    float rs = rsqrtf(var+1e-5f);
    #pragma unroll
    for(int p=0;p<4;++p){
        int d=tid+p*256;
        float v = (sx[d]-mu)*rs*gam[d]+bet[d];
        size_t o=(size_t)n*DIM+d;
        if(WHICH==0){
            bf16 h = __float2bfloat16(v);
            g_h_hi[o]=h; g_h_lo[o]=__float2bfloat16(v - __bfloat162float(h));
        } else {
            g_h2f[o]=v;
            g_h2h[o]=__float2half_rn(v);
        }
    }
}

// ---------- w_attn transpose + split to bf16 hi/lo ----------
__global__ void transpose_split0(const float* __restrict__ src){
    constexpr int Kd = DIM, Nd = 3*DIM;
    __shared__ float t[32][33];
    const int n0=blockIdx.x*32, k0=blockIdx.y*32;
    const int tx=threadIdx.x, ty=threadIdx.y;
    for(int i=ty;i<32;i+=8)
        t[i][tx] = src[(size_t)(k0+i)*Nd + n0 + tx];
    __syncthreads();
    const int tid = ty*32+tx;
    const int wq = tid&7, nn = tid>>3;
    float v0=t[wq*4+0][nn], v1=t[wq*4+1][nn], v2=t[wq*4+2][nn], v3=t[wq*4+3][nn];
    bf16 h0=__float2bfloat16(v0), h1=__float2bfloat16(v1);
    bf16 h2=__float2bfloat16(v2), h3=__float2bfloat16(v3);
    size_t o = (size_t)(n0+nn)*Kd + k0 + wq*4;
    uint2 hv, lv;
    hv.x = (uint32_t)__bfloat16_as_ushort(h0) | ((uint32_t)__bfloat16_as_ushort(h1)<<16);
    hv.y = (uint32_t)__bfloat16_as_ushort(h2) | ((uint32_t)__bfloat16_as_ushort(h3)<<16);
    lv.x = packb(v0-__bfloat162float(h0), v1-__bfloat162float(h1));
    lv.y = packb(v2-__bfloat162float(h2), v3-__bfloat162float(h3));
    *(uint2*)&g_waT_hi[o] = hv;
    *(uint2*)&g_waT_lo[o] = lv;
}

// ---------- weight transpose to single fp16 (w_proj, w1, w2) ----------
template<int WHICH>   // 1: w_proj, 2: w1, 3: w2
__global__ void transpose_h(const float* __restrict__ src){
    constexpr int Kd = (WHICH==3)?HID:DIM;
    constexpr int Nd = (WHICH==2)?HID:DIM;
    h16* dst = (WHICH==1)? g_wpT_h : ((WHICH==2)? g_w1T_h : g_w2T_h);
    const int e=blockIdx.z;
    src += (size_t)e*Kd*Nd; dst += (size_t)e*(size_t)Nd*Kd;
    __shared__ float t[32][33];
    const int n0=blockIdx.x*32, k0=blockIdx.y*32;
    const int tx=threadIdx.x, ty=threadIdx.y;
    for(int i=ty;i<32;i+=8)
        t[i][tx] = src[(size_t)(k0+i)*Nd + n0 + tx];
    __syncthreads();
    const int tid = ty*32+tx;
    const int wq = tid&7, nn = tid>>3;
    uint2 w;
    w.x = packh(t[wq*4+0][nn], t[wq*4+1][nn]);
    w.y = packh(t[wq*4+2][nn], t[wq*4+3][nn]);
    *(uint2*)&dst[(size_t)(n0+nn)*Kd + k0 + wq*4] = w;
}

// ---------- bf16 3-pass QKV GEMM (R7-proven): block 128x256, warp 64x64, K64, 2-stage ----------
__global__ void __launch_bounds__(256,1) tgemm0(){
    constexpr int N = 3*DIM, K = DIM;
    constexpr int NKT = K/64;
    constexpr int STG = 98304;
    extern __shared__ char smem[];
    const uint32_t sb = s2u(smem);
    const int tid = threadIdx.x, lane = tid&31, wid = tid>>5;
    const int wm = wid>>2, wn = wid&3;
    const int m0 = blockIdx.y*128, n0 = blockIdx.x*256;

    const uint32_t d0 = swz((uint32_t)((tid>>3)*128 + (tid&7)*16));
    const bf16 *pah[4], *pal[4];
    #pragma unroll
    for(int i=0;i<4;++i){
        int r = (tid>>3) + i*32;
        pah[i]=g_h_hi+(size_t)(m0+r)*K+(tid&7)*8; pal[i]=g_h_lo+(size_t)(m0+r)*K+(tid&7)*8;
    }
    const bf16 *pb_h = g_waT_hi + (size_t)(n0 + (tid>>3))*K + (tid&7)*8;
    const bf16 *pb_l = g_waT_lo + (size_t)(n0 + (tid>>3))*K + (tid&7)*8;

    float acc[4][8][4];
    #pragma unroll
    for(int a=0;a<4;++a)
        #pragma unroll
        for(int b=0;b<8;++b)
            #pragma unroll
            for(int c=0;c<4;++c) acc[a][b][c]=0.f;

    const int arow = wm*64 + (lane&15), achk = lane>>4;
    const int brow_b = wn*64 + ((lane>>4)&1)*8 + (lane&7), bchk = (lane>>3)&1;

    auto issue = [&](int kt){
        const uint32_t st = sb + (kt&1)*STG;
        const int ko = kt*64;
        #pragma unroll
        for(int i=0;i<4;++i){
            cp16(st+d0+i*4096,        pah[i]+ko, true);
            cp16(st+16384+d0+i*4096,  pal[i]+ko, true);
        }
        #pragma unroll
        for(int i=0;i<8;++i){
            cp16(st+32768+d0+i*4096,  pb_h + (size_t)i*32*K + ko, true);
            cp16(st+65536+d0+i*4096,  pb_l + (size_t)i*32*K + ko, true);
        }
        asm volatile("cp.async.commit_group;":::"memory");
    };

    issue(0);
    for(int kt=0; kt<NKT; ++kt){
        if(kt+1<NKT){ issue(kt+1); asm volatile("cp.async.wait_group 1;":::"memory"); }
        else        { asm volatile("cp.async.wait_group 0;":::"memory"); }
        __syncthreads();
        const uint32_t st = sb + (kt&1)*STG;
        #pragma unroll
        for(int k16=0;k16<4;++k16){
            uint32_t ah[4][4], al[4][4];
            #pragma unroll
            for(int mi=0;mi<4;++mi){
                uint32_t off = swz((uint32_t)((arow+mi*16)*128 + k16*32 + achk*16));
                ldx4(ah[mi], st + off);
                ldx4(al[mi], st + 16384 + off);
            }
            #pragma unroll
            for(int n16=0;n16<4;++n16){
                uint32_t off = swz((uint32_t)((brow_b+n16*16)*128 + k16*32 + bchk*16));
                uint32_t rh[4], rl[4];
                ldx4(rh, st + 32768 + off);
                ldx4(rl, st + 65536 + off);
                #pragma unroll
                for(int mi=0;mi<4;++mi){
                    mma16816(acc[mi][n16*2],   ah[mi], rh);
                    mma16816(acc[mi][n16*2],   ah[mi], rl);
                    mma16816(acc[mi][n16*2],   al[mi], rh);
                    mma16816(acc[mi][n16*2+1], ah[mi], rh+2);
                    mma16816(acc[mi][n16*2+1], ah[mi], rl+2);
                    mma16816(acc[mi][n16*2+1], al[mi], rh+2);
                }
            }
        }
        __syncthreads();
    }

    const int r0 = lane>>2, c2 = (lane&3)*2;
    #pragma unroll
    for(int mi=0;mi<4;++mi){
        #pragma unroll
        for(int half=0; half<2; ++half){
            const int m = m0 + wm*64 + mi*16 + r0 + half*8;
            #pragma unroll
            for(int ni=0;ni<8;++ni){
                const int col = n0 + wn*64 + ni*8 + c2;
                float dd0 = acc[mi][ni][half*2], dd1 = acc[mi][ni][half*2+1];
                const int which = col>>10, r = col&1023, h = r>>6, d = r&63;
                const int b = m>>11, t = m&2047;
                size_t o = ((size_t)(b*16+h)*2048 + t)*64 + d;
                if(which==2){
                    *(uint32_t*)&g_vh[o] = packh(dd0, dd1);
                } else {
                    bf16 *ph, *pl;
                    if(which==0){ dd0*=0.125f; dd1*=0.125f; ph=g_q_hi; pl=g_q_lo; }
                    else { ph=g_k_hi; pl=g_k_lo; }
                    bf16 h0=__float2bfloat16(dd0), h1=__float2bfloat16(dd1);
                    *(uint32_t*)&ph[o] = (uint32_t)__bfloat16_as_ushort(h0)
                                       | ((uint32_t)__bfloat16_as_ushort(h1)<<16);
                    *(uint32_t*)&pl[o] = packb(dd0-__bfloat162float(h0), dd1-__bfloat162float(h1));
                }
            }
        }
    }
}

// ---------- single-fp16 GEMM: block 128x256, warp 64x64, K64, 3 stages x 48KB ----------
// MODE 1: proj (dense y@wp, +x residual). MODE 2: moe-up. MODE 3: moe-dn.
template<int MODE, int N, int K>
__global__ void __launch_bounds__(256,1) hgemm(const float* __restrict__ aux){
    constexpr int NKT = K/64;
    constexpr int STG = 49152;
    const int e = (MODE>=2)? blockIdx.z : 0;
    int Mrows = NTOK, pbase = 0;
    if(MODE>=2){
        Mrows = g_cnt[e]; pbase = g_basei[e];
        if((int)blockIdx.y*128 >= Mrows) return;
    }
    extern __shared__ char smem[];
    const uint32_t sb = s2u(smem);
    const int tid = threadIdx.x, lane = tid&31, wid = tid>>5;
    const int wm = wid>>2, wn = wid&3;
    const int m0 = blockIdx.y*128, n0 = blockIdx.x*256;

    const h16 *A, *B;
    if(MODE==1){ A=g_yh;    B=g_wpT_h; }
    else if(MODE==2){ A=g_h2h;  B=g_w1T_h+(size_t)e*HID*DIM; }
    else       { A=g_poolh; B=g_w2T_h+(size_t)e*DIM*HID; }

    const uint32_t d0 = swz((uint32_t)((tid>>3)*128 + (tid&7)*16));
    const h16 *pa[4]; bool av[4];
    #pragma unroll
    for(int i=0;i<4;++i){
        int r = (tid>>3) + i*32, gm = m0 + r;
        bool v = gm < Mrows;
        long rg = gm;
        if(MODE==2) rg = v ? g_tok[e*MAXTOK+gm] : 0;
        if(MODE==3) rg = (long)pbase + (v?gm:0);
        pa[i]=A+(size_t)rg*K+(tid&7)*8; av[i]=v;
    }
    const h16 *pb = B + (size_t)(n0 + (tid>>3))*K + (tid&7)*8;

    float acc[4][8][4];
    #pragma unroll
    for(int a=0;a<4;++a)
        #pragma unroll
        for(int b=0;b<8;++b)
            #pragma unroll
            for(int c=0;c<4;++c) acc[a][b][c]=0.f;

    const int arow = wm*64 + (lane&15), achk = lane>>4;
    const int brow_b = wn*64 + ((lane>>4)&1)*8 + (lane&7), bchk = (lane>>3)&1;

    auto issue = [&](int kt){
        const uint32_t st = sb + (kt%3)*STG;
        const int ko = kt*64;
        #pragma unroll
        for(int i=0;i<4;++i)
            cp16(st+d0+i*4096, pa[i]+ko, av[i]);
        #pragma unroll
        for(int i=0;i<8;++i)
            cp16(st+16384+d0+i*4096, pb + (size_t)i*32*K + ko, true);
        asm volatile("cp.async.commit_group;":::"memory");
    };

    issue(0); issue(1);
    for(int kt=0; kt<NKT; ++kt){
        if(kt+1<NKT){ asm volatile("cp.async.wait_group 1;":::"memory"); }
        else        { asm volatile("cp.async.wait_group 0;":::"memory"); }
        __syncthreads();
        if(kt+2<NKT) issue(kt+2);
        const uint32_t st = sb + (kt%3)*STG;
        #pragma unroll
        for(int k16=0;k16<4;++k16){
            uint32_t ah[4][4];
            #pragma unroll
            for(int mi=0;mi<4;++mi){
                uint32_t off = swz((uint32_t)((arow+mi*16)*128 + k16*32 + achk*16));
                ldx4(ah[mi], st + off);
            }
            #pragma unroll
            for(int n16=0;n16<4;++n16){
                uint32_t off = swz((uint32_t)((brow_b+n16*16)*128 + k16*32 + bchk*16));
                uint32_t rb[4];
                ldx4(rb, st + 16384 + off);
                #pragma unroll
                for(int mi=0;mi<4;++mi){
                    mma16816h(acc[mi][n16*2],   ah[mi], rb);
                    mma16816h(acc[mi][n16*2+1], ah[mi], rb+2);
                }
            }
        }
    }

    const int r0 = lane>>2, c2 = (lane&3)*2;
    const float* bias = (MODE>=2) ? (aux + (size_t)e*N) : aux;
    #pragma unroll
    for(int mi=0;mi<4;++mi){
        #pragma unroll
        for(int half=0; half<2; ++half){
            const int m = m0 + wm*64 + mi*16 + r0 + half*8;
            if(MODE>=2 && m>=Mrows) continue;
            int tok=0, slot=0; float wgt=0.f;
            if(MODE==3){ int ix=e*MAXTOK+m; tok=g_tok[ix]; wgt=g_wt[ix]; slot=g_slot[ix]; }
            #pragma unroll
            for(int ni=0;ni<8;++ni){
                const int col = n0 + wn*64 + ni*8 + c2;
                float dd0 = acc[mi][ni][half*2], dd1 = acc[mi][ni][half*2+1];
                if(MODE==1){
                    const float* rx = bias + (size_t)m*N + col;   // x residual
                    float2 w; w.x = rx[0]+dd0; w.y = rx[1]+dd1;
                    *(float2*)&g_x1[(size_t)m*N+col] = w;
                } else if(MODE==2){
                    size_t prow=(size_t)(pbase+m);
                    float v0=dd0+bias[col], v1=dd1+bias[col+1];
                    float gg0=0.5f*v0*(1.f+erff(v0*0.70710678f));
                    float gg1=0.5f*v1*(1.f+erff(v1*0.70710678f));
                    *(uint32_t*)&g_poolh[prow*HID+col] = packh(gg0, gg1);
                } else {
                    float2 w; w.x = wgt*(dd0+bias[col]); w.y = wgt*(dd1+bias[col+1]);
                    *(float2*)&((slot?g_c1:g_c0)[(size_t)tok*DIM+col]) = w;
                }
            }
        }
    }
}

// ---------- flash attention: QK bf16 3-pass, PV single fp16; stage 24KB x3 ----------
__global__ void __launch_bounds__(256,1) attn_mma(){
    extern __shared__ char smem[];
    const uint32_t sb = s2u(smem);
    const int tid=threadIdx.x, lane=tid&31, wid=tid>>5;
    const int bh = blockIdx.y;
    const int qt = (gridDim.x-1) - blockIdx.x;
    const int q0 = qt*128;
    const size_t pbase = (size_t)bh*2048*64;

    #pragma unroll
    for(int i=0;i<4;++i){
        int idx=tid+i*256, r=idx>>3, c=idx&7;
        uint32_t off = swz((uint32_t)(r*128+c*16));
        cp16(sb+off,        g_q_hi + pbase + (size_t)(q0+r)*64 + c*8, true);
        cp16(sb+16384+off,  g_q_lo + pbase + (size_t)(q0+r)*64 + c*8, true);
    }
    auto issueKV = [&](int kb){
        const uint32_t st = sb + 32768 + (kb%3)*24576;
        #pragma unroll
        for(int i=0;i<2;++i){
            int idx=tid+i*256, r=idx>>3, c=idx&7;
            uint32_t off = swz((uint32_t)(r*128+c*16));
            size_t src = pbase + (size_t)(kb*64+r)*64 + c*8;
            cp16(st+off,        g_k_hi+src, true);
            cp16(st+8192+off,   g_k_lo+src, true);
            cp16(st+16384+off,  g_vh+src, true);
        }
        asm volatile("cp.async.commit_group;":::"memory");
    };
    const int kbmax = 2*qt+1;
    issueKV(0);
    issueKV(1);

    asm volatile("cp.async.wait_group 1;":::"memory");
    __syncthreads();
    uint32_t qh[4][4], ql[4][4];
    {
        const int qrow = wid*16 + (lane&15), qchk = lane>>4;
        #pragma unroll
        for(int k16=0;k16<4;++k16){
            uint32_t off = swz((uint32_t)(qrow*128 + k16*32 + qchk*16));
            ldx4(qh[k16], sb+off);
            ldx4(ql[k16], sb+16384+off);
        }
    }

    float O[8][4], mstat[2], lstat[2];
    #pragma unroll
    for(int t=0;t<8;++t){ O[t][0]=0;O[t][1]=0;O[t][2]=0;O[t][3]=0; }
    mstat[0]=mstat[1]=-1e30f; lstat[0]=lstat[1]=0.f;

    const int rloc = lane>>2, cloc = (lane&3)*2;
    const int brow_b = ((lane>>4)&1)*8 + (lane&7), bchk = (lane>>3)&1;
    const int vrow_b = ((lane>>3)&1)*8 + (lane&7), vcol_b = ((lane>>4)&1)*8;

    for(int kb=0; kb<=kbmax; ++kb){
        if(kb<kbmax){ asm volatile("cp.async.wait_group 1;":::"memory"); }
        else        { asm volatile("cp.async.wait_group 0;":::"memory"); }
        __syncthreads();
        if(kb+2<=kbmax) issueKV(kb+2);
        const uint32_t st = sb + 32768 + (kb%3)*24576;

        float s[8][4];
        #pragma unroll
        for(int t=0;t<8;++t){ s[t][0]=0;s[t][1]=0;s[t][2]=0;s[t][3]=0; }
        #pragma unroll
        for(int k16=0;k16<4;++k16){
            uint32_t bkh[8][2], bkl[8][2];
            #pragma unroll
            for(int n16=0;n16<4;++n16){
                uint32_t off = swz((uint32_t)((n16*16+brow_b)*128 + k16*32 + bchk*16));
                uint32_t r[4];
                ldx4(r, st+off);
                bkh[n16*2][0]=r[0]; bkh[n16*2][1]=r[1]; bkh[n16*2+1][0]=r[2]; bkh[n16*2+1][1]=r[3];
                ldx4(r, st+8192+off);
                bkl[n16*2][0]=r[0]; bkl[n16*2][1]=r[1]; bkl[n16*2+1][0]=r[2]; bkl[n16*2+1][1]=r[3];
            }
            #pragma unroll
            for(int t=0;t<8;++t){
                mma16816(s[t], qh[k16], bkh[t]);
                mma16816(s[t], qh[k16], bkl[t]);
                mma16816(s[t], ql[k16], bkh[t]);
            }
        }
        if(kb >= 2*qt){
            const int row0 = q0 + wid*16 + rloc;
            #pragma unroll
            for(int t=0;t<8;++t){
                int c0 = kb*64 + t*8 + cloc;
                if(c0   > row0  ) s[t][0]=-1e30f;
                if(c0+1 > row0  ) s[t][1]=-1e30f;
                if(c0   > row0+8) s[t][2]=-1e30f;
                if(c0+1 > row0+8) s[t][3]=-1e30f;
            }
        }
        float corr[2];
        #pragma unroll
        for(int rh=0; rh<2; ++rh){
            float mt=-1e30f;
            #pragma unroll
            for(int t=0;t<8;++t) mt = fmaxf(mt, fmaxf(s[t][rh*2], s[t][rh*2+1]));
            mt = fmaxf(mt, __shfl_xor_sync(~0u, mt, 1, 4));
            mt = fmaxf(mt, __shfl_xor_sync(~0u, mt, 2, 4));
            float mn = fmaxf(mstat[rh], mt);
            corr[rh] = __expf(mstat[rh]-mn); mstat[rh]=mn;
            float rs=0.f;
            #pragma unroll
            for(int t=0;t<8;++t){
                float p0=__expf(s[t][rh*2]-mn), p1=__expf(s[t][rh*2+1]-mn);
                s[t][rh*2]=p0; s[t][rh*2+1]=p1; rs += p0+p1;
            }
            rs += __shfl_xor_sync(~0u, rs, 1, 4);
            rs += __shfl_xor_sync(~0u, rs, 2, 4);
            lstat[rh] = lstat[rh]*corr[rh] + rs;
        }
        #pragma unroll
        for(int t=0;t<8;++t){
            O[t][0]*=corr[0]; O[t][1]*=corr[0]; O[t][2]*=corr[1]; O[t][3]*=corr[1];
        }
        // P frags in fp16 (single)
        uint32_t ph[4][4];
        #pragma unroll
        for(int k16=0;k16<4;++k16){
            #pragma unroll
            for(int half=0; half<2; ++half){
                const int t = 2*k16+half;
                ph[k16][half*2]   = packh(s[t][0], s[t][1]);
                ph[k16][half*2+1] = packh(s[t][2], s[t][3]);
            }
        }
        // O += P V, single fp16 pass
        #pragma unroll
        for(int k16=0;k16<4;++k16){
            uint32_t bv[8][2];
            #pragma unroll
            for(int d16=0;d16<4;++d16){
                uint32_t off = swz((uint32_t)((k16*16+vrow_b)*128 + (d16*16+vcol_b)*2));
                uint32_t r[4];
                ldx4t(r, st+16384+off);
                bv[d16*2][0]=r[0]; bv[d16*2][1]=r[1]; bv[d16*2+1][0]=r[2]; bv[d16*2+1][1]=r[3];
            }
            #pragma unroll
            for(int t=0;t<8;++t)
                mma16816h(O[t], ph[k16], bv[t]);
        }
        __syncthreads();
    }

    const int b = bh>>4, h = bh&15;
    #pragma unroll
    for(int rh=0; rh<2; ++rh){
        const float inv = 1.f/lstat[rh];
        const int row = q0 + wid*16 + rloc + rh*8;
        size_t base = (size_t)(b*TT+row)*DIM + h*64;
        #pragma unroll
        for(int t=0;t<8;++t){
            float v0 = O[t][rh*2]*inv, v1 = O[t][rh*2+1]*inv;
            *(uint32_t*)&g_yh[base + t*8 + cloc] = packh(v0, v1);
        }
    }
}

// ---------- router ----------
__global__ void router_kernel(const float* __restrict__ wr){
    const int n=blockIdx.x, tid=threadIdx.x;
    float acc[NEXP];
    #pragma unroll
    for(int e=0;e<NEXP;++e) acc[e]=0.f;
    const float* row=g_h2f+(size_t)n*DIM;
    for(int d=tid;d<DIM;d+=128){
        float hv=row[d];
        #pragma unroll
        for(int e=0;e<NEXP;++e) acc[e]+=hv*wr[d*NEXP+e];
    }
    __shared__ float sm[4][NEXP];
    #pragma unroll
    for(int e=0;e<NEXP;++e){
        float v=acc[e];
        #pragma unroll
        for(int o=16;o;o>>=1) v+=__shfl_xor_sync(~0u,v,o);
        if((tid&31)==0) sm[tid>>5][e]=v;
    }
    __syncthreads();
    if(tid==0){
        float lg[NEXP];
        #pragma unroll
        for(int e=0;e<NEXP;++e) lg[e]=sm[0][e]+sm[1][e]+sm[2][e]+sm[3][e];
        int e0=0;
        #pragma unroll
        for(int e=1;e<NEXP;++e) if(lg[e]>lg[e0]) e0=e;
        int e1=-1;
        #pragma unroll
        for(int e=0;e<NEXP;++e) if(e!=e0 && (e1<0||lg[e]>lg[e1])) e1=e;
        float w0=1.f/(1.f+__expf(lg[e1]-lg[e0])), w1=1.f-w0;
        int p0=atomicAdd(&g_cnt[e0],1);
        g_tok[e0*MAXTOK+p0]=n; g_wt[e0*MAXTOK+p0]=w0; g_slot[e0*MAXTOK+p0]=0;
        int p1=atomicAdd(&g_cnt[e1],1);
        g_tok[e1*MAXTOK+p1]=n; g_wt[e1*MAXTOK+p1]=w1; g_slot[e1*MAXTOK+p1]=1;
    }
}

// ---------- launch ----------
extern "C" void kernel_launch(void* const* d_in, const int* in_sizes, int n_in,
                              void* d_out, int out_size){
    const float* x      =(const float*)d_in[0];
    const float* ln1_g  =(const float*)d_in[1];
    const float* ln1_b  =(const float*)d_in[2];
    const float* w_attn =(const float*)d_in[3];
    const float* w_proj =(const float*)d_in[4];
    const float* ln2_g  =(const float*)d_in[5];
    const float* ln2_b  =(const float*)d_in[6];
    const float* w_rtr  =(const float*)d_in[7];
    const float* w1     =(const float*)d_in[8];
    const float* b1     =(const float*)d_in[9];
    const float* w2     =(const float*)d_in[10];
    const float* b2     =(const float*)d_in[11];
    float* out=(float*)d_out;

    const int SMG = 196608;
    const int SMH = 147456;
    const int SMA = 106496;
    cudaFuncSetAttribute(tgemm0,           cudaFuncAttributeMaxDynamicSharedMemorySize, SMG);
    cudaFuncSetAttribute(hgemm<1,DIM,DIM>, cudaFuncAttributeMaxDynamicSharedMemorySize, SMH);
    cudaFuncSetAttribute(hgemm<2,HID,DIM>, cudaFuncAttributeMaxDynamicSharedMemorySize, SMH);
    cudaFuncSetAttribute(hgemm<3,DIM,HID>, cudaFuncAttributeMaxDynamicSharedMemorySize, SMH);
    cudaFuncSetAttribute(attn_mma,         cudaFuncAttributeMaxDynamicSharedMemorySize, SMA);

    zero_cnt_kernel<<<1,32>>>();
    transpose_split0<<<dim3(96,32,1), dim3(32,8)>>>(w_attn);
    transpose_h<1><<<dim3(32,32,1), dim3(32,8)>>>(w_proj);
    transpose_h<2><<<dim3(128,32,NEXP), dim3(32,8)>>>(w1);
    transpose_h<3><<<dim3(32,128,NEXP), dim3(32,8)>>>(w2);

    ln_kernel<0><<<NTOK,256>>>(x, ln1_g, ln1_b);
    tgemm0<<<dim3(12,32,1),256,SMG>>>();
    attn_mma<<<dim3(TT/128, BB*16),256,SMA>>>();
    hgemm<1,DIM,DIM><<<dim3(4,32,1),256,SMH>>>(x);
    ln_kernel<1><<<NTOK,256>>>(nullptr, ln2_g, ln2_b);
    router_kernel<<<NTOK,128>>>(w_rtr);
    base_kernel<<<1,32>>>();
    hgemm<2,HID,DIM><<<dim3(16,32,NEXP),256,SMH>>>(b1);
    hgemm<3,DIM,HID><<<dim3(4,32,NEXP),256,SMH>>>(b2);
    final_kernel<<<NTOK*DIM/256,256>>>(out);
}

// round 15
// speedup vs baseline: 2.7460x; 1.0911x over previous
#include <cuda_runtime.h>
#include <cuda_bf16.h>
#include <cuda_fp16.h>
#include <math.h>
#include <stdint.h>

#define BB 2
#define TT 2048
#define DIM 1024
#define NTOK 4096
#define NEXP 8
#define HID 4096
#define MAXTOK 4096
typedef __nv_bfloat16 bf16;
typedef __half h16;

// ---------- scratch ----------
__device__ bf16 g_h_hi[NTOK*DIM], g_h_lo[NTOK*DIM];
__device__ bf16 g_q_hi[32*2048*64], g_q_lo[32*2048*64];
__device__ bf16 g_k_hi[32*2048*64], g_k_lo[32*2048*64];
__device__ h16  g_vh[32*2048*64];
__device__ h16  g_yh[NTOK*DIM];
__device__ float g_x1[NTOK*DIM], g_h2f[NTOK*DIM];
__device__ h16  g_h2h[NTOK*DIM];
__device__ h16  g_poolh[(size_t)2*NTOK*HID];
__device__ float g_c0[NTOK*DIM], g_c1[NTOK*DIM];
__device__ int g_cnt[NEXP], g_basei[NEXP], g_tok[NEXP*MAXTOK], g_slot[NEXP*MAXTOK];
__device__ float g_wt[NEXP*MAXTOK];
__device__ bf16 g_waT_hi[(size_t)3*DIM*DIM], g_waT_lo[(size_t)3*DIM*DIM];
__device__ h16  g_wpT_h[(size_t)DIM*DIM];
__device__ h16  g_w1T_h[(size_t)NEXP*HID*DIM];
__device__ h16  g_w2T_h[(size_t)NEXP*DIM*HID];

// ---------- ptx helpers ----------
__device__ __forceinline__ uint32_t s2u(const void* p){
    uint32_t a; asm("{ .reg .u64 t; cvta.to.shared.u64 t, %1; cvt.u32.u64 %0, t; }":"=r"(a):"l"(p)); return a;
}
__device__ __forceinline__ uint32_t swz(uint32_t o){ return o ^ ((o>>3)&0x70); }
__device__ __forceinline__ void cp16(uint32_t d, const void* s, bool v){
    asm volatile("cp.async.cg.shared.global [%0], [%1], 16, %2;"
        ::"r"(d),"l"(__cvta_generic_to_global(s)),"r"(v?16:0));
}
__device__ __forceinline__ void ldx4(uint32_t* r, uint32_t a){
    asm volatile("ldmatrix.sync.aligned.m8n8.x4.shared.b16 {%0,%1,%2,%3},[%4];"
        :"=r"(r[0]),"=r"(r[1]),"=r"(r[2]),"=r"(r[3]):"r"(a));
}
__device__ __forceinline__ void ldx4t(uint32_t* r, uint32_t a){
    asm volatile("ldmatrix.sync.aligned.m8n8.x4.trans.shared.b16 {%0,%1,%2,%3},[%4];"
        :"=r"(r[0]),"=r"(r[1]),"=r"(r[2]),"=r"(r[3]):"r"(a));
}
__device__ __forceinline__ void mma16816(float* d, const uint32_t* a, const uint32_t* b){
    asm volatile("mma.sync.aligned.m16n8k16.row.col.f32.bf16.bf16.f32 "
        "{%0,%1,%2,%3},{%4,%5,%6,%7},{%8,%9},{%0,%1,%2,%3};"
        : "+f"(d[0]),"+f"(d[1]),"+f"(d[2]),"+f"(d[3])
        : "r"(a[0]),"r"(a[1]),"r"(a[2]),"r"(a[3]),"r"(b[0]),"r"(b[1]));
}
__device__ __forceinline__ void mma16816h(float* d, const uint32_t* a, const uint32_t* b){
    asm volatile("mma.sync.aligned.m16n8k16.row.col.f32.f16.f16.f32 "
        "{%0,%1,%2,%3},{%4,%5,%6,%7},{%8,%9},{%0,%1,%2,%3};"
        : "+f"(d[0]),"+f"(d[1]),"+f"(d[2]),"+f"(d[3])
        : "r"(a[0]),"r"(a[1]),"r"(a[2]),"r"(a[3]),"r"(b[0]),"r"(b[1]));
}
__device__ __forceinline__ uint32_t packb(float f0, float f1){
    bf16 b0=__float2bfloat16(f0), b1=__float2bfloat16(f1);
    return (uint32_t)__bfloat16_as_ushort(b0) | ((uint32_t)__bfloat16_as_ushort(b1)<<16);
}
__device__ __forceinline__ uint32_t packh(float f0, float f1){
    __half2 p = __floats2half2_rn(f0, f1);
    return *(uint32_t*)&p;
}
__device__ __forceinline__ uint32_t h2exp2(uint32_t a){
    uint32_t d; asm("ex2.approx.f16x2 %0, %1;" : "=r"(d) : "r"(a)); return d;
}

// ---------- small kernels ----------
__global__ void zero_cnt_kernel(){ if(threadIdx.x<NEXP) g_cnt[threadIdx.x]=0; }
__global__ void base_kernel(){
    if(threadIdx.x==0){ int s=0; for(int e=0;e<NEXP;++e){ g_basei[e]=s; s+=g_cnt[e]; } }
}
__global__ void final_kernel(float* __restrict__ out){
    int i = blockIdx.x*256 + threadIdx.x;
    out[i] = g_x1[i] + g_c0[i] + g_c1[i];
}

// ---------- layernorm ----------
template<int WHICH>
__global__ void ln_kernel(const float* __restrict__ in, const float* __restrict__ gam,
                          const float* __restrict__ bet){
    __shared__ float sx[DIM]; __shared__ float red[8];
    const int n=blockIdx.x, tid=threadIdx.x;
    const float* row = (WHICH==0 ? in : g_x1) + (size_t)n*DIM;
    float4 x4 = ((const float4*)row)[tid];
    ((float4*)sx)[tid] = x4;
    float s = x4.x+x4.y+x4.z+x4.w;
    #pragma unroll
    for(int o=16;o;o>>=1) s += __shfl_xor_sync(~0u,s,o);
    if((tid&31)==0) red[tid>>5]=s;
    __syncthreads();
    float mu = (red[0]+red[1]+red[2]+red[3]+red[4]+red[5]+red[6]+red[7])*(1.f/DIM);
    float sq=0.f;
    #pragma unroll
    for(int p=0;p<4;++p){ float d=sx[tid+p*256]-mu; sq+=d*d; }
    #pragma unroll
    for(int o=16;o;o>>=1) sq += __shfl_xor_sync(~0u,sq,o);
    __syncthreads();
    if((tid&31)==0) red[tid>>5]=sq;
    __syncthreads();
    float var=(red[0]+red[1]+red[2]+red[3]+red[4]+red[5]+red[6]+red[7])*(1.f/DIM);
    float rs = rsqrtf(var+1e-5f);
    #pragma unroll
    for(int p=0;p<4;++p){
        int d=tid+p*256;
        float v = (sx[d]-mu)*rs*gam[d]+bet[d];
        size_t o=(size_t)n*DIM+d;
        if(WHICH==0){
            bf16 h = __float2bfloat16(v);
            g_h_hi[o]=h; g_h_lo[o]=__float2bfloat16(v - __bfloat162float(h));
        } else {
            g_h2f[o]=v;
            g_h2h[o]=__float2half_rn(v);
        }
    }
}

// ---------- w_attn transpose + split to bf16 hi/lo ----------
__global__ void transpose_split0(const float* __restrict__ src){
    constexpr int Kd = DIM, Nd = 3*DIM;
    __shared__ float t[32][33];
    const int n0=blockIdx.x*32, k0=blockIdx.y*32;
    const int tx=threadIdx.x, ty=threadIdx.y;
    for(int i=ty;i<32;i+=8)
        t[i][tx] = src[(size_t)(k0+i)*Nd + n0 + tx];
    __syncthreads();
    const int tid = ty*32+tx;
    const int wq = tid&7, nn = tid>>3;
    float v0=t[wq*4+0][nn], v1=t[wq*4+1][nn], v2=t[wq*4+2][nn], v3=t[wq*4+3][nn];
    bf16 h0=__float2bfloat16(v0), h1=__float2bfloat16(v1);
    bf16 h2=__float2bfloat16(v2), h3=__float2bfloat16(v3);
    size_t o = (size_t)(n0+nn)*Kd + k0 + wq*4;
    uint2 hv, lv;
    hv.x = (uint32_t)__bfloat16_as_ushort(h0) | ((uint32_t)__bfloat16_as_ushort(h1)<<16);
    hv.y = (uint32_t)__bfloat16_as_ushort(h2) | ((uint32_t)__bfloat16_as_ushort(h3)<<16);
    lv.x = packb(v0-__bfloat162float(h0), v1-__bfloat162float(h1));
    lv.y = packb(v2-__bfloat162float(h2), v3-__bfloat162float(h3));
    *(uint2*)&g_waT_hi[o] = hv;
    *(uint2*)&g_waT_lo[o] = lv;
}

// ---------- weight transpose to single fp16: 64(k)x32(n) tiles, 128B-coalesced writes ----------
template<int WHICH>   // 1: w_proj, 2: w1, 3: w2
__global__ void __launch_bounds__(256) transpose_h(const float* __restrict__ src){
    constexpr int Kd = (WHICH==3)?HID:DIM;
    constexpr int Nd = (WHICH==2)?HID:DIM;
    h16* dst = (WHICH==1)? g_wpT_h : ((WHICH==2)? g_w1T_h : g_w2T_h);
    const int e=blockIdx.z;
    src += (size_t)e*Kd*Nd; dst += (size_t)e*(size_t)Nd*Kd;
    __shared__ float t[64][33];
    const int n0=blockIdx.x*32, k0=blockIdx.y*64;
    const int tid=threadIdx.x;
    const int lw = tid>>5, col = tid&31;
    #pragma unroll
    for(int i=0;i<8;++i){
        int k = i*8 + lw;
        t[k][col] = src[(size_t)(k0+k)*Nd + n0 + col];
    }
    __syncthreads();
    const int nn = tid>>3, kc = (tid&7)*8;
    uint4 w;
    w.x = packh(t[kc+0][nn], t[kc+1][nn]);
    w.y = packh(t[kc+2][nn], t[kc+3][nn]);
    w.z = packh(t[kc+4][nn], t[kc+5][nn]);
    w.w = packh(t[kc+6][nn], t[kc+7][nn]);
    *(uint4*)&dst[(size_t)(n0+nn)*Kd + k0 + kc] = w;
}

// ---------- bf16 3-pass QKV GEMM: block 128x256, warp 64x64, K64, 2-stage ----------
__global__ void __launch_bounds__(256,1) tgemm0(){
    constexpr int N = 3*DIM, K = DIM;
    constexpr int NKT = K/64;
    constexpr int STG = 98304;
    extern __shared__ char smem[];
    const uint32_t sb = s2u(smem);
    const int tid = threadIdx.x, lane = tid&31, wid = tid>>5;
    const int wm = wid>>2, wn = wid&3;
    const int m0 = blockIdx.y*128, n0 = blockIdx.x*256;

    const uint32_t d0 = swz((uint32_t)((tid>>3)*128 + (tid&7)*16));
    const bf16 *pah[4], *pal[4];
    #pragma unroll
    for(int i=0;i<4;++i){
        int r = (tid>>3) + i*32;
        pah[i]=g_h_hi+(size_t)(m0+r)*K+(tid&7)*8; pal[i]=g_h_lo+(size_t)(m0+r)*K+(tid&7)*8;
    }
    const bf16 *pb_h = g_waT_hi + (size_t)(n0 + (tid>>3))*K + (tid&7)*8;
    const bf16 *pb_l = g_waT_lo + (size_t)(n0 + (tid>>3))*K + (tid&7)*8;

    float acc[4][8][4];
    #pragma unroll
    for(int a=0;a<4;++a)
        #pragma unroll
        for(int b=0;b<8;++b)
            #pragma unroll
            for(int c=0;c<4;++c) acc[a][b][c]=0.f;

    const int arow = wm*64 + (lane&15), achk = lane>>4;
    const int brow_b = wn*64 + ((lane>>4)&1)*8 + (lane&7), bchk = (lane>>3)&1;

    auto issue = [&](int kt){
        const uint32_t st = sb + (kt&1)*STG;
        const int ko = kt*64;
        #pragma unroll
        for(int i=0;i<4;++i){
            cp16(st+d0+i*4096,        pah[i]+ko, true);
            cp16(st+16384+d0+i*4096,  pal[i]+ko, true);
        }
        #pragma unroll
        for(int i=0;i<8;++i){
            cp16(st+32768+d0+i*4096,  pb_h + (size_t)i*32*K + ko, true);
            cp16(st+65536+d0+i*4096,  pb_l + (size_t)i*32*K + ko, true);
        }
        asm volatile("cp.async.commit_group;":::"memory");
    };

    issue(0);
    for(int kt=0; kt<NKT; ++kt){
        if(kt+1<NKT){ issue(kt+1); asm volatile("cp.async.wait_group 1;":::"memory"); }
        else        { asm volatile("cp.async.wait_group 0;":::"memory"); }
        __syncthreads();
        const uint32_t st = sb + (kt&1)*STG;
        #pragma unroll
        for(int k16=0;k16<4;++k16){
            uint32_t ah[4][4], al[4][4];
            #pragma unroll
            for(int mi=0;mi<4;++mi){
                uint32_t off = swz((uint32_t)((arow+mi*16)*128 + k16*32 + achk*16));
                ldx4(ah[mi], st + off);
                ldx4(al[mi], st + 16384 + off);
            }
            #pragma unroll
            for(int n16=0;n16<4;++n16){
                uint32_t off = swz((uint32_t)((brow_b+n16*16)*128 + k16*32 + bchk*16));
                uint32_t rh[4], rl[4];
                ldx4(rh, st + 32768 + off);
                ldx4(rl, st + 65536 + off);
                #pragma unroll
                for(int mi=0;mi<4;++mi){
                    mma16816(acc[mi][n16*2],   ah[mi], rh);
                    mma16816(acc[mi][n16*2],   ah[mi], rl);
                    mma16816(acc[mi][n16*2],   al[mi], rh);
                    mma16816(acc[mi][n16*2+1], ah[mi], rh+2);
                    mma16816(acc[mi][n16*2+1], ah[mi], rl+2);
                    mma16816(acc[mi][n16*2+1], al[mi], rh+2);
                }
            }
        }
        __syncthreads();
    }

    const int r0 = lane>>2, c2 = (lane&3)*2;
    #pragma unroll
    for(int mi=0;mi<4;++mi){
        #pragma unroll
        for(int half=0; half<2; ++half){
            const int m = m0 + wm*64 + mi*16 + r0 + half*8;
            #pragma unroll
            for(int ni=0;ni<8;++ni){
                const int col = n0 + wn*64 + ni*8 + c2;
                float dd0 = acc[mi][ni][half*2], dd1 = acc[mi][ni][half*2+1];
                const int which = col>>10, r = col&1023, h = r>>6, d = r&63;
                const int b = m>>11, t = m&2047;
                size_t o = ((size_t)(b*16+h)*2048 + t)*64 + d;
                if(which==2){
                    *(uint32_t*)&g_vh[o] = packh(dd0, dd1);
                } else {
                    bf16 *ph, *pl;
                    if(which==0){ dd0*=0.180336887f; dd1*=0.180336887f; ph=g_q_hi; pl=g_q_lo; }  // 0.125*log2e
                    else { ph=g_k_hi; pl=g_k_lo; }
                    bf16 h0=__float2bfloat16(dd0), h1=__float2bfloat16(dd1);
                    *(uint32_t*)&ph[o] = (uint32_t)__bfloat16_as_ushort(h0)
                                       | ((uint32_t)__bfloat16_as_ushort(h1)<<16);
                    *(uint32_t*)&pl[o] = packb(dd0-__bfloat162float(h0), dd1-__bfloat162float(h1));
                }
            }
        }
    }
}

// ---------- single-fp16 GEMM: block 128x256, warp 64x64, K64, 3 stages x 48KB ----------
template<int MODE, int N, int K>
__global__ void __launch_bounds__(256,1) hgemm(const float* __restrict__ aux){
    constexpr int NKT = K/64;
    constexpr int STG = 49152;
    const int e = (MODE>=2)? blockIdx.z : 0;
    int Mrows = NTOK, pbase = 0;
    if(MODE>=2){
        Mrows = g_cnt[e]; pbase = g_basei[e];
        if((int)blockIdx.y*128 >= Mrows) return;
    }
    extern __shared__ char smem[];
    const uint32_t sb = s2u(smem);
    const int tid = threadIdx.x, lane = tid&31, wid = tid>>5;
    const int wm = wid>>2, wn = wid&3;
    const int m0 = blockIdx.y*128, n0 = blockIdx.x*256;

    const h16 *A, *B;
    if(MODE==1){ A=g_yh;    B=g_wpT_h; }
    else if(MODE==2){ A=g_h2h;  B=g_w1T_h+(size_t)e*HID*DIM; }
    else       { A=g_poolh; B=g_w2T_h+(size_t)e*DIM*HID; }

    const uint32_t d0 = swz((uint32_t)((tid>>3)*128 + (tid&7)*16));
    const h16 *pa[4]; bool av[4];
    #pragma unroll
    for(int i=0;i<4;++i){
        int r = (tid>>3) + i*32, gm = m0 + r;
        bool v = gm < Mrows;
        long rg = gm;
        if(MODE==2) rg = v ? g_tok[e*MAXTOK+gm] : 0;
        if(MODE==3) rg = (long)pbase + (v?gm:0);
        pa[i]=A+(size_t)rg*K+(tid&7)*8; av[i]=v;
    }
    const h16 *pb = B + (size_t)(n0 + (tid>>3))*K + (tid&7)*8;

    float acc[4][8][4];
    #pragma unroll
    for(int a=0;a<4;++a)
        #pragma unroll
        for(int b=0;b<8;++b)
            #pragma unroll
            for(int c=0;c<4;++c) acc[a][b][c]=0.f;

    const int arow = wm*64 + (lane&15), achk = lane>>4;
    const int brow_b = wn*64 + ((lane>>4)&1)*8 + (lane&7), bchk = (lane>>3)&1;

    auto issue = [&](int kt){
        const uint32_t st = sb + (kt%3)*STG;
        const int ko = kt*64;
        #pragma unroll
        for(int i=0;i<4;++i)
            cp16(st+d0+i*4096, pa[i]+ko, av[i]);
        #pragma unroll
        for(int i=0;i<8;++i)
            cp16(st+16384+d0+i*4096, pb + (size_t)i*32*K + ko, true);
        asm volatile("cp.async.commit_group;":::"memory");
    };

    issue(0); issue(1);
    for(int kt=0; kt<NKT; ++kt){
        if(kt+1<NKT){ asm volatile("cp.async.wait_group 1;":::"memory"); }
        else        { asm volatile("cp.async.wait_group 0;":::"memory"); }
        __syncthreads();
        if(kt+2<NKT) issue(kt+2);
        const uint32_t st = sb + (kt%3)*STG;
        #pragma unroll
        for(int k16=0;k16<4;++k16){
            uint32_t ah[4][4];
            #pragma unroll
            for(int mi=0;mi<4;++mi){
                uint32_t off = swz((uint32_t)((arow+mi*16)*128 + k16*32 + achk*16));
                ldx4(ah[mi], st + off);
            }
            #pragma unroll
            for(int n16=0;n16<4;++n16){
                uint32_t off = swz((uint32_t)((brow_b+n16*16)*128 + k16*32 + bchk*16));
                uint32_t rb[4];
                ldx4(rb, st + 16384 + off);
                #pragma unroll
                for(int mi=0;mi<4;++mi){
                    mma16816h(acc[mi][n16*2],   ah[mi], rb);
                    mma16816h(acc[mi][n16*2+1], ah[mi], rb+2);
                }
            }
        }
    }

    const int r0 = lane>>2, c2 = (lane&3)*2;
    const float* bias = (MODE>=2) ? (aux + (size_t)e*N) : aux;
    #pragma unroll
    for(int mi=0;mi<4;++mi){
        #pragma unroll
        for(int half=0; half<2; ++half){
            const int m = m0 + wm*64 + mi*16 + r0 + half*8;
            if(MODE>=2 && m>=Mrows) continue;
            int tok=0, slot=0; float wgt=0.f;
            if(MODE==3){ int ix=e*MAXTOK+m; tok=g_tok[ix]; wgt=g_wt[ix]; slot=g_slot[ix]; }
            #pragma unroll
            for(int ni=0;ni<8;++ni){
                const int col = n0 + wn*64 + ni*8 + c2;
                float dd0 = acc[mi][ni][half*2], dd1 = acc[mi][ni][half*2+1];
                if(MODE==1){
                    const float* rx = bias + (size_t)m*N + col;   // x residual
                    float2 w; w.x = rx[0]+dd0; w.y = rx[1]+dd1;
                    *(float2*)&g_x1[(size_t)m*N+col] = w;
                } else if(MODE==2){
                    size_t prow=(size_t)(pbase+m);
                    float v0=dd0+bias[col], v1=dd1+bias[col+1];
                    float gg0=0.5f*v0*(1.f+erff(v0*0.70710678f));
                    float gg1=0.5f*v1*(1.f+erff(v1*0.70710678f));
                    *(uint32_t*)&g_poolh[prow*HID+col] = packh(gg0, gg1);
                } else {
                    float2 w; w.x = wgt*(dd0+bias[col]); w.y = wgt*(dd1+bias[col+1]);
                    *(float2*)&((slot?g_c1:g_c0)[(size_t)tok*DIM+col]) = w;
                }
            }
        }
    }
}

// ---------- flash attention: QK bf16 3-pass (log2 domain), PV fp16, ex2.f16x2 softmax ----------
__global__ void __launch_bounds__(256,1) attn_mma(){
    extern __shared__ char smem[];
    const uint32_t sb = s2u(smem);
    const int tid=threadIdx.x, lane=tid&31, wid=tid>>5;
    const int bh = blockIdx.y;
    const int qt = (gridDim.x-1) - blockIdx.x;
    const int q0 = qt*128;
    const size_t pbase = (size_t)bh*2048*64;

    #pragma unroll
    for(int i=0;i<4;++i){
        int idx=tid+i*256, r=idx>>3, c=idx&7;
        uint32_t off = swz((uint32_t)(r*128+c*16));
        cp16(sb+off,        g_q_hi + pbase + (size_t)(q0+r)*64 + c*8, true);
        cp16(sb+16384+off,  g_q_lo + pbase + (size_t)(q0+r)*64 + c*8, true);
    }
    auto issueKV = [&](int kb){
        const uint32_t st = sb + 32768 + (kb%3)*24576;
        #pragma unroll
        for(int i=0;i<2;++i){
            int idx=tid+i*256, r=idx>>3, c=idx&7;
            uint32_t off = swz((uint32_t)(r*128+c*16));
            size_t src = pbase + (size_t)(kb*64+r)*64 + c*8;
            cp16(st+off,        g_k_hi+src, true);
            cp16(st+8192+off,   g_k_lo+src, true);
            cp16(st+16384+off,  g_vh+src, true);
        }
        asm volatile("cp.async.commit_group;":::"memory");
    };
    const int kbmax = 2*qt+1;
    issueKV(0);
    issueKV(1);

    asm volatile("cp.async.wait_group 1;":::"memory");
    __syncthreads();
    uint32_t qh[4][4], ql[4][4];
    {
        const int qrow = wid*16 + (lane&15), qchk = lane>>4;
        #pragma unroll
        for(int k16=0;k16<4;++k16){
            uint32_t off = swz((uint32_t)(qrow*128 + k16*32 + qchk*16));
            ldx4(qh[k16], sb+off);
            ldx4(ql[k16], sb+16384+off);
        }
    }

    float O[8][4], mstat[2], lstat[2];
    #pragma unroll
    for(int t=0;t<8;++t){ O[t][0]=0;O[t][1]=0;O[t][2]=0;O[t][3]=0; }
    mstat[0]=mstat[1]=-1e30f; lstat[0]=lstat[1]=0.f;

    const int rloc = lane>>2, cloc = (lane&3)*2;
    const int brow_b = ((lane>>4)&1)*8 + (lane&7), bchk = (lane>>3)&1;
    const int vrow_b = ((lane>>3)&1)*8 + (lane&7), vcol_b = ((lane>>4)&1)*8;

    for(int kb=0; kb<=kbmax; ++kb){
        if(kb<kbmax){ asm volatile("cp.async.wait_group 1;":::"memory"); }
        else        { asm volatile("cp.async.wait_group 0;":::"memory"); }
        __syncthreads();
        if(kb+2<=kbmax) issueKV(kb+2);
        const uint32_t st = sb + 32768 + (kb%3)*24576;

        float s[8][4];
        #pragma unroll
        for(int t=0;t<8;++t){ s[t][0]=0;s[t][1]=0;s[t][2]=0;s[t][3]=0; }
        #pragma unroll
        for(int k16=0;k16<4;++k16){
            uint32_t bkh[8][2], bkl[8][2];
            #pragma unroll
            for(int n16=0;n16<4;++n16){
                uint32_t off = swz((uint32_t)((n16*16+brow_b)*128 + k16*32 + bchk*16));
                uint32_t r[4];
                ldx4(r, st+off);
                bkh[n16*2][0]=r[0]; bkh[n16*2][1]=r[1]; bkh[n16*2+1][0]=r[2]; bkh[n16*2+1][1]=r[3];
                ldx4(r, st+8192+off);
                bkl[n16*2][0]=r[0]; bkl[n16*2][1]=r[1]; bkl[n16*2+1][0]=r[2]; bkl[n16*2+1][1]=r[3];
            }
            #pragma unroll
            for(int t=0;t<8;++t){
                mma16816(s[t], qh[k16], bkh[t]);
                mma16816(s[t], qh[k16], bkl[t]);
                mma16816(s[t], ql[k16], bkh[t]);
            }
        }
        if(kb >= 2*qt){
            const int row0 = q0 + wid*16 + rloc;
            #pragma unroll
            for(int t=0;t<8;++t){
                int c0 = kb*64 + t*8 + cloc;
                if(c0   > row0  ) s[t][0]=-30000.f;
                if(c0+1 > row0  ) s[t][1]=-30000.f;
                if(c0   > row0+8) s[t][2]=-30000.f;
                if(c0+1 > row0+8) s[t][3]=-30000.f;
            }
        }
        float corr[2], mn[2];
        #pragma unroll
        for(int rh=0; rh<2; ++rh){
            float mt=-1e30f;
            #pragma unroll
            for(int t=0;t<8;++t) mt = fmaxf(mt, fmaxf(s[t][rh*2], s[t][rh*2+1]));
            mt = fmaxf(mt, __shfl_xor_sync(~0u, mt, 1, 4));
            mt = fmaxf(mt, __shfl_xor_sync(~0u, mt, 2, 4));
            mn[rh] = fmaxf(mstat[rh], mt);
            corr[rh] = exp2f(mstat[rh]-mn[rh]); mstat[rh]=mn[rh];
        }
        uint32_t ph[4][4];
        float rs0=0.f, rs1=0.f;
        #pragma unroll
        for(int k16=0;k16<4;++k16){
            #pragma unroll
            for(int half=0; half<2; ++half){
                const int t = 2*k16+half;
                uint32_t p0 = h2exp2(packh(s[t][0]-mn[0], s[t][1]-mn[0]));
                uint32_t p1 = h2exp2(packh(s[t][2]-mn[1], s[t][3]-mn[1]));
                ph[k16][half*2]   = p0;
                ph[k16][half*2+1] = p1;
                float2 f0 = __half22float2(*(__half2*)&p0);
                float2 f1 = __half22float2(*(__half2*)&p1);
                rs0 += f0.x + f0.y;
                rs1 += f1.x + f1.y;
            }
        }
        rs0 += __shfl_xor_sync(~0u, rs0, 1, 4);
        rs0 += __shfl_xor_sync(~0u, rs0, 2, 4);
        rs1 += __shfl_xor_sync(~0u, rs1, 1, 4);
        rs1 += __shfl_xor_sync(~0u, rs1, 2, 4);
        lstat[0] = lstat[0]*corr[0] + rs0;
        lstat[1] = lstat[1]*corr[1] + rs1;
        #pragma unroll
        for(int t=0;t<8;++t){
            O[t][0]*=corr[0]; O[t][1]*=corr[0]; O[t][2]*=corr[1]; O[t][3]*=corr[1];
        }
        #pragma unroll
        for(int k16=0;k16<4;++k16){
            uint32_t bv[8][2];
            #pragma unroll
            for(int d16=0;d16<4;++d16){
                uint32_t off = swz((uint32_t)((k16*16+vrow_b)*128 + (d16*16+vcol_b)*2));
                uint32_t r[4];
                ldx4t(r, st+16384+off);
                bv[d16*2][0]=r[0]; bv[d16*2][1]=r[1]; bv[d16*2+1][0]=r[2]; bv[d16*2+1][1]=r[3];
            }
            #pragma unroll
            for(int t=0;t<8;++t)
                mma16816h(O[t], ph[k16], bv[t]);
        }
        __syncthreads();
    }

    const int b = bh>>4, h = bh&15;
    #pragma unroll
    for(int rh=0; rh<2; ++rh){
        const float inv = 1.f/lstat[rh];
        const int row = q0 + wid*16 + rloc + rh*8;
        size_t base = (size_t)(b*TT+row)*DIM + h*64;
        #pragma unroll
        for(int t=0;t<8;++t){
            float v0 = O[t][rh*2]*inv, v1 = O[t][rh*2+1]*inv;
            *(uint32_t*)&g_yh[base + t*8 + cloc] = packh(v0, v1);
        }
    }
}

// ---------- router ----------
__global__ void router_kernel(const float* __restrict__ wr){
    const int n=blockIdx.x, tid=threadIdx.x;
    float acc[NEXP];
    #pragma unroll
    for(int e=0;e<NEXP;++e) acc[e]=0.f;
    const float* row=g_h2f+(size_t)n*DIM;
    for(int d=tid;d<DIM;d+=128){
        float hv=row[d];
        #pragma unroll
        for(int e=0;e<NEXP;++e) acc[e]+=hv*wr[d*NEXP+e];
    }
    __shared__ float sm[4][NEXP];
    #pragma unroll
    for(int e=0;e<NEXP;++e){
        float v=acc[e];
        #pragma unroll
        for(int o=16;o;o>>=1) v+=__shfl_xor_sync(~0u,v,o);
        if((tid&31)==0) sm[tid>>5][e]=v;
    }
    __syncthreads();
    if(tid==0){
        float lg[NEXP];
        #pragma unroll
        for(int e=0;e<NEXP;++e) lg[e]=sm[0][e]+sm[1][e]+sm[2][e]+sm[3][e];
        int e0=0;
        #pragma unroll
        for(int e=1;e<NEXP;++e) if(lg[e]>lg[e0]) e0=e;
        int e1=-1;
        #pragma unroll
        for(int e=0;e<NEXP;++e) if(e!=e0 && (e1<0||lg[e]>lg[e1])) e1=e;
        float w0=1.f/(1.f+__expf(lg[e1]-lg[e0])), w1=1.f-w0;
        int p0=atomicAdd(&g_cnt[e0],1);
        g_tok[e0*MAXTOK+p0]=n; g_wt[e0*MAXTOK+p0]=w0; g_slot[e0*MAXTOK+p0]=0;
        int p1=atomicAdd(&g_cnt[e1],1);
        g_tok[e1*MAXTOK+p1]=n; g_wt[e1*MAXTOK+p1]=w1; g_slot[e1*MAXTOK+p1]=1;
    }
}

// ---------- launch ----------
extern "C" void kernel_launch(void* const* d_in, const int* in_sizes, int n_in,
                              void* d_out, int out_size){
    const float* x      =(const float*)d_in[0];
    const float* ln1_g  =(const float*)d_in[1];
    const float* ln1_b  =(const float*)d_in[2];
    const float* w_attn =(const float*)d_in[3];
    const float* w_proj =(const float*)d_in[4];
    const float* ln2_g  =(const float*)d_in[5];
    const float* ln2_b  =(const float*)d_in[6];
    const float* w_rtr  =(const float*)d_in[7];
    const float* w1     =(const float*)d_in[8];
    const float* b1     =(const float*)d_in[9];
    const float* w2     =(const float*)d_in[10];
    const float* b2     =(const float*)d_in[11];
    float* out=(float*)d_out;

    const int SMG = 196608;
    const int SMH = 147456;
    const int SMA = 106496;
    cudaFuncSetAttribute(tgemm0,           cudaFuncAttributeMaxDynamicSharedMemorySize, SMG);
    cudaFuncSetAttribute(hgemm<1,DIM,DIM>, cudaFuncAttributeMaxDynamicSharedMemorySize, SMH);
    cudaFuncSetAttribute(hgemm<2,HID,DIM>, cudaFuncAttributeMaxDynamicSharedMemorySize, SMH);
    cudaFuncSetAttribute(hgemm<3,DIM,HID>, cudaFuncAttributeMaxDynamicSharedMemorySize, SMH);
    cudaFuncSetAttribute(attn_mma,         cudaFuncAttributeMaxDynamicSharedMemorySize, SMA);

    zero_cnt_kernel<<<1,32>>>();
    transpose_split0<<<dim3(96,32,1), dim3(32,8)>>>(w_attn);
    transpose_h<1><<<dim3(32,16,1), 256>>>(w_proj);
    transpose_h<2><<<dim3(128,16,NEXP), 256>>>(w1);
    transpose_h<3><<<dim3(32,64,NEXP), 256>>>(w2);

    ln_kernel<0><<<NTOK,256>>>(x, ln1_g, ln1_b);
    tgemm0<<<dim3(12,32,1),256,SMG>>>();
    attn_mma<<<dim3(TT/128, BB*16),256,SMA>>>();
    hgemm<1,DIM,DIM><<<dim3(4,32,1),256,SMH>>>(x);
    ln_kernel<1><<<NTOK,256>>>(nullptr, ln2_g, ln2_b);
    router_kernel<<<NTOK,128>>>(w_rtr);
    base_kernel<<<1,32>>>();
    hgemm<2,HID,DIM><<<dim3(16,32,NEXP),256,SMH>>>(b1);
    hgemm<3,DIM,HID><<<dim3(4,32,NEXP),256,SMH>>>(b2);
    final_kernel<<<NTOK*DIM/256,256>>>(out);
}

// round 16
// speedup vs baseline: 2.7820x; 1.0131x over previous
#include <cuda_runtime.h>
#include <cuda_bf16.h>
#include <cuda_fp16.h>
#include <math.h>
#include <stdint.h>

#define BB 2
#define TT 2048
#define DIM 1024
#define NTOK 4096
#define NEXP 8
#define HID 4096
#define MAXTOK 4096
typedef __nv_bfloat16 bf16;
typedef __half h16;

// ---------- scratch ----------
__device__ bf16 g_h_hi[NTOK*DIM], g_h_lo[NTOK*DIM];
__device__ bf16 g_q_hi[32*2048*64], g_q_lo[32*2048*64];
__device__ bf16 g_k_hi[32*2048*64], g_k_lo[32*2048*64];
__device__ h16  g_vh[32*2048*64];
__device__ h16  g_yh[NTOK*DIM];
__device__ float g_x1[NTOK*DIM], g_h2f[NTOK*DIM];
__device__ h16  g_h2h[NTOK*DIM];
__device__ h16  g_poolh[(size_t)2*NTOK*HID];
__device__ float g_c0[NTOK*DIM], g_c1[NTOK*DIM];
__device__ int g_cnt[NEXP], g_basei[NEXP], g_tok[NEXP*MAXTOK], g_slot[NEXP*MAXTOK];
__device__ float g_wt[NEXP*MAXTOK];
__device__ bf16 g_waT_hi[(size_t)3*DIM*DIM], g_waT_lo[(size_t)3*DIM*DIM];
__device__ h16  g_wpT_h[(size_t)DIM*DIM];
__device__ h16  g_w1T_h[(size_t)NEXP*HID*DIM];
__device__ h16  g_w2T_h[(size_t)NEXP*DIM*HID];

// ---------- ptx helpers ----------
__device__ __forceinline__ uint32_t s2u(const void* p){
    uint32_t a; asm("{ .reg .u64 t; cvta.to.shared.u64 t, %1; cvt.u32.u64 %0, t; }":"=r"(a):"l"(p)); return a;
}
__device__ __forceinline__ uint32_t swz(uint32_t o){ return o ^ ((o>>3)&0x70); }
__device__ __forceinline__ void cp16(uint32_t d, const void* s, bool v){
    asm volatile("cp.async.cg.shared.global [%0], [%1], 16, %2;"
        ::"r"(d),"l"(__cvta_generic_to_global(s)),"r"(v?16:0));
}
__device__ __forceinline__ void ldx4(uint32_t* r, uint32_t a){
    asm volatile("ldmatrix.sync.aligned.m8n8.x4.shared.b16 {%0,%1,%2,%3},[%4];"
        :"=r"(r[0]),"=r"(r[1]),"=r"(r[2]),"=r"(r[3]):"r"(a));
}
__device__ __forceinline__ void ldx4t(uint32_t* r, uint32_t a){
    asm volatile("ldmatrix.sync.aligned.m8n8.x4.trans.shared.b16 {%0,%1,%2,%3},[%4];"
        :"=r"(r[0]),"=r"(r[1]),"=r"(r[2]),"=r"(r[3]):"r"(a));
}
__device__ __forceinline__ void mma16816(float* d, const uint32_t* a, const uint32_t* b){
    asm volatile("mma.sync.aligned.m16n8k16.row.col.f32.bf16.bf16.f32 "
        "{%0,%1,%2,%3},{%4,%5,%6,%7},{%8,%9},{%0,%1,%2,%3};"
        : "+f"(d[0]),"+f"(d[1]),"+f"(d[2]),"+f"(d[3])
        : "r"(a[0]),"r"(a[1]),"r"(a[2]),"r"(a[3]),"r"(b[0]),"r"(b[1]));
}
__device__ __forceinline__ void mma16816h(float* d, const uint32_t* a, const uint32_t* b){
    asm volatile("mma.sync.aligned.m16n8k16.row.col.f32.f16.f16.f32 "
        "{%0,%1,%2,%3},{%4,%5,%6,%7},{%8,%9},{%0,%1,%2,%3};"
        : "+f"(d[0]),"+f"(d[1]),"+f"(d[2]),"+f"(d[3])
        : "r"(a[0]),"r"(a[1]),"r"(a[2]),"r"(a[3]),"r"(b[0]),"r"(b[1]));
}
__device__ __forceinline__ uint32_t packb(float f0, float f1){
    bf16 b0=__float2bfloat16(f0), b1=__float2bfloat16(f1);
    return (uint32_t)__bfloat16_as_ushort(b0) | ((uint32_t)__bfloat16_as_ushort(b1)<<16);
}
__device__ __forceinline__ uint32_t packh(float f0, float f1){
    __half2 p = __floats2half2_rn(f0, f1);
    return *(uint32_t*)&p;
}
__device__ __forceinline__ uint32_t h2exp2(uint32_t a){
    uint32_t d; asm("ex2.approx.f16x2 %0, %1;" : "=r"(d) : "r"(a)); return d;
}

// ---------- small kernels ----------
__global__ void zero_cnt_kernel(){ if(threadIdx.x<NEXP) g_cnt[threadIdx.x]=0; }
__global__ void base_kernel(){
    if(threadIdx.x==0){ int s=0; for(int e=0;e<NEXP;++e){ g_basei[e]=s; s+=g_cnt[e]; } }
}
__global__ void final_kernel(float* __restrict__ out){
    int i = blockIdx.x*256 + threadIdx.x;
    float4 a = ((const float4*)g_x1)[i];
    float4 b = ((const float4*)g_c0)[i];
    float4 c = ((const float4*)g_c1)[i];
    ((float4*)out)[i] = make_float4(a.x+b.x+c.x, a.y+b.y+c.y, a.z+b.z+c.z, a.w+b.w+c.w);
}

// ---------- layernorm ----------
template<int WHICH>
__global__ void ln_kernel(const float* __restrict__ in, const float* __restrict__ gam,
                          const float* __restrict__ bet){
    __shared__ float sx[DIM]; __shared__ float red[8];
    const int n=blockIdx.x, tid=threadIdx.x;
    const float* row = (WHICH==0 ? in : g_x1) + (size_t)n*DIM;
    float4 x4 = ((const float4*)row)[tid];
    ((float4*)sx)[tid] = x4;
    float s = x4.x+x4.y+x4.z+x4.w;
    #pragma unroll
    for(int o=16;o;o>>=1) s += __shfl_xor_sync(~0u,s,o);
    if((tid&31)==0) red[tid>>5]=s;
    __syncthreads();
    float mu = (red[0]+red[1]+red[2]+red[3]+red[4]+red[5]+red[6]+red[7])*(1.f/DIM);
    float sq=0.f;
    #pragma unroll
    for(int p=0;p<4;++p){ float d=sx[tid+p*256]-mu; sq+=d*d; }
    #pragma unroll
    for(int o=16;o;o>>=1) sq += __shfl_xor_sync(~0u,sq,o);
    __syncthreads();
    if((tid&31)==0) red[tid>>5]=sq;
    __syncthreads();
    float var=(red[0]+red[1]+red[2]+red[3]+red[4]+red[5]+red[6]+red[7])*(1.f/DIM);
    float rs = rsqrtf(var+1e-5f);
    #pragma unroll
    for(int p=0;p<4;++p){
        int d=tid+p*256;
        float v = (sx[d]-mu)*rs*gam[d]+bet[d];
        size_t o=(size_t)n*DIM+d;
        if(WHICH==0){
            bf16 h = __float2bfloat16(v);
            g_h_hi[o]=h; g_h_lo[o]=__float2bfloat16(v - __bfloat162float(h));
        } else {
            g_h2f[o]=v;
            g_h2h[o]=__float2half_rn(v);
        }
    }
}

// ---------- w_attn transpose + split to bf16 hi/lo: 64(k)x32(n), coalesced uint4 writes ----------
__global__ void __launch_bounds__(256) transpose_split0(const float* __restrict__ src){
    constexpr int Kd = DIM, Nd = 3*DIM;
    __shared__ float t[64][33];
    const int n0=blockIdx.x*32, k0=blockIdx.y*64;
    const int tid=threadIdx.x;
    const int lw = tid>>5, col = tid&31;
    #pragma unroll
    for(int i=0;i<8;++i){
        int k = i*8 + lw;
        t[k][col] = src[(size_t)(k0+k)*Nd + n0 + col];
    }
    __syncthreads();
    const int nn = tid>>3, kc = (tid&7)*8;
    uint4 hv, lv;
    uint32_t* hw = (uint32_t*)&hv;
    uint32_t* lw2 = (uint32_t*)&lv;
    #pragma unroll
    for(int j=0;j<4;++j){
        float a = t[kc+2*j][nn], b = t[kc+2*j+1][nn];
        bf16 ha=__float2bfloat16(a), hb=__float2bfloat16(b);
        hw[j] = (uint32_t)__bfloat16_as_ushort(ha) | ((uint32_t)__bfloat16_as_ushort(hb)<<16);
        lw2[j] = packb(a-__bfloat162float(ha), b-__bfloat162float(hb));
    }
    size_t o = (size_t)(n0+nn)*Kd + k0 + kc;
    *(uint4*)&g_waT_hi[o] = hv;
    *(uint4*)&g_waT_lo[o] = lv;
}

// ---------- weight transpose to single fp16: 64(k)x32(n) tiles, coalesced ----------
template<int WHICH>   // 1: w_proj, 2: w1, 3: w2
__global__ void __launch_bounds__(256) transpose_h(const float* __restrict__ src){
    constexpr int Kd = (WHICH==3)?HID:DIM;
    constexpr int Nd = (WHICH==2)?HID:DIM;
    h16* dst = (WHICH==1)? g_wpT_h : ((WHICH==2)? g_w1T_h : g_w2T_h);
    const int e=blockIdx.z;
    src += (size_t)e*Kd*Nd; dst += (size_t)e*(size_t)Nd*Kd;
    __shared__ float t[64][33];
    const int n0=blockIdx.x*32, k0=blockIdx.y*64;
    const int tid=threadIdx.x;
    const int lw = tid>>5, col = tid&31;
    #pragma unroll
    for(int i=0;i<8;++i){
        int k = i*8 + lw;
        t[k][col] = src[(size_t)(k0+k)*Nd + n0 + col];
    }
    __syncthreads();
    const int nn = tid>>3, kc = (tid&7)*8;
    uint4 w;
    w.x = packh(t[kc+0][nn], t[kc+1][nn]);
    w.y = packh(t[kc+2][nn], t[kc+3][nn]);
    w.z = packh(t[kc+4][nn], t[kc+5][nn]);
    w.w = packh(t[kc+6][nn], t[kc+7][nn]);
    *(uint4*)&dst[(size_t)(n0+nn)*Kd + k0 + kc] = w;
}

// ---------- bf16 3-pass QKV GEMM: block 128x256, warp 64x64, K64, 2-stage, single sync ----------
__global__ void __launch_bounds__(256,1) tgemm0(){
    constexpr int N = 3*DIM, K = DIM;
    constexpr int NKT = K/64;
    constexpr int STG = 98304;
    extern __shared__ char smem[];
    const uint32_t sb = s2u(smem);
    const int tid = threadIdx.x, lane = tid&31, wid = tid>>5;
    const int wm = wid>>2, wn = wid&3;
    const int m0 = blockIdx.y*128, n0 = blockIdx.x*256;

    const uint32_t d0 = swz((uint32_t)((tid>>3)*128 + (tid&7)*16));
    const bf16 *pah[4], *pal[4];
    #pragma unroll
    for(int i=0;i<4;++i){
        int r = (tid>>3) + i*32;
        pah[i]=g_h_hi+(size_t)(m0+r)*K+(tid&7)*8; pal[i]=g_h_lo+(size_t)(m0+r)*K+(tid&7)*8;
    }
    const bf16 *pb_h = g_waT_hi + (size_t)(n0 + (tid>>3))*K + (tid&7)*8;
    const bf16 *pb_l = g_waT_lo + (size_t)(n0 + (tid>>3))*K + (tid&7)*8;

    float acc[4][8][4];
    #pragma unroll
    for(int a=0;a<4;++a)
        #pragma unroll
        for(int b=0;b<8;++b)
            #pragma unroll
            for(int c=0;c<4;++c) acc[a][b][c]=0.f;

    const int arow = wm*64 + (lane&15), achk = lane>>4;
    const int brow_b = wn*64 + ((lane>>4)&1)*8 + (lane&7), bchk = (lane>>3)&1;

    auto issue = [&](int kt){
        const uint32_t st = sb + (kt&1)*STG;
        const int ko = kt*64;
        #pragma unroll
        for(int i=0;i<4;++i){
            cp16(st+d0+i*4096,        pah[i]+ko, true);
            cp16(st+16384+d0+i*4096,  pal[i]+ko, true);
        }
        #pragma unroll
        for(int i=0;i<8;++i){
            cp16(st+32768+d0+i*4096,  pb_h + (size_t)i*32*K + ko, true);
            cp16(st+65536+d0+i*4096,  pb_l + (size_t)i*32*K + ko, true);
        }
        asm volatile("cp.async.commit_group;":::"memory");
    };

    issue(0);
    for(int kt=0; kt<NKT; ++kt){
        asm volatile("cp.async.wait_group 0;":::"memory");
        __syncthreads();
        if(kt+1<NKT) issue(kt+1);   // writes other stage: fully consumed at iter kt-1, proven by sync
        const uint32_t st = sb + (kt&1)*STG;
        #pragma unroll
        for(int k16=0;k16<4;++k16){
            uint32_t ah[4][4], al[4][4];
            #pragma unroll
            for(int mi=0;mi<4;++mi){
                uint32_t off = swz((uint32_t)((arow+mi*16)*128 + k16*32 + achk*16));
                ldx4(ah[mi], st + off);
                ldx4(al[mi], st + 16384 + off);
            }
            #pragma unroll
            for(int n16=0;n16<4;++n16){
                uint32_t off = swz((uint32_t)((brow_b+n16*16)*128 + k16*32 + bchk*16));
                uint32_t rh[4], rl[4];
                ldx4(rh, st + 32768 + off);
                ldx4(rl, st + 65536 + off);
                #pragma unroll
                for(int mi=0;mi<4;++mi){
                    mma16816(acc[mi][n16*2],   ah[mi], rh);
                    mma16816(acc[mi][n16*2],   ah[mi], rl);
                    mma16816(acc[mi][n16*2],   al[mi], rh);
                    mma16816(acc[mi][n16*2+1], ah[mi], rh+2);
                    mma16816(acc[mi][n16*2+1], ah[mi], rl+2);
                    mma16816(acc[mi][n16*2+1], al[mi], rh+2);
                }
            }
        }
    }

    const int r0 = lane>>2, c2 = (lane&3)*2;
    #pragma unroll
    for(int mi=0;mi<4;++mi){
        #pragma unroll
        for(int half=0; half<2; ++half){
            const int m = m0 + wm*64 + mi*16 + r0 + half*8;
            #pragma unroll
            for(int ni=0;ni<8;++ni){
                const int col = n0 + wn*64 + ni*8 + c2;
                float dd0 = acc[mi][ni][half*2], dd1 = acc[mi][ni][half*2+1];
                const int which = col>>10, r = col&1023, h = r>>6, d = r&63;
                const int b = m>>11, t = m&2047;
                size_t o = ((size_t)(b*16+h)*2048 + t)*64 + d;
                if(which==2){
                    *(uint32_t*)&g_vh[o] = packh(dd0, dd1);
                } else {
                    bf16 *ph, *pl;
                    if(which==0){ dd0*=0.180336887f; dd1*=0.180336887f; ph=g_q_hi; pl=g_q_lo; }  // 0.125*log2e
                    else { ph=g_k_hi; pl=g_k_lo; }
                    bf16 h0=__float2bfloat16(dd0), h1=__float2bfloat16(dd1);
                    *(uint32_t*)&ph[o] = (uint32_t)__bfloat16_as_ushort(h0)
                                       | ((uint32_t)__bfloat16_as_ushort(h1)<<16);
                    *(uint32_t*)&pl[o] = packb(dd0-__bfloat162float(h0), dd1-__bfloat162float(h1));
                }
            }
        }
    }
}

// ---------- single-fp16 GEMM: block 128x256, warp 64x64, K64, 3 stages x 48KB ----------
template<int MODE, int N, int K>
__global__ void __launch_bounds__(256,1) hgemm(const float* __restrict__ aux){
    constexpr int NKT = K/64;
    constexpr int STG = 49152;
    const int e = (MODE>=2)? blockIdx.z : 0;
    int Mrows = NTOK, pbase = 0;
    if(MODE>=2){
        Mrows = g_cnt[e]; pbase = g_basei[e];
        if((int)blockIdx.y*128 >= Mrows) return;
    }
    extern __shared__ char smem[];
    const uint32_t sb = s2u(smem);
    const int tid = threadIdx.x, lane = tid&31, wid = tid>>5;
    const int wm = wid>>2, wn = wid&3;
    const int m0 = blockIdx.y*128, n0 = blockIdx.x*256;

    const h16 *A, *B;
    if(MODE==1){ A=g_yh;    B=g_wpT_h; }
    else if(MODE==2){ A=g_h2h;  B=g_w1T_h+(size_t)e*HID*DIM; }
    else       { A=g_poolh; B=g_w2T_h+(size_t)e*DIM*HID; }

    const uint32_t d0 = swz((uint32_t)((tid>>3)*128 + (tid&7)*16));
    const h16 *pa[4]; bool av[4];
    #pragma unroll
    for(int i=0;i<4;++i){
        int r = (tid>>3) + i*32, gm = m0 + r;
        bool v = gm < Mrows;
        long rg = gm;
        if(MODE==2) rg = v ? g_tok[e*MAXTOK+gm] : 0;
        if(MODE==3) rg = (long)pbase + (v?gm:0);
        pa[i]=A+(size_t)rg*K+(tid&7)*8; av[i]=v;
    }
    const h16 *pb = B + (size_t)(n0 + (tid>>3))*K + (tid&7)*8;

    float acc[4][8][4];
    #pragma unroll
    for(int a=0;a<4;++a)
        #pragma unroll
        for(int b=0;b<8;++b)
            #pragma unroll
            for(int c=0;c<4;++c) acc[a][b][c]=0.f;

    const int arow = wm*64 + (lane&15), achk = lane>>4;
    const int brow_b = wn*64 + ((lane>>4)&1)*8 + (lane&7), bchk = (lane>>3)&1;

    auto issue = [&](int kt){
        const uint32_t st = sb + (kt%3)*STG;
        const int ko = kt*64;
        #pragma unroll
        for(int i=0;i<4;++i)
            cp16(st+d0+i*4096, pa[i]+ko, av[i]);
        #pragma unroll
        for(int i=0;i<8;++i)
            cp16(st+16384+d0+i*4096, pb + (size_t)i*32*K + ko, true);
        asm volatile("cp.async.commit_group;":::"memory");
    };

    issue(0); issue(1);
    for(int kt=0; kt<NKT; ++kt){
        if(kt+1<NKT){ asm volatile("cp.async.wait_group 1;":::"memory"); }
        else        { asm volatile("cp.async.wait_group 0;":::"memory"); }
        __syncthreads();
        if(kt+2<NKT) issue(kt+2);
        const uint32_t st = sb + (kt%3)*STG;
        #pragma unroll
        for(int k16=0;k16<4;++k16){
            uint32_t ah[4][4];
            #pragma unroll
            for(int mi=0;mi<4;++mi){
                uint32_t off = swz((uint32_t)((arow+mi*16)*128 + k16*32 + achk*16));
                ldx4(ah[mi], st + off);
            }
            #pragma unroll
            for(int n16=0;n16<4;++n16){
                uint32_t off = swz((uint32_t)((brow_b+n16*16)*128 + k16*32 + bchk*16));
                uint32_t rb[4];
                ldx4(rb, st + 16384 + off);
                #pragma unroll
                for(int mi=0;mi<4;++mi){
                    mma16816h(acc[mi][n16*2],   ah[mi], rb);
                    mma16816h(acc[mi][n16*2+1], ah[mi], rb+2);
                }
            }
        }
    }

    const int r0 = lane>>2, c2 = (lane&3)*2;
    const float* bias = (MODE>=2) ? (aux + (size_t)e*N) : aux;
    #pragma unroll
    for(int mi=0;mi<4;++mi){
        #pragma unroll
        for(int half=0; half<2; ++half){
            const int m = m0 + wm*64 + mi*16 + r0 + half*8;
            if(MODE>=2 && m>=Mrows) continue;
            int tok=0, slot=0; float wgt=0.f;
            if(MODE==3){ int ix=e*MAXTOK+m; tok=g_tok[ix]; wgt=g_wt[ix]; slot=g_slot[ix]; }
            #pragma unroll
            for(int ni=0;ni<8;++ni){
                const int col = n0 + wn*64 + ni*8 + c2;
                float dd0 = acc[mi][ni][half*2], dd1 = acc[mi][ni][half*2+1];
                if(MODE==1){
                    const float* rx = bias + (size_t)m*N + col;   // x residual
                    float2 w; w.x = rx[0]+dd0; w.y = rx[1]+dd1;
                    *(float2*)&g_x1[(size_t)m*N+col] = w;
                } else if(MODE==2){
                    size_t prow=(size_t)(pbase+m);
                    float v0=dd0+bias[col], v1=dd1+bias[col+1];
                    float gg0=0.5f*v0*(1.f+erff(v0*0.70710678f));
                    float gg1=0.5f*v1*(1.f+erff(v1*0.70710678f));
                    *(uint32_t*)&g_poolh[prow*HID+col] = packh(gg0, gg1);
                } else {
                    float2 w; w.x = wgt*(dd0+bias[col]); w.y = wgt*(dd1+bias[col+1]);
                    *(float2*)&((slot?g_c1:g_c0)[(size_t)tok*DIM+col]) = w;
                }
            }
        }
    }
}

// ---------- flash attention: QK bf16 3-pass (log2 domain), PV fp16, ex2.f16x2 softmax ----------
__global__ void __launch_bounds__(256,1) attn_mma(){
    extern __shared__ char smem[];
    const uint32_t sb = s2u(smem);
    const int tid=threadIdx.x, lane=tid&31, wid=tid>>5;
    const int bh = blockIdx.y;
    const int qt = (gridDim.x-1) - blockIdx.x;
    const int q0 = qt*128;
    const size_t pbase = (size_t)bh*2048*64;

    #pragma unroll
    for(int i=0;i<4;++i){
        int idx=tid+i*256, r=idx>>3, c=idx&7;
        uint32_t off = swz((uint32_t)(r*128+c*16));
        cp16(sb+off,        g_q_hi + pbase + (size_t)(q0+r)*64 + c*8, true);
        cp16(sb+16384+off,  g_q_lo + pbase + (size_t)(q0+r)*64 + c*8, true);
    }
    auto issueKV = [&](int kb){
        const uint32_t st = sb + 32768 + (kb%3)*24576;
        #pragma unroll
        for(int i=0;i<2;++i){
            int idx=tid+i*256, r=idx>>3, c=idx&7;
            uint32_t off = swz((uint32_t)(r*128+c*16));
            size_t src = pbase + (size_t)(kb*64+r)*64 + c*8;
            cp16(st+off,        g_k_hi+src, true);
            cp16(st+8192+off,   g_k_lo+src, true);
            cp16(st+16384+off,  g_vh+src, true);
        }
        asm volatile("cp.async.commit_group;":::"memory");
    };
    const int kbmax = 2*qt+1;
    issueKV(0);
    issueKV(1);

    asm volatile("cp.async.wait_group 1;":::"memory");
    __syncthreads();
    uint32_t qh[4][4], ql[4][4];
    {
        const int qrow = wid*16 + (lane&15), qchk = lane>>4;
        #pragma unroll
        for(int k16=0;k16<4;++k16){
            uint32_t off = swz((uint32_t)(qrow*128 + k16*32 + qchk*16));
            ldx4(qh[k16], sb+off);
            ldx4(ql[k16], sb+16384+off);
        }
    }

    float O[8][4], mstat[2], lstat[2];
    #pragma unroll
    for(int t=0;t<8;++t){ O[t][0]=0;O[t][1]=0;O[t][2]=0;O[t][3]=0; }
    mstat[0]=mstat[1]=-1e30f; lstat[0]=lstat[1]=0.f;

    const int rloc = lane>>2, cloc = (lane&3)*2;
    const int brow_b = ((lane>>4)&1)*8 + (lane&7), bchk = (lane>>3)&1;
    const int vrow_b = ((lane>>3)&1)*8 + (lane&7), vcol_b = ((lane>>4)&1)*8;

    for(int kb=0; kb<=kbmax; ++kb){
        if(kb<kbmax){ asm volatile("cp.async.wait_group 1;":::"memory"); }
        else        { asm volatile("cp.async.wait_group 0;":::"memory"); }
        __syncthreads();
        if(kb+2<=kbmax) issueKV(kb+2);
        const uint32_t st = sb + 32768 + (kb%3)*24576;

        float s[8][4];
        #pragma unroll
        for(int t=0;t<8;++t){ s[t][0]=0;s[t][1]=0;s[t][2]=0;s[t][3]=0; }
        #pragma unroll
        for(int k16=0;k16<4;++k16){
            uint32_t bkh[8][2], bkl[8][2];
            #pragma unroll
            for(int n16=0;n16<4;++n16){
                uint32_t off = swz((uint32_t)((n16*16+brow_b)*128 + k16*32 + bchk*16));
                uint32_t r[4];
                ldx4(r, st+off);
                bkh[n16*2][0]=r[0]; bkh[n16*2][1]=r[1]; bkh[n16*2+1][0]=r[2]; bkh[n16*2+1][1]=r[3];
                ldx4(r, st+8192+off);
                bkl[n16*2][0]=r[0]; bkl[n16*2][1]=r[1]; bkl[n16*2+1][0]=r[2]; bkl[n16*2+1][1]=r[3];
            }
            #pragma unroll
            for(int t=0;t<8;++t){
                mma16816(s[t], qh[k16], bkh[t]);
                mma16816(s[t], qh[k16], bkl[t]);
                mma16816(s[t], ql[k16], bkh[t]);
            }
        }
        if(kb >= 2*qt){
            const int row0 = q0 + wid*16 + rloc;
            #pragma unroll
            for(int t=0;t<8;++t){
                int c0 = kb*64 + t*8 + cloc;
                if(c0   > row0  ) s[t][0]=-30000.f;
                if(c0+1 > row0  ) s[t][1]=-30000.f;
                if(c0   > row0+8) s[t][2]=-30000.f;
                if(c0+1 > row0+8) s[t][3]=-30000.f;
            }
        }
        float corr[2], mn[2];
        #pragma unroll
        for(int rh=0; rh<2; ++rh){
            float mt=-1e30f;
            #pragma unroll
            for(int t=0;t<8;++t) mt = fmaxf(mt, fmaxf(s[t][rh*2], s[t][rh*2+1]));
            mt = fmaxf(mt, __shfl_xor_sync(~0u, mt, 1, 4));
            mt = fmaxf(mt, __shfl_xor_sync(~0u, mt, 2, 4));
            mn[rh] = fmaxf(mstat[rh], mt);
            corr[rh] = exp2f(mstat[rh]-mn[rh]); mstat[rh]=mn[rh];
        }
        uint32_t ph[4][4];
        float rs0=0.f, rs1=0.f;
        #pragma unroll
        for(int k16=0;k16<4;++k16){
            #pragma unroll
            for(int half=0; half<2; ++half){
                const int t = 2*k16+half;
                uint32_t p0 = h2exp2(packh(s[t][0]-mn[0], s[t][1]-mn[0]));
                uint32_t p1 = h2exp2(packh(s[t][2]-mn[1], s[t][3]-mn[1]));
                ph[k16][half*2]   = p0;
                ph[k16][half*2+1] = p1;
                float2 f0 = __half22float2(*(__half2*)&p0);
                float2 f1 = __half22float2(*(__half2*)&p1);
                rs0 += f0.x + f0.y;
                rs1 += f1.x + f1.y;
            }
        }
        rs0 += __shfl_xor_sync(~0u, rs0, 1, 4);
        rs0 += __shfl_xor_sync(~0u, rs0, 2, 4);
        rs1 += __shfl_xor_sync(~0u, rs1, 1, 4);
        rs1 += __shfl_xor_sync(~0u, rs1, 2, 4);
        lstat[0] = lstat[0]*corr[0] + rs0;
        lstat[1] = lstat[1]*corr[1] + rs1;
        #pragma unroll
        for(int t=0;t<8;++t){
            O[t][0]*=corr[0]; O[t][1]*=corr[0]; O[t][2]*=corr[1]; O[t][3]*=corr[1];
        }
        #pragma unroll
        for(int k16=0;k16<4;++k16){
            uint32_t bv[8][2];
            #pragma unroll
            for(int d16=0;d16<4;++d16){
                uint32_t off = swz((uint32_t)((k16*16+vrow_b)*128 + (d16*16+vcol_b)*2));
                uint32_t r[4];
                ldx4t(r, st+16384+off);
                bv[d16*2][0]=r[0]; bv[d16*2][1]=r[1]; bv[d16*2+1][0]=r[2]; bv[d16*2+1][1]=r[3];
            }
            #pragma unroll
            for(int t=0;t<8;++t)
                mma16816h(O[t], ph[k16], bv[t]);
        }
        __syncthreads();
    }

    const int b = bh>>4, h = bh&15;
    #pragma unroll
    for(int rh=0; rh<2; ++rh){
        const float inv = 1.f/lstat[rh];
        const int row = q0 + wid*16 + rloc + rh*8;
        size_t base = (size_t)(b*TT+row)*DIM + h*64;
        #pragma unroll
        for(int t=0;t<8;++t){
            float v0 = O[t][rh*2]*inv, v1 = O[t][rh*2+1]*inv;
            *(uint32_t*)&g_yh[base + t*8 + cloc] = packh(v0, v1);
        }
    }
}

// ---------- router ----------
__global__ void router_kernel(const float* __restrict__ wr){
    const int n=blockIdx.x, tid=threadIdx.x;
    float acc[NEXP];
    #pragma unroll
    for(int e=0;e<NEXP;++e) acc[e]=0.f;
    const float* row=g_h2f+(size_t)n*DIM;
    for(int d=tid;d<DIM;d+=128){
        float hv=row[d];
        #pragma unroll
        for(int e=0;e<NEXP;++e) acc[e]+=hv*wr[d*NEXP+e];
    }
    __shared__ float sm[4][NEXP];
    #pragma unroll
    for(int e=0;e<NEXP;++e){
        float v=acc[e];
        #pragma unroll
        for(int o=16;o;o>>=1) v+=__shfl_xor_sync(~0u,v,o);
        if((tid&31)==0) sm[tid>>5][e]=v;
    }
    __syncthreads();
    if(tid==0){
        float lg[NEXP];
        #pragma unroll
        for(int e=0;e<NEXP;++e) lg[e]=sm[0][e]+sm[1][e]+sm[2][e]+sm[3][e];
        int e0=0;
        #pragma unroll
        for(int e=1;e<NEXP;++e) if(lg[e]>lg[e0]) e0=e;
        int e1=-1;
        #pragma unroll
        for(int e=0;e<NEXP;++e) if(e!=e0 && (e1<0||lg[e]>lg[e1])) e1=e;
        float w0=1.f/(1.f+__expf(lg[e1]-lg[e0])), w1=1.f-w0;
        int p0=atomicAdd(&g_cnt[e0],1);
        g_tok[e0*MAXTOK+p0]=n; g_wt[e0*MAXTOK+p0]=w0; g_slot[e0*MAXTOK+p0]=0;
        int p1=atomicAdd(&g_cnt[e1],1);
        g_tok[e1*MAXTOK+p1]=n; g_wt[e1*MAXTOK+p1]=w1; g_slot[e1*MAXTOK+p1]=1;
    }
}

// ---------- launch ----------
extern "C" void kernel_launch(void* const* d_in, const int* in_sizes, int n_in,
                              void* d_out, int out_size){
    const float* x      =(const float*)d_in[0];
    const float* ln1_g  =(const float*)d_in[1];
    const float* ln1_b  =(const float*)d_in[2];
    const float* w_attn =(const float*)d_in[3];
    const float* w_proj =(const float*)d_in[4];
    const float* ln2_g  =(const float*)d_in[5];
    const float* ln2_b  =(const float*)d_in[6];
    const float* w_rtr  =(const float*)d_in[7];
    const float* w1     =(const float*)d_in[8];
    const float* b1     =(const float*)d_in[9];
    const float* w2     =(const float*)d_in[10];
    const float* b2     =(const float*)d_in[11];
    float* out=(float*)d_out;

    const int SMG = 196608;
    const int SMH = 147456;
    const int SMA = 106496;
    cudaFuncSetAttribute(tgemm0,           cudaFuncAttributeMaxDynamicSharedMemorySize, SMG);
    cudaFuncSetAttribute(hgemm<1,DIM,DIM>, cudaFuncAttributeMaxDynamicSharedMemorySize, SMH);
    cudaFuncSetAttribute(hgemm<2,HID,DIM>, cudaFuncAttributeMaxDynamicSharedMemorySize, SMH);
    cudaFuncSetAttribute(hgemm<3,DIM,HID>, cudaFuncAttributeMaxDynamicSharedMemorySize, SMH);
    cudaFuncSetAttribute(attn_mma,         cudaFuncAttributeMaxDynamicSharedMemorySize, SMA);

    zero_cnt_kernel<<<1,32>>>();
    transpose_split0<<<dim3(96,16,1), 256>>>(w_attn);
    transpose_h<1><<<dim3(32,16,1), 256>>>(w_proj);
    transpose_h<2><<<dim3(128,16,NEXP), 256>>>(w1);
    transpose_h<3><<<dim3(32,64,NEXP), 256>>>(w2);

    ln_kernel<0><<<NTOK,256>>>(x, ln1_g, ln1_b);
    tgemm0<<<dim3(12,32,1),256,SMG>>>();
    attn_mma<<<dim3(TT/128, BB*16),256,SMA>>>();
    hgemm<1,DIM,DIM><<<dim3(4,32,1),256,SMH>>>(x);
    ln_kernel<1><<<NTOK,256>>>(nullptr, ln2_g, ln2_b);
    router_kernel<<<NTOK,128>>>(w_rtr);
    base_kernel<<<1,32>>>();
    hgemm<2,HID,DIM><<<dim3(16,32,NEXP),256,SMH>>>(b1);
    hgemm<3,DIM,HID><<<dim3(4,32,NEXP),256,SMH>>>(b2);
    final_kernel<<<NTOK*DIM/1024,256>>>(out);
}

// round 17
// speedup vs baseline: 3.0706x; 1.1037x over previous
#include <cuda_runtime.h>
#include <cuda_fp16.h>
#include <math.h>
#include <stdint.h>

#define BB 2
#define TT 2048
#define DIM 1024
#define NTOK 4096
#define NEXP 8
#define HID 4096
#define MAXTOK 4096
typedef __half h16;

// ---------- scratch ----------
__device__ h16  g_h_hi[NTOK*DIM], g_h_lo[NTOK*DIM];
__device__ h16  g_q_hi[32*2048*64], g_q_lo[32*2048*64];
__device__ h16  g_kh[32*2048*64];
__device__ h16  g_vh[32*2048*64];
__device__ h16  g_yh[NTOK*DIM];
__device__ float g_x1[NTOK*DIM], g_h2f[NTOK*DIM];
__device__ h16  g_h2h[NTOK*DIM];
__device__ h16  g_poolh[(size_t)2*NTOK*HID];
__device__ float g_c0[NTOK*DIM], g_c1[NTOK*DIM];
__device__ int g_cnt[NEXP], g_basei[NEXP], g_tok[NEXP*MAXTOK], g_slot[NEXP*MAXTOK];
__device__ float g_wt[NEXP*MAXTOK];
__device__ h16  g_waT_h[(size_t)3*DIM*DIM];
__device__ h16  g_wpT_h[(size_t)DIM*DIM];
__device__ h16  g_w1T_h[(size_t)NEXP*HID*DIM];
__device__ h16  g_w2T_h[(size_t)NEXP*DIM*HID];

// ---------- ptx helpers ----------
__device__ __forceinline__ uint32_t s2u(const void* p){
    uint32_t a; asm("{ .reg .u64 t; cvta.to.shared.u64 t, %1; cvt.u32.u64 %0, t; }":"=r"(a):"l"(p)); return a;
}
__device__ __forceinline__ uint32_t swz(uint32_t o){ return o ^ ((o>>3)&0x70); }
__device__ __forceinline__ void cp16(uint32_t d, const void* s, bool v){
    asm volatile("cp.async.cg.shared.global [%0], [%1], 16, %2;"
        ::"r"(d),"l"(__cvta_generic_to_global(s)),"r"(v?16:0));
}
__device__ __forceinline__ void ldx4(uint32_t* r, uint32_t a){
    asm volatile("ldmatrix.sync.aligned.m8n8.x4.shared.b16 {%0,%1,%2,%3},[%4];"
        :"=r"(r[0]),"=r"(r[1]),"=r"(r[2]),"=r"(r[3]):"r"(a));
}
__device__ __forceinline__ void ldx4t(uint32_t* r, uint32_t a){
    asm volatile("ldmatrix.sync.aligned.m8n8.x4.trans.shared.b16 {%0,%1,%2,%3},[%4];"
        :"=r"(r[0]),"=r"(r[1]),"=r"(r[2]),"=r"(r[3]):"r"(a));
}
__device__ __forceinline__ void mma16816h(float* d, const uint32_t* a, const uint32_t* b){
    asm volatile("mma.sync.aligned.m16n8k16.row.col.f32.f16.f16.f32 "
        "{%0,%1,%2,%3},{%4,%5,%6,%7},{%8,%9},{%0,%1,%2,%3};"
        : "+f"(d[0]),"+f"(d[1]),"+f"(d[2]),"+f"(d[3])
        : "r"(a[0]),"r"(a[1]),"r"(a[2]),"r"(a[3]),"r"(b[0]),"r"(b[1]));
}
__device__ __forceinline__ uint32_t packh(float f0, float f1){
    __half2 p = __floats2half2_rn(f0, f1);
    return *(uint32_t*)&p;
}
__device__ __forceinline__ uint32_t h2exp2(uint32_t a){
    uint32_t d; asm("ex2.approx.f16x2 %0, %1;" : "=r"(d) : "r"(a)); return d;
}

// ---------- small kernels ----------
__global__ void zero_cnt_kernel(){ if(threadIdx.x<NEXP) g_cnt[threadIdx.x]=0; }
__global__ void base_kernel(){
    if(threadIdx.x==0){ int s=0; for(int e=0;e<NEXP;++e){ g_basei[e]=s; s+=g_cnt[e]; } }
}
__global__ void final_kernel(float* __restrict__ out){
    int i = blockIdx.x*256 + threadIdx.x;
    float4 a = ((const float4*)g_x1)[i];
    float4 b = ((const float4*)g_c0)[i];
    float4 c = ((const float4*)g_c1)[i];
    ((float4*)out)[i] = make_float4(a.x+b.x+c.x, a.y+b.y+c.y, a.z+b.z+c.z, a.w+b.w+c.w);
}

// ---------- layernorm ----------
template<int WHICH>
__global__ void ln_kernel(const float* __restrict__ in, const float* __restrict__ gam,
                          const float* __restrict__ bet){
    __shared__ float sx[DIM]; __shared__ float red[8];
    const int n=blockIdx.x, tid=threadIdx.x;
    const float* row = (WHICH==0 ? in : g_x1) + (size_t)n*DIM;
    float4 x4 = ((const float4*)row)[tid];
    ((float4*)sx)[tid] = x4;
    float s = x4.x+x4.y+x4.z+x4.w;
    #pragma unroll
    for(int o=16;o;o>>=1) s += __shfl_xor_sync(~0u,s,o);
    if((tid&31)==0) red[tid>>5]=s;
    __syncthreads();
    float mu = (red[0]+red[1]+red[2]+red[3]+red[4]+red[5]+red[6]+red[7])*(1.f/DIM);
    float sq=0.f;
    #pragma unroll
    for(int p=0;p<4;++p){ float d=sx[tid+p*256]-mu; sq+=d*d; }
    #pragma unroll
    for(int o=16;o;o>>=1) sq += __shfl_xor_sync(~0u,sq,o);
    __syncthreads();
    if((tid&31)==0) red[tid>>5]=sq;
    __syncthreads();
    float var=(red[0]+red[1]+red[2]+red[3]+red[4]+red[5]+red[6]+red[7])*(1.f/DIM);
    float rs = rsqrtf(var+1e-5f);
    #pragma unroll
    for(int p=0;p<4;++p){
        int d=tid+p*256;
        float v = (sx[d]-mu)*rs*gam[d]+bet[d];
        size_t o=(size_t)n*DIM+d;
        if(WHICH==0){
            h16 h = __float2half_rn(v);
            g_h_hi[o]=h; g_h_lo[o]=__float2half_rn(v - __half2float(h));
        } else {
            g_h2f[o]=v;
            g_h2h[o]=__float2half_rn(v);
        }
    }
}

// ---------- weight transpose to single fp16: 64(k)x32(n) tiles, coalesced ----------
template<int WHICH>   // 0: w_attn, 1: w_proj, 2: w1, 3: w2
__global__ void __launch_bounds__(256) transpose_h(const float* __restrict__ src){
    constexpr int Kd = (WHICH==3)?HID:DIM;
    constexpr int Nd = (WHICH==0)?3*DIM:((WHICH==2)?HID:DIM);
    h16* dst = (WHICH==0)? g_waT_h : ((WHICH==1)? g_wpT_h : ((WHICH==2)? g_w1T_h : g_w2T_h));
    const int e=blockIdx.z;
    src += (size_t)e*Kd*Nd; dst += (size_t)e*(size_t)Nd*Kd;
    __shared__ float t[64][33];
    const int n0=blockIdx.x*32, k0=blockIdx.y*64;
    const int tid=threadIdx.x;
    const int lw = tid>>5, col = tid&31;
    #pragma unroll
    for(int i=0;i<8;++i){
        int k = i*8 + lw;
        t[k][col] = src[(size_t)(k0+k)*Nd + n0 + col];
    }
    __syncthreads();
    const int nn = tid>>3, kc = (tid&7)*8;
    uint4 w;
    w.x = packh(t[kc+0][nn], t[kc+1][nn]);
    w.y = packh(t[kc+2][nn], t[kc+3][nn]);
    w.z = packh(t[kc+4][nn], t[kc+5][nn]);
    w.w = packh(t[kc+6][nn], t[kc+7][nn]);
    *(uint4*)&dst[(size_t)(n0+nn)*Kd + k0 + kc] = w;
}

// ---------- fp16 2-term QKV GEMM: block 128x256, warp 64x64, K64, 2-stage, single sync ----------
// D = h_hi*W + h_lo*W (activations split fp16 hi/lo, weight single fp16)
__global__ void __launch_bounds__(256,1) tgemm0(){
    constexpr int N = 3*DIM, K = DIM;
    constexpr int NKT = K/64;
    constexpr int STG = 65536;   // A_hi 16K | A_lo 16K | B 32K
    extern __shared__ char smem[];
    const uint32_t sb = s2u(smem);
    const int tid = threadIdx.x, lane = tid&31, wid = tid>>5;
    const int wm = wid>>2, wn = wid&3;
    const int m0 = blockIdx.y*128, n0 = blockIdx.x*256;

    const uint32_t d0 = swz((uint32_t)((tid>>3)*128 + (tid&7)*16));
    const h16 *pah[4], *pal[4];
    #pragma unroll
    for(int i=0;i<4;++i){
        int r = (tid>>3) + i*32;
        pah[i]=g_h_hi+(size_t)(m0+r)*K+(tid&7)*8; pal[i]=g_h_lo+(size_t)(m0+r)*K+(tid&7)*8;
    }
    const h16 *pb = g_waT_h + (size_t)(n0 + (tid>>3))*K + (tid&7)*8;

    float acc[4][8][4];
    #pragma unroll
    for(int a=0;a<4;++a)
        #pragma unroll
        for(int b=0;b<8;++b)
            #pragma unroll
            for(int c=0;c<4;++c) acc[a][b][c]=0.f;

    const int arow = wm*64 + (lane&15), achk = lane>>4;
    const int brow_b = wn*64 + ((lane>>4)&1)*8 + (lane&7), bchk = (lane>>3)&1;

    auto issue = [&](int kt){
        const uint32_t st = sb + (kt&1)*STG;
        const int ko = kt*64;
        #pragma unroll
        for(int i=0;i<4;++i){
            cp16(st+d0+i*4096,        pah[i]+ko, true);
            cp16(st+16384+d0+i*4096,  pal[i]+ko, true);
        }
        #pragma unroll
        for(int i=0;i<8;++i)
            cp16(st+32768+d0+i*4096,  pb + (size_t)i*32*K + ko, true);
        asm volatile("cp.async.commit_group;":::"memory");
    };

    issue(0);
    for(int kt=0; kt<NKT; ++kt){
        asm volatile("cp.async.wait_group 0;":::"memory");
        __syncthreads();
        if(kt+1<NKT) issue(kt+1);
        const uint32_t st = sb + (kt&1)*STG;
        #pragma unroll
        for(int k16=0;k16<4;++k16){
            uint32_t ah[4][4], al[4][4];
            #pragma unroll
            for(int mi=0;mi<4;++mi){
                uint32_t off = swz((uint32_t)((arow+mi*16)*128 + k16*32 + achk*16));
                ldx4(ah[mi], st + off);
                ldx4(al[mi], st + 16384 + off);
            }
            #pragma unroll
            for(int n16=0;n16<4;++n16){
                uint32_t off = swz((uint32_t)((brow_b+n16*16)*128 + k16*32 + bchk*16));
                uint32_t rb[4];
                ldx4(rb, st + 32768 + off);
                #pragma unroll
                for(int mi=0;mi<4;++mi){
                    mma16816h(acc[mi][n16*2],   ah[mi], rb);
                    mma16816h(acc[mi][n16*2],   al[mi], rb);
                    mma16816h(acc[mi][n16*2+1], ah[mi], rb+2);
                    mma16816h(acc[mi][n16*2+1], al[mi], rb+2);
                }
            }
        }
    }

    const int r0 = lane>>2, c2 = (lane&3)*2;
    #pragma unroll
    for(int mi=0;mi<4;++mi){
        #pragma unroll
        for(int half=0; half<2; ++half){
            const int m = m0 + wm*64 + mi*16 + r0 + half*8;
            #pragma unroll
            for(int ni=0;ni<8;++ni){
                const int col = n0 + wn*64 + ni*8 + c2;
                float dd0 = acc[mi][ni][half*2], dd1 = acc[mi][ni][half*2+1];
                const int which = col>>10, r = col&1023, h = r>>6, d = r&63;
                const int b = m>>11, t = m&2047;
                size_t o = ((size_t)(b*16+h)*2048 + t)*64 + d;
                if(which==2){
                    *(uint32_t*)&g_vh[o] = packh(dd0, dd1);
                } else if(which==1){
                    *(uint32_t*)&g_kh[o] = packh(dd0, dd1);
                } else {
                    dd0*=0.180336887f; dd1*=0.180336887f;   // 0.125*log2e
                    h16 h0=__float2half_rn(dd0), h1=__float2half_rn(dd1);
                    *(uint32_t*)&g_q_hi[o] = (uint32_t)__half_as_ushort(h0)
                                           | ((uint32_t)__half_as_ushort(h1)<<16);
                    *(uint32_t*)&g_q_lo[o] = packh(dd0-__half2float(h0), dd1-__half2float(h1));
                }
            }
        }
    }
}

// ---------- single-fp16 GEMM: block 128x256, warp 64x64, K64, 3 stages x 48KB ----------
template<int MODE, int N, int K>
__global__ void __launch_bounds__(256,1) hgemm(const float* __restrict__ aux){
    constexpr int NKT = K/64;
    constexpr int STG = 49152;
    const int e = (MODE>=2)? blockIdx.z : 0;
    int Mrows = NTOK, pbase = 0;
    if(MODE>=2){
        Mrows = g_cnt[e]; pbase = g_basei[e];
        if((int)blockIdx.y*128 >= Mrows) return;
    }
    extern __shared__ char smem[];
    const uint32_t sb = s2u(smem);
    const int tid = threadIdx.x, lane = tid&31, wid = tid>>5;
    const int wm = wid>>2, wn = wid&3;
    const int m0 = blockIdx.y*128, n0 = blockIdx.x*256;

    const h16 *A, *B;
    if(MODE==1){ A=g_yh;    B=g_wpT_h; }
    else if(MODE==2){ A=g_h2h;  B=g_w1T_h+(size_t)e*HID*DIM; }
    else       { A=g_poolh; B=g_w2T_h+(size_t)e*DIM*HID; }

    const uint32_t d0 = swz((uint32_t)((tid>>3)*128 + (tid&7)*16));
    const h16 *pa[4]; bool av[4];
    #pragma unroll
    for(int i=0;i<4;++i){
        int r = (tid>>3) + i*32, gm = m0 + r;
        bool v = gm < Mrows;
        long rg = gm;
        if(MODE==2) rg = v ? g_tok[e*MAXTOK+gm] : 0;
        if(MODE==3) rg = (long)pbase + (v?gm:0);
        pa[i]=A+(size_t)rg*K+(tid&7)*8; av[i]=v;
    }
    const h16 *pb = B + (size_t)(n0 + (tid>>3))*K + (tid&7)*8;

    float acc[4][8][4];
    #pragma unroll
    for(int a=0;a<4;++a)
        #pragma unroll
        for(int b=0;b<8;++b)
            #pragma unroll
            for(int c=0;c<4;++c) acc[a][b][c]=0.f;

    const int arow = wm*64 + (lane&15), achk = lane>>4;
    const int brow_b = wn*64 + ((lane>>4)&1)*8 + (lane&7), bchk = (lane>>3)&1;

    auto issue = [&](int kt){
        const uint32_t st = sb + (kt%3)*STG;
        const int ko = kt*64;
        #pragma unroll
        for(int i=0;i<4;++i)
            cp16(st+d0+i*4096, pa[i]+ko, av[i]);
        #pragma unroll
        for(int i=0;i<8;++i)
            cp16(st+16384+d0+i*4096, pb + (size_t)i*32*K + ko, true);
        asm volatile("cp.async.commit_group;":::"memory");
    };

    issue(0); issue(1);
    for(int kt=0; kt<NKT; ++kt){
        if(kt+1<NKT){ asm volatile("cp.async.wait_group 1;":::"memory"); }
        else        { asm volatile("cp.async.wait_group 0;":::"memory"); }
        __syncthreads();
        if(kt+2<NKT) issue(kt+2);
        const uint32_t st = sb + (kt%3)*STG;
        #pragma unroll
        for(int k16=0;k16<4;++k16){
            uint32_t ah[4][4];
            #pragma unroll
            for(int mi=0;mi<4;++mi){
                uint32_t off = swz((uint32_t)((arow+mi*16)*128 + k16*32 + achk*16));
                ldx4(ah[mi], st + off);
            }
            #pragma unroll
            for(int n16=0;n16<4;++n16){
                uint32_t off = swz((uint32_t)((brow_b+n16*16)*128 + k16*32 + bchk*16));
                uint32_t rb[4];
                ldx4(rb, st + 16384 + off);
                #pragma unroll
                for(int mi=0;mi<4;++mi){
                    mma16816h(acc[mi][n16*2],   ah[mi], rb);
                    mma16816h(acc[mi][n16*2+1], ah[mi], rb+2);
                }
            }
        }
    }

    const int r0 = lane>>2, c2 = (lane&3)*2;
    const float* bias = (MODE>=2) ? (aux + (size_t)e*N) : aux;
    #pragma unroll
    for(int mi=0;mi<4;++mi){
        #pragma unroll
        for(int half=0; half<2; ++half){
            const int m = m0 + wm*64 + mi*16 + r0 + half*8;
            if(MODE>=2 && m>=Mrows) continue;
            int tok=0, slot=0; float wgt=0.f;
            if(MODE==3){ int ix=e*MAXTOK+m; tok=g_tok[ix]; wgt=g_wt[ix]; slot=g_slot[ix]; }
            #pragma unroll
            for(int ni=0;ni<8;++ni){
                const int col = n0 + wn*64 + ni*8 + c2;
                float dd0 = acc[mi][ni][half*2], dd1 = acc[mi][ni][half*2+1];
                if(MODE==1){
                    const float* rx = bias + (size_t)m*N + col;   // x residual
                    float2 w; w.x = rx[0]+dd0; w.y = rx[1]+dd1;
                    *(float2*)&g_x1[(size_t)m*N+col] = w;
                } else if(MODE==2){
                    size_t prow=(size_t)(pbase+m);
                    float v0=dd0+bias[col], v1=dd1+bias[col+1];
                    float gg0=0.5f*v0*(1.f+erff(v0*0.70710678f));
                    float gg1=0.5f*v1*(1.f+erff(v1*0.70710678f));
                    *(uint32_t*)&g_poolh[prow*HID+col] = packh(gg0, gg1);
                } else {
                    float2 w; w.x = wgt*(dd0+bias[col]); w.y = wgt*(dd1+bias[col+1]);
                    *(float2*)&((slot?g_c1:g_c0)[(size_t)tok*DIM+col]) = w;
                }
            }
        }
    }
}

// ---------- flash attention: QK fp16 2-pass (log2 domain), PV fp16, ex2.f16x2 softmax ----------
// smem: Qhi [0,16K), Qlo [16K,32K), stage kb%3 at 32K+16K each: K 8K | V 8K
__global__ void __launch_bounds__(256,1) attn_mma(){
    extern __shared__ char smem[];
    const uint32_t sb = s2u(smem);
    const int tid=threadIdx.x, lane=tid&31, wid=tid>>5;
    const int bh = blockIdx.y;
    const int qt = (gridDim.x-1) - blockIdx.x;
    const int q0 = qt*128;
    const size_t pbase = (size_t)bh*2048*64;

    #pragma unroll
    for(int i=0;i<4;++i){
        int idx=tid+i*256, r=idx>>3, c=idx&7;
        uint32_t off = swz((uint32_t)(r*128+c*16));
        cp16(sb+off,        g_q_hi + pbase + (size_t)(q0+r)*64 + c*8, true);
        cp16(sb+16384+off,  g_q_lo + pbase + (size_t)(q0+r)*64 + c*8, true);
    }
    auto issueKV = [&](int kb){
        const uint32_t st = sb + 32768 + (kb%3)*16384;
        #pragma unroll
        for(int i=0;i<2;++i){
            int idx=tid+i*256, r=idx>>3, c=idx&7;
            uint32_t off = swz((uint32_t)(r*128+c*16));
            size_t src = pbase + (size_t)(kb*64+r)*64 + c*8;
            cp16(st+off,       g_kh+src, true);
            cp16(st+8192+off,  g_vh+src, true);
        }
        asm volatile("cp.async.commit_group;":::"memory");
    };
    const int kbmax = 2*qt+1;
    issueKV(0);
    issueKV(1);

    asm volatile("cp.async.wait_group 1;":::"memory");
    __syncthreads();
    uint32_t qh[4][4], ql[4][4];
    {
        const int qrow = wid*16 + (lane&15), qchk = lane>>4;
        #pragma unroll
        for(int k16=0;k16<4;++k16){
            uint32_t off = swz((uint32_t)(qrow*128 + k16*32 + qchk*16));
            ldx4(qh[k16], sb+off);
            ldx4(ql[k16], sb+16384+off);
        }
    }

    float O[8][4], mstat[2], lstat[2];
    #pragma unroll
    for(int t=0;t<8;++t){ O[t][0]=0;O[t][1]=0;O[t][2]=0;O[t][3]=0; }
    mstat[0]=mstat[1]=-1e30f; lstat[0]=lstat[1]=0.f;

    const int rloc = lane>>2, cloc = (lane&3)*2;
    const int brow_b = ((lane>>4)&1)*8 + (lane&7), bchk = (lane>>3)&1;
    const int vrow_b = ((lane>>3)&1)*8 + (lane&7), vcol_b = ((lane>>4)&1)*8;

    for(int kb=0; kb<=kbmax; ++kb){
        if(kb<kbmax){ asm volatile("cp.async.wait_group 1;":::"memory"); }
        else        { asm volatile("cp.async.wait_group 0;":::"memory"); }
        __syncthreads();
        if(kb+2<=kbmax) issueKV(kb+2);
        const uint32_t st = sb + 32768 + (kb%3)*16384;

        float s[8][4];
        #pragma unroll
        for(int t=0;t<8;++t){ s[t][0]=0;s[t][1]=0;s[t][2]=0;s[t][3]=0; }
        #pragma unroll
        for(int k16=0;k16<4;++k16){
            uint32_t bk[8][2];
            #pragma unroll
            for(int n16=0;n16<4;++n16){
                uint32_t off = swz((uint32_t)((n16*16+brow_b)*128 + k16*32 + bchk*16));
                uint32_t r[4];
                ldx4(r, st+off);
                bk[n16*2][0]=r[0]; bk[n16*2][1]=r[1]; bk[n16*2+1][0]=r[2]; bk[n16*2+1][1]=r[3];
            }
            #pragma unroll
            for(int t=0;t<8;++t){
                mma16816h(s[t], qh[k16], bk[t]);
                mma16816h(s[t], ql[k16], bk[t]);
            }
        }
        if(kb >= 2*qt){
            const int row0 = q0 + wid*16 + rloc;
            #pragma unroll
            for(int t=0;t<8;++t){
                int c0 = kb*64 + t*8 + cloc;
                if(c0   > row0  ) s[t][0]=-30000.f;
                if(c0+1 > row0  ) s[t][1]=-30000.f;
                if(c0   > row0+8) s[t][2]=-30000.f;
                if(c0+1 > row0+8) s[t][3]=-30000.f;
            }
        }
        float corr[2], mn[2];
        #pragma unroll
        for(int rh=0; rh<2; ++rh){
            float mt=-1e30f;
            #pragma unroll
            for(int t=0;t<8;++t) mt = fmaxf(mt, fmaxf(s[t][rh*2], s[t][rh*2+1]));
            mt = fmaxf(mt, __shfl_xor_sync(~0u, mt, 1, 4));
            mt = fmaxf(mt, __shfl_xor_sync(~0u, mt, 2, 4));
            mn[rh] = fmaxf(mstat[rh], mt);
            corr[rh] = exp2f(mstat[rh]-mn[rh]); mstat[rh]=mn[rh];
        }
        uint32_t ph[4][4];
        float rs0=0.f, rs1=0.f;
        #pragma unroll
        for(int k16=0;k16<4;++k16){
            #pragma unroll
            for(int half=0; half<2; ++half){
                const int t = 2*k16+half;
                uint32_t p0 = h2exp2(packh(s[t][0]-mn[0], s[t][1]-mn[0]));
                uint32_t p1 = h2exp2(packh(s[t][2]-mn[1], s[t][3]-mn[1]));
                ph[k16][half*2]   = p0;
                ph[k16][half*2+1] = p1;
                float2 f0 = __half22float2(*(__half2*)&p0);
                float2 f1 = __half22float2(*(__half2*)&p1);
                rs0 += f0.x + f0.y;
                rs1 += f1.x + f1.y;
            }
        }
        rs0 += __shfl_xor_sync(~0u, rs0, 1, 4);
        rs0 += __shfl_xor_sync(~0u, rs0, 2, 4);
        rs1 += __shfl_xor_sync(~0u, rs1, 1, 4);
        rs1 += __shfl_xor_sync(~0u, rs1, 2, 4);
        lstat[0] = lstat[0]*corr[0] + rs0;
        lstat[1] = lstat[1]*corr[1] + rs1;
        #pragma unroll
        for(int t=0;t<8;++t){
            O[t][0]*=corr[0]; O[t][1]*=corr[0]; O[t][2]*=corr[1]; O[t][3]*=corr[1];
        }
        #pragma unroll
        for(int k16=0;k16<4;++k16){
            uint32_t bv[8][2];
            #pragma unroll
            for(int d16=0;d16<4;++d16){
                uint32_t off = swz((uint32_t)((k16*16+vrow_b)*128 + (d16*16+vcol_b)*2));
                uint32_t r[4];
                ldx4t(r, st+8192+off);
                bv[d16*2][0]=r[0]; bv[d16*2][1]=r[1]; bv[d16*2+1][0]=r[2]; bv[d16*2+1][1]=r[3];
            }
            #pragma unroll
            for(int t=0;t<8;++t)
                mma16816h(O[t], ph[k16], bv[t]);
        }
        __syncthreads();
    }

    const int b = bh>>4, h = bh&15;
    #pragma unroll
    for(int rh=0; rh<2; ++rh){
        const float inv = 1.f/lstat[rh];
        const int row = q0 + wid*16 + rloc + rh*8;
        size_t base = (size_t)(b*TT+row)*DIM + h*64;
        #pragma unroll
        for(int t=0;t<8;++t){
            float v0 = O[t][rh*2]*inv, v1 = O[t][rh*2+1]*inv;
            *(uint32_t*)&g_yh[base + t*8 + cloc] = packh(v0, v1);
        }
    }
}

// ---------- router ----------
__global__ void router_kernel(const float* __restrict__ wr){
    const int n=blockIdx.x, tid=threadIdx.x;
    float acc[NEXP];
    #pragma unroll
    for(int e=0;e<NEXP;++e) acc[e]=0.f;
    const float* row=g_h2f+(size_t)n*DIM;
    for(int d=tid;d<DIM;d+=128){
        float hv=row[d];
        #pragma unroll
        for(int e=0;e<NEXP;++e) acc[e]+=hv*wr[d*NEXP+e];
    }
    __shared__ float sm[4][NEXP];
    #pragma unroll
    for(int e=0;e<NEXP;++e){
        float v=acc[e];
        #pragma unroll
        for(int o=16;o;o>>=1) v+=__shfl_xor_sync(~0u,v,o);
        if((tid&31)==0) sm[tid>>5][e]=v;
    }
    __syncthreads();
    if(tid==0){
        float lg[NEXP];
        #pragma unroll
        for(int e=0;e<NEXP;++e) lg[e]=sm[0][e]+sm[1][e]+sm[2][e]+sm[3][e];
        int e0=0;
        #pragma unroll
        for(int e=1;e<NEXP;++e) if(lg[e]>lg[e0]) e0=e;
        int e1=-1;
        #pragma unroll
        for(int e=0;e<NEXP;++e) if(e!=e0 && (e1<0||lg[e]>lg[e1])) e1=e;
        float w0=1.f/(1.f+__expf(lg[e1]-lg[e0])), w1=1.f-w0;
        int p0=atomicAdd(&g_cnt[e0],1);
        g_tok[e0*MAXTOK+p0]=n; g_wt[e0*MAXTOK+p0]=w0; g_slot[e0*MAXTOK+p0]=0;
        int p1=atomicAdd(&g_cnt[e1],1);
        g_tok[e1*MAXTOK+p1]=n; g_wt[e1*MAXTOK+p1]=w1; g_slot[e1*MAXTOK+p1]=1;
    }
}

// ---------- launch ----------
extern "C" void kernel_launch(void* const* d_in, const int* in_sizes, int n_in,
                              void* d_out, int out_size){
    const float* x      =(const float*)d_in[0];
    const float* ln1_g  =(const float*)d_in[1];
    const float* ln1_b  =(const float*)d_in[2];
    const float* w_attn =(const float*)d_in[3];
    const float* w_proj =(const float*)d_in[4];
    const float* ln2_g  =(const float*)d_in[5];
    const float* ln2_b  =(const float*)d_in[6];
    const float* w_rtr  =(const float*)d_in[7];
    const float* w1     =(const float*)d_in[8];
    const float* b1     =(const float*)d_in[9];
    const float* w2     =(const float*)d_in[10];
    const float* b2     =(const float*)d_in[11];
    float* out=(float*)d_out;

    const int SMG = 131072;
    const int SMH = 147456;
    const int SMA = 81920;
    cudaFuncSetAttribute(tgemm0,           cudaFuncAttributeMaxDynamicSharedMemorySize, SMG);
    cudaFuncSetAttribute(hgemm<1,DIM,DIM>, cudaFuncAttributeMaxDynamicSharedMemorySize, SMH);
    cudaFuncSetAttribute(hgemm<2,HID,DIM>, cudaFuncAttributeMaxDynamicSharedMemorySize, SMH);
    cudaFuncSetAttribute(hgemm<3,DIM,HID>, cudaFuncAttributeMaxDynamicSharedMemorySize, SMH);
    cudaFuncSetAttribute(attn_mma,         cudaFuncAttributeMaxDynamicSharedMemorySize, SMA);

    zero_cnt_kernel<<<1,32>>>();
    transpose_h<0><<<dim3(96,16,1), 256>>>(w_attn);
    transpose_h<1><<<dim3(32,16,1), 256>>>(w_proj);
    transpose_h<2><<<dim3(128,16,NEXP), 256>>>(w1);
    transpose_h<3><<<dim3(32,64,NEXP), 256>>>(w2);

    ln_kernel<0><<<NTOK,256>>>(x, ln1_g, ln1_b);
    tgemm0<<<dim3(12,32,1),256,SMG>>>();
    attn_mma<<<dim3(TT/128, BB*16),256,SMA>>>();
    hgemm<1,DIM,DIM><<<dim3(4,32,1),256,SMH>>>(x);
    ln_kernel<1><<<NTOK,256>>>(nullptr, ln2_g, ln2_b);
    router_kernel<<<NTOK,128>>>(w_rtr);
    base_kernel<<<1,32>>>();
    hgemm<2,HID,DIM><<<dim3(16,32,NEXP),256,SMH>>>(b1);
    hgemm<3,DIM,HID><<<dim3(4,32,NEXP),256,SMH>>>(b2);
    final_kernel<<<NTOK*DIM/1024,256>>>(out);
}